// round 2
// baseline (speedup 1.0000x reference)
#include <cuda_runtime.h>
#include <cuda_bf16.h>
#include <math.h>

// ---------------- problem constants ----------------
#define BB   16
#define CH   128
#define HH   128
#define WW   128
#define HO   64
#define WO   64
#define TOK  4096            // tokens per batch (64*64)
#define NT   65536           // total tokens (BB*TOK)
#define NG   128             // attention groups (BB*8)
#define QL   512             // chunk length (4096/8)

// ---------------- scratch (static device allocs are allowed) ----------------
__device__ float g_hlh[(size_t)NT * 256];      // concat(HL,LH) tokens
__device__ float g_yL [(size_t)NT * 128];
__device__ float g_yHH[(size_t)NT * 128];
__device__ float g_y  [(size_t)NT * 128];      // conv1x1 output tokens (y_t / y_img)
__device__ float g_S  [(size_t)NG * QL * QL];  // attention scores
__device__ float g_attn[(size_t)NT * 128];
__device__ float g_t0 [(size_t)NT * 128];
__device__ float g_t1 [(size_t)NT * 128];
__device__ float g_x1 [(size_t)NT * 128];
__device__ float g_x2 [(size_t)NT * 128];
__device__ float g_x3 [(size_t)NT * 128];
__device__ float g_gate[(size_t)NT * 128];
__device__ float g_ffn[(size_t)NT * 128];
__device__ float g_dw [(size_t)BB * CH * HO * WO];

__device__ __forceinline__ float gelu_f(float v) {
    return 0.5f * v * (1.0f + erff(v * 0.70710678118654752f));
}

// ---------------- Haar DWT -> token layout ----------------
// grid (64 rows, 16 batches), 256 threads
__global__ void haar_k(const float* __restrict__ x,
                       float* __restrict__ yL, float* __restrict__ yHH,
                       float* __restrict__ hlh) {
    __shared__ float sLL[32][65], sHL[32][65], sLH[32][65], sHH[32][65];
    int i = blockIdx.x, b = blockIdx.y, tid = threadIdx.x;
    for (int cc = 0; cc < 4; cc++) {
        for (int idx = tid; idx < 32 * 64; idx += 256) {
            int cl = idx / 64, j = idx % 64;
            int c = cc * 32 + cl;
            const float* base = x + (((long long)(b * CH + c) * HH + 2 * i) * WW) + 2 * j;
            float a = base[0], bb2 = base[1], cv = base[WW], d = base[WW + 1];
            sLL[cl][j] = (a + bb2 + cv + d) * 0.5f;
            sHL[cl][j] = (a - bb2 + cv - d) * 0.5f;
            sLH[cl][j] = (a + bb2 - cv - d) * 0.5f;
            sHH[cl][j] = (a - bb2 - cv + d) * 0.5f;
        }
        __syncthreads();
        for (int idx = tid; idx < 64 * 32; idx += 256) {
            int j = idx / 32, cl = idx % 32;
            long long t = (long long)b * TOK + i * 64 + j;
            int c = cc * 32 + cl;
            yL [t * 128 + c] = sLL[cl][j];
            yHH[t * 128 + c] = sHH[cl][j];
            hlh[t * 256 + c]       = sHL[cl][j];
            hlh[t * 256 + 128 + c] = sLH[cl][j];
        }
        __syncthreads();
    }
}

// ---------------- generic batched GEMM: C = epi(alpha*A@B^T + bias) ----------------
// A[m][k] row-major (k contiguous), B either [n][k] (BKMAJ) or [k][n] (!BKMAJ)
// EPI: 0 none, 1 gelu, 2 sigmoid, 3 gelu then minus extra
template <bool BKMAJ, int EPI>
__global__ __launch_bounds__(256) void gemm_k(
    const float* __restrict__ A, long long sAg, int lda,
    const float* __restrict__ Bm, long long sBg, int ldb,
    float* __restrict__ Cm, long long sCg, int ldc,
    int M, int N, int K, float alpha,
    const float* __restrict__ bias,
    const float* __restrict__ extra) {
    __shared__ float As[8][128];
    __shared__ float Bs[8][128];
    int g = blockIdx.z;
    A  += (long long)g * sAg;
    Bm += (long long)g * sBg;
    Cm += (long long)g * sCg;
    if (EPI == 3) extra += (long long)g * sCg;
    int m0 = blockIdx.y * 128;
    int n0 = blockIdx.x * 128;
    int tid = threadIdx.x;
    int tx = tid % 16, ty = tid / 16;
    float acc[8][8];
#pragma unroll
    for (int u = 0; u < 8; u++)
#pragma unroll
        for (int v = 0; v < 8; v++) acc[u][v] = 0.f;

    int arow  = tid >> 1;
    int acol4 = (tid & 1) * 4;
    for (int k0 = 0; k0 < K; k0 += 8) {
        float4 av = *reinterpret_cast<const float4*>(&A[(long long)(m0 + arow) * lda + k0 + acol4]);
        As[acol4 + 0][arow] = av.x;
        As[acol4 + 1][arow] = av.y;
        As[acol4 + 2][arow] = av.z;
        As[acol4 + 3][arow] = av.w;
        if (BKMAJ) {
            float4 bv = *reinterpret_cast<const float4*>(&Bm[(long long)(n0 + arow) * ldb + k0 + acol4]);
            Bs[acol4 + 0][arow] = bv.x;
            Bs[acol4 + 1][arow] = bv.y;
            Bs[acol4 + 2][arow] = bv.z;
            Bs[acol4 + 3][arow] = bv.w;
        } else {
            int bk  = tid >> 5;
            int bn4 = (tid & 31) * 4;
            float4 bv = *reinterpret_cast<const float4*>(&Bm[(long long)(k0 + bk) * ldb + n0 + bn4]);
            *reinterpret_cast<float4*>(&Bs[bk][bn4]) = bv;
        }
        __syncthreads();
#pragma unroll
        for (int kk = 0; kk < 8; kk++) {
            float4 a0 = *reinterpret_cast<const float4*>(&As[kk][ty * 8]);
            float4 a1 = *reinterpret_cast<const float4*>(&As[kk][ty * 8 + 4]);
            float4 b0 = *reinterpret_cast<const float4*>(&Bs[kk][tx * 8]);
            float4 b1 = *reinterpret_cast<const float4*>(&Bs[kk][tx * 8 + 4]);
            float a[8] = {a0.x, a0.y, a0.z, a0.w, a1.x, a1.y, a1.z, a1.w};
            float bb2[8] = {b0.x, b0.y, b0.z, b0.w, b1.x, b1.y, b1.z, b1.w};
#pragma unroll
            for (int u = 0; u < 8; u++)
#pragma unroll
                for (int v = 0; v < 8; v++) acc[u][v] += a[u] * bb2[v];
        }
        __syncthreads();
    }
#pragma unroll
    for (int u = 0; u < 8; u++) {
        int m = m0 + ty * 8 + u;
#pragma unroll
        for (int v = 0; v < 8; v++) {
            int n = n0 + tx * 8 + v;
            float val = acc[u][v] * alpha;
            if (bias) val += bias[n];
            if (EPI == 1 || EPI == 3) val = gelu_f(val);
            if (EPI == 2) val = 1.f / (1.f + expf(-val));
            if (EPI == 3) val -= extra[(long long)m * ldc + n];
            Cm[(long long)m * ldc + n] = val;
        }
    }
}

// ---------------- direct conv 4x4 stride2 pad1 + relu ----------------
// grid (32 spatial tiles, 4 oc-blocks, 16 batches), 128 threads
__global__ __launch_bounds__(128) void conv_l1_k(const float* __restrict__ x,
                                                 const float* __restrict__ w,
                                                 const float* __restrict__ bias,
                                                 float* __restrict__ dw) {
    __shared__ float sw[512];       // 32 oc x 16
    __shared__ float sx[34 * 19];   // 34 rows x 18 cols (padded to 19)
    int tile = blockIdx.x;
    int oc0 = blockIdx.y * 32;
    int b = blockIdx.z;
    int i0 = (tile / 8) * 16;
    int j0 = (tile % 8) * 8;
    int t = threadIdx.x;
    int pg = t % 32, os = t / 32;
    int iL2 = 2 * (pg / 8), jL2 = 2 * (pg % 8);
    float acc[8][4];
#pragma unroll
    for (int u = 0; u < 8; u++)
#pragma unroll
        for (int m = 0; m < 4; m++) acc[u][m] = 0.f;

    for (int ic = 0; ic < 128; ic++) {
        {
            int idx = t * 4;
            int oc_l = idx >> 4, rs = idx & 15;
            float4 wv = *reinterpret_cast<const float4*>(
                &w[(long long)(oc0 + oc_l) * 2048 + ic * 16 + rs]);
            *reinterpret_cast<float4*>(&sw[idx]) = wv;
        }
        const float* xp = x + (long long)(b * CH + ic) * HH * WW;
        for (int idx = t; idx < 34 * 18; idx += 128) {
            int row = idx / 18, col = idx % 18;
            int gy = 2 * i0 - 1 + row, gx = 2 * j0 - 1 + col;
            float v = 0.f;
            if (gy >= 0 && gy < HH && gx >= 0 && gx < WW) v = xp[gy * WW + gx];
            sx[row * 19 + col] = v;
        }
        __syncthreads();
#pragma unroll
        for (int r = 0; r < 4; r++) {
#pragma unroll
            for (int s = 0; s < 4; s++) {
                int xoff = (iL2 + r) * 19 + jL2 + s;
                float xv0 = sx[xoff];
                float xv1 = sx[xoff + 8 * 19];
                float xv2 = sx[xoff + 16 * 19];
                float xv3 = sx[xoff + 24 * 19];
                int woff = os * 16 + r * 4 + s;
#pragma unroll
                for (int u = 0; u < 8; u++) {
                    float wv = sw[woff + 64 * u];
                    acc[u][0] += wv * xv0;
                    acc[u][1] += wv * xv1;
                    acc[u][2] += wv * xv2;
                    acc[u][3] += wv * xv3;
                }
            }
        }
        __syncthreads();
    }
#pragma unroll
    for (int u = 0; u < 8; u++) {
        int oc = oc0 + os + 4 * u;
        float bv = bias[oc];
#pragma unroll
        for (int m = 0; m < 4; m++) {
            int i = i0 + pg / 8 + 4 * m;
            int j = j0 + pg % 8;
            float v = acc[u][m] + bv;
            dw[(((long long)b * CH + oc) * HO + i) * WO + j] = fmaxf(v, 0.f);
        }
    }
}

// ---------------- column softmax over q axis ----------------
// grid (16 kblocks, 128 groups), 256 threads (32 cols x 8 q-stripes)
__global__ void softmax_q_k(float* __restrict__ S) {
    __shared__ float sm[8][32], ss[8][32];
    int g = blockIdx.y;
    int k0 = blockIdx.x * 32;
    int tid = threadIdx.x;
    int kc = tid % 32;
    int qh = tid / 32;
    float* Sg = S + (long long)g * QL * QL + k0 + kc;
    float m = -INFINITY, s = 0.f;
    for (int q = qh; q < QL; q += 8) {
        float v = Sg[(long long)q * QL];
        if (v > m) { s = s * expf(m - v) + 1.f; m = v; }
        else s += expf(v - m);
    }
    sm[qh][kc] = m;
    ss[qh][kc] = s;
    __syncthreads();
    if (tid < 32) {
        float M = sm[0][kc], Sm = ss[0][kc];
#pragma unroll
        for (int r = 1; r < 8; r++) {
            float m2 = sm[r][kc], s2 = ss[r][kc];
            float nm = fmaxf(M, m2);
            Sm = Sm * expf(M - nm) + s2 * expf(m2 - nm);
            M = nm;
        }
        sm[0][kc] = M;
        ss[0][kc] = 1.f / Sm;
    }
    __syncthreads();
    float M = sm[0][kc], inv = ss[0][kc];
    for (int q = qh; q < QL; q += 8) {
        float v = Sg[(long long)q * QL];
        Sg[(long long)q * QL] = expf(v - M) * inv;
    }
}

// ---------------- per-token layernorm ----------------
// block 256 = 8 warps, 1 token/warp
__global__ void ln_k(const float* __restrict__ X, float* __restrict__ Y,
                     const float* __restrict__ gw, const float* __restrict__ bw) {
    int warp = threadIdx.x / 32, lane = threadIdx.x % 32;
    long long t = (long long)blockIdx.x * 8 + warp;
    const float* xv = X + t * 128;
    float v[4];
    float sum = 0.f;
#pragma unroll
    for (int i = 0; i < 4; i++) { v[i] = xv[lane + 32 * i]; sum += v[i]; }
#pragma unroll
    for (int o = 16; o; o >>= 1) sum += __shfl_xor_sync(0xffffffffu, sum, o);
    float mean = sum * (1.f / 128.f);
    float vs = 0.f;
#pragma unroll
    for (int i = 0; i < 4; i++) { float d = v[i] - mean; vs += d * d; }
#pragma unroll
    for (int o = 16; o; o >>= 1) vs += __shfl_xor_sync(0xffffffffu, vs, o);
    float inv = rsqrtf(vs * (1.f / 128.f) + 1e-5f);
#pragma unroll
    for (int i = 0; i < 4; i++) {
        int c = lane + 32 * i;
        Y[t * 128 + c] = (v[i] - mean) * inv * gw[c] + bw[c];
    }
}

// ---------------- out = gate * LN(x2 + x3) ----------------
__global__ void addlngate_k(const float* __restrict__ X2, const float* __restrict__ X3,
                            const float* __restrict__ G,
                            const float* __restrict__ gw, const float* __restrict__ bw,
                            float* __restrict__ Y) {
    int warp = threadIdx.x / 32, lane = threadIdx.x % 32;
    long long t = (long long)blockIdx.x * 8 + warp;
    float v[4];
    float sum = 0.f;
#pragma unroll
    for (int i = 0; i < 4; i++) {
        int c = lane + 32 * i;
        v[i] = X2[t * 128 + c] + X3[t * 128 + c];
        sum += v[i];
    }
#pragma unroll
    for (int o = 16; o; o >>= 1) sum += __shfl_xor_sync(0xffffffffu, sum, o);
    float mean = sum * (1.f / 128.f);
    float vs = 0.f;
#pragma unroll
    for (int i = 0; i < 4; i++) { float d = v[i] - mean; vs += d * d; }
#pragma unroll
    for (int o = 16; o; o >>= 1) vs += __shfl_xor_sync(0xffffffffu, vs, o);
    float inv = rsqrtf(vs * (1.f / 128.f) + 1e-5f);
#pragma unroll
    for (int i = 0; i < 4; i++) {
        int c = lane + 32 * i;
        float nrm = (v[i] - mean) * inv * gw[c] + bw[c];
        Y[t * 128 + c] = G[t * 128 + c] * nrm;
    }
}

// ---------------- final combine: out = ffn*(down2x - dw) + y_img ----------------
// grid (64 rows, 16 batches), 256 threads
__global__ void final_k(const float* __restrict__ x, const float* __restrict__ ffn,
                        const float* __restrict__ ytok, const float* __restrict__ dw,
                        float* __restrict__ out) {
    __shared__ float sf[32][65], sy[32][65];
    int i = blockIdx.x, b = blockIdx.y, tid = threadIdx.x;
    float pos_i = (float)(i * 127) / 63.f;
    int y0 = (int)floorf(pos_i);
    int y1 = min(y0 + 1, 127);
    float wy = pos_i - (float)y0;
    for (int cc = 0; cc < 4; cc++) {
        for (int idx = tid; idx < 64 * 32; idx += 256) {
            int j = idx / 32, cl = idx % 32;
            long long t = (long long)b * TOK + i * 64 + j;
            sf[cl][j] = ffn[t * 128 + cc * 32 + cl];
            sy[cl][j] = ytok[t * 128 + cc * 32 + cl];
        }
        __syncthreads();
        for (int idx = tid; idx < 32 * 64; idx += 256) {
            int cl = idx / 64, j = idx % 64;
            int c = cc * 32 + cl;
            float pos_j = (float)(j * 127) / 63.f;
            int x0 = (int)floorf(pos_j);
            int x1i = min(x0 + 1, 127);
            float wx = pos_j - (float)x0;
            const float* xb = x + (long long)(b * CH + c) * HH * WW;
            float r0 = xb[y0 * WW + x0] * (1.f - wy) + xb[y1 * WW + x0] * wy;
            float r1 = xb[y0 * WW + x1i] * (1.f - wy) + xb[y1 * WW + x1i] * wy;
            float dv = r0 * (1.f - wx) + r1 * wx;
            long long oi = (((long long)b * CH + c) * HO + i) * WO + j;
            float dwv = dw[oi];
            out[oi] = sf[cl][j] * (dv - dwv) + sy[cl][j];
        }
        __syncthreads();
    }
}

// ---------------- launch ----------------
extern "C" void kernel_launch(void* const* d_in, const int* in_sizes, int n_in,
                              void* d_out, int out_size) {
    (void)in_sizes; (void)n_in; (void)out_size;
    const float* x       = (const float*)d_in[0];
    const float* conv1_w = (const float*)d_in[1];
    const float* conv1_b = (const float*)d_in[2];
    const float* l1_w    = (const float*)d_in[3];
    const float* l1_b    = (const float*)d_in[4];
    const float* ln1_g   = (const float*)d_in[5];
    const float* ln1_b   = (const float*)d_in[6];
    const float* fc1_w   = (const float*)d_in[7];
    const float* fc1_b   = (const float*)d_in[8];
    const float* div_w   = (const float*)d_in[9];
    const float* div_b   = (const float*)d_in[10];
    const float* fc2_w   = (const float*)d_in[11];
    const float* fc2_b   = (const float*)d_in[12];
    const float* ln3_g   = (const float*)d_in[13];
    const float* ln3_b   = (const float*)d_in[14];
    const float* fc3a_w  = (const float*)d_in[15];
    const float* fc3a_b  = (const float*)d_in[16];
    const float* fc3b_w  = (const float*)d_in[17];
    const float* fc3b_b  = (const float*)d_in[18];
    const float* lnn_g   = (const float*)d_in[19];
    const float* lnn_b   = (const float*)d_in[20];
    const float* act_w   = (const float*)d_in[21];
    const float* act_b   = (const float*)d_in[22];
    float* out = (float*)d_out;

    float *yL, *yHH, *hlh, *y, *S, *attn, *t0, *t1, *x1, *x2, *x3, *gate, *ffn, *dw;
    cudaGetSymbolAddress((void**)&yL,   g_yL);
    cudaGetSymbolAddress((void**)&yHH,  g_yHH);
    cudaGetSymbolAddress((void**)&hlh,  g_hlh);
    cudaGetSymbolAddress((void**)&y,    g_y);
    cudaGetSymbolAddress((void**)&S,    g_S);
    cudaGetSymbolAddress((void**)&attn, g_attn);
    cudaGetSymbolAddress((void**)&t0,   g_t0);
    cudaGetSymbolAddress((void**)&t1,   g_t1);
    cudaGetSymbolAddress((void**)&x1,   g_x1);
    cudaGetSymbolAddress((void**)&x2,   g_x2);
    cudaGetSymbolAddress((void**)&x3,   g_x3);
    cudaGetSymbolAddress((void**)&gate, g_gate);
    cudaGetSymbolAddress((void**)&ffn,  g_ffn);
    cudaGetSymbolAddress((void**)&dw,   g_dw);

    // 1. Haar DWT into token layouts
    haar_k<<<dim3(64, 16), 256>>>(x, yL, yHH, hlh);

    // 2. 1x1 conv as GEMM: y = hlh @ conv1_w^T + b
    gemm_k<true, 0><<<dim3(1, 512, 1), 256>>>(hlh, 0, 256, conv1_w, 0, 256,
                                              y, 0, 128, NT, 128, 256, 1.f, conv1_b, nullptr);

    // 3. strided conv + relu
    conv_l1_k<<<dim3(32, 4, 16), 128>>>(x, l1_w, l1_b, dw);

    // 4. attention scores S = scale * Q @ K^T  (batched over 128 groups)
    gemm_k<true, 0><<<dim3(4, 4, NG), 256>>>(yL, (long long)QL * 128, 128,
                                             y, (long long)QL * 128, 128,
                                             S, (long long)QL * QL, QL,
                                             QL, QL, 128, 0.35355339059327373f, nullptr, nullptr);

    // 5. softmax over q axis
    softmax_q_k<<<dim3(16, NG), 256>>>(S);

    // 6. attn = P @ V
    gemm_k<false, 0><<<dim3(1, 4, NG), 256>>>(S, (long long)QL * QL, QL,
                                              yHH, (long long)QL * 128, 128,
                                              attn, (long long)QL * 128, 128,
                                              QL, 128, QL, 1.f, nullptr, nullptr);

    // 7-14. FFN
    ln_k<<<8192, 256>>>(attn, t0, ln1_g, ln1_b);
    gemm_k<true, 1><<<dim3(1, 512), 256>>>(t0, 0, 128, fc1_w, 0, 128,
                                           x1, 0, 128, NT, 128, 128, 1.f, fc1_b, nullptr);
    gemm_k<true, 3><<<dim3(1, 512), 256>>>(attn, 0, 128, div_w, 0, 128,
                                           x2, 0, 128, NT, 128, 128, 1.f, div_b, x1);
    gemm_k<true, 1><<<dim3(1, 512), 256>>>(x2, 0, 128, fc2_w, 0, 128,
                                           t1, 0, 128, NT, 128, 128, 1.f, fc2_b, nullptr);
    ln_k<<<8192, 256>>>(attn, t0, ln3_g, ln3_b);
    gemm_k<true, 1><<<dim3(1, 512), 256>>>(t0, 0, 128, fc3a_w, 0, 128,
                                           x2, 0, 128, NT, 128, 128, 1.f, fc3a_b, nullptr);
    gemm_k<true, 0><<<dim3(1, 512), 256>>>(x2, 0, 128, fc3b_w, 0, 128,
                                           x3, 0, 128, NT, 128, 128, 1.f, fc3b_b, nullptr);
    gemm_k<true, 2><<<dim3(1, 512), 256>>>(attn, 0, 128, act_w, 0, 128,
                                           gate, 0, 128, NT, 128, 128, 1.f, act_b, nullptr);
    addlngate_k<<<8192, 256>>>(t1, x3, gate, lnn_g, lnn_b, ffn);

    // 15. final combine with bilinear resize and dw gate
    final_k<<<dim3(64, 16), 256>>>(x, ffn, y, dw, out);
}

// round 4
// speedup vs baseline: 1.0913x; 1.0913x over previous
#include <cuda_runtime.h>
#include <cuda_bf16.h>
#include <math.h>

// ---------------- problem constants ----------------
#define BB   16
#define CH   128
#define HH   128
#define WW   128
#define HO   64
#define WO   64
#define TOK  4096            // tokens per batch (64*64)
#define NT   65536           // total tokens (BB*TOK)
#define NG   128             // attention groups (BB*8)
#define QL   512             // chunk length (4096/8)

typedef unsigned long long ull;

// ---------------- scratch ----------------
__device__ float g_hlh[(size_t)NT * 256];
__device__ float g_yL [(size_t)NT * 128];
__device__ float g_yHH[(size_t)NT * 128];
__device__ float g_y  [(size_t)NT * 128];
__device__ float g_S  [(size_t)NG * QL * QL];
__device__ float g_attn[(size_t)NT * 128];
__device__ float g_t0 [(size_t)NT * 128];
__device__ float g_t1 [(size_t)NT * 128];
__device__ float g_x1 [(size_t)NT * 128];
__device__ float g_x2 [(size_t)NT * 128];
__device__ float g_x3 [(size_t)NT * 128];
__device__ float g_gate[(size_t)NT * 128];
__device__ float g_ffn[(size_t)NT * 128];
__device__ float g_dw [(size_t)BB * CH * HO * WO];

__device__ __forceinline__ float gelu_f(float v) {
    return 0.5f * v * (1.0f + erff(v * 0.70710678118654752f));
}

// packed fp32x2 helpers (Blackwell FFMA2 — only reachable via PTX)
__device__ __forceinline__ ull ffma2(ull a, ull b, ull c) {
    ull d;
    asm("fma.rn.f32x2 %0, %1, %2, %3;" : "=l"(d) : "l"(a), "l"(b), "l"(c));
    return d;
}
__device__ __forceinline__ ull pack2(float x, float y) {
    ull r;
    asm("mov.b64 %0, {%1, %2};" : "=l"(r) : "f"(x), "f"(y));
    return r;
}
__device__ __forceinline__ float2 unpack2(ull p) {
    float2 f;
    asm("mov.b64 {%0, %1}, %2;" : "=f"(f.x), "=f"(f.y) : "l"(p));
    return f;
}

// ---------------- Haar DWT -> token layout ----------------
__global__ void haar_k(const float* __restrict__ x,
                       float* __restrict__ yL, float* __restrict__ yHH,
                       float* __restrict__ hlh) {
    __shared__ float sLL[32][65], sHL[32][65], sLH[32][65], sHH[32][65];
    int i = blockIdx.x, b = blockIdx.y, tid = threadIdx.x;
    for (int cc = 0; cc < 4; cc++) {
        for (int idx = tid; idx < 32 * 64; idx += 256) {
            int cl = idx / 64, j = idx % 64;
            int c = cc * 32 + cl;
            const float* base = x + (((long long)(b * CH + c) * HH + 2 * i) * WW) + 2 * j;
            float a = base[0], bb2 = base[1], cv = base[WW], d = base[WW + 1];
            sLL[cl][j] = (a + bb2 + cv + d) * 0.5f;
            sHL[cl][j] = (a - bb2 + cv - d) * 0.5f;
            sLH[cl][j] = (a + bb2 - cv - d) * 0.5f;
            sHH[cl][j] = (a - bb2 - cv + d) * 0.5f;
        }
        __syncthreads();
        for (int idx = tid; idx < 64 * 32; idx += 256) {
            int j = idx / 32, cl = idx % 32;
            long long t = (long long)b * TOK + i * 64 + j;
            int c = cc * 32 + cl;
            yL [t * 128 + c] = sLL[cl][j];
            yHH[t * 128 + c] = sHH[cl][j];
            hlh[t * 256 + c]       = sHL[cl][j];
            hlh[t * 256 + 128 + c] = sLH[cl][j];
        }
        __syncthreads();
    }
}

// ---------------- batched GEMM (f32x2, double-buffered) ----------------
// C = epi(alpha*A@B^T + bias); A[m][k]; B [n][k] if BKMAJ else [k][n]
// EPI: 0 none, 1 gelu, 2 sigmoid, 3 gelu then minus extra
template <bool BKMAJ, int EPI>
__global__ __launch_bounds__(256) void gemm_k(
    const float* __restrict__ A, long long sAg, int lda,
    const float* __restrict__ Bm, long long sBg, int ldb,
    float* __restrict__ Cm, long long sCg, int ldc,
    int M, int N, int K, float alpha,
    const float* __restrict__ bias,
    const float* __restrict__ extra) {
    __shared__ float As[2][8][128];
    __shared__ float Bs[2][8][128];
    int g = blockIdx.z;
    A  += (long long)g * sAg;
    Bm += (long long)g * sBg;
    Cm += (long long)g * sCg;
    if (EPI == 3) extra += (long long)g * sCg;
    int m0 = blockIdx.y * 128;
    int n0 = blockIdx.x * 128;
    int tid = threadIdx.x;
    int tx = tid % 16, ty = tid / 16;
    ull acc[8][4];
#pragma unroll
    for (int u = 0; u < 8; u++)
#pragma unroll
        for (int v = 0; v < 4; v++) acc[u][v] = 0ULL;

    int arow  = tid >> 1;
    int acol4 = (tid & 1) * 4;
    int bk  = tid >> 5;
    int bn4 = (tid & 31) * 4;

    // initial tile -> buf 0
    {
        float4 av = *reinterpret_cast<const float4*>(&A[(long long)(m0 + arow) * lda + acol4]);
        As[0][acol4 + 0][arow] = av.x;
        As[0][acol4 + 1][arow] = av.y;
        As[0][acol4 + 2][arow] = av.z;
        As[0][acol4 + 3][arow] = av.w;
        if (BKMAJ) {
            float4 bv = *reinterpret_cast<const float4*>(&Bm[(long long)(n0 + arow) * ldb + acol4]);
            Bs[0][acol4 + 0][arow] = bv.x;
            Bs[0][acol4 + 1][arow] = bv.y;
            Bs[0][acol4 + 2][arow] = bv.z;
            Bs[0][acol4 + 3][arow] = bv.w;
        } else {
            float4 bv = *reinterpret_cast<const float4*>(&Bm[(long long)bk * ldb + n0 + bn4]);
            *reinterpret_cast<float4*>(&Bs[0][bk][bn4]) = bv;
        }
    }
    __syncthreads();

    int buf = 0;
    for (int k0 = 0; k0 < K; k0 += 8, buf ^= 1) {
        bool has_next = (k0 + 8 < K);
        float4 nav, nbv;
        if (has_next) {
            nav = *reinterpret_cast<const float4*>(&A[(long long)(m0 + arow) * lda + k0 + 8 + acol4]);
            if (BKMAJ)
                nbv = *reinterpret_cast<const float4*>(&Bm[(long long)(n0 + arow) * ldb + k0 + 8 + acol4]);
            else
                nbv = *reinterpret_cast<const float4*>(&Bm[(long long)(k0 + 8 + bk) * ldb + n0 + bn4]);
        }
#pragma unroll
        for (int kk = 0; kk < 8; kk++) {
            float4 a0 = *reinterpret_cast<const float4*>(&As[buf][kk][ty * 8]);
            float4 a1 = *reinterpret_cast<const float4*>(&As[buf][kk][ty * 8 + 4]);
            ulonglong2 b0 = *reinterpret_cast<const ulonglong2*>(&Bs[buf][kk][tx * 8]);
            ulonglong2 b1 = *reinterpret_cast<const ulonglong2*>(&Bs[buf][kk][tx * 8 + 4]);
            ull bp[4] = {b0.x, b0.y, b1.x, b1.y};
            float a[8] = {a0.x, a0.y, a0.z, a0.w, a1.x, a1.y, a1.z, a1.w};
#pragma unroll
            for (int u = 0; u < 8; u++) {
                ull ap = pack2(a[u], a[u]);
#pragma unroll
                for (int v = 0; v < 4; v++) acc[u][v] = ffma2(ap, bp[v], acc[u][v]);
            }
        }
        if (has_next) {
            As[buf ^ 1][acol4 + 0][arow] = nav.x;
            As[buf ^ 1][acol4 + 1][arow] = nav.y;
            As[buf ^ 1][acol4 + 2][arow] = nav.z;
            As[buf ^ 1][acol4 + 3][arow] = nav.w;
            if (BKMAJ) {
                Bs[buf ^ 1][acol4 + 0][arow] = nbv.x;
                Bs[buf ^ 1][acol4 + 1][arow] = nbv.y;
                Bs[buf ^ 1][acol4 + 2][arow] = nbv.z;
                Bs[buf ^ 1][acol4 + 3][arow] = nbv.w;
            } else {
                *reinterpret_cast<float4*>(&Bs[buf ^ 1][bk][bn4]) = nbv;
            }
        }
        __syncthreads();
    }

#pragma unroll
    for (int u = 0; u < 8; u++) {
        int m = m0 + ty * 8 + u;
#pragma unroll
        for (int v4 = 0; v4 < 4; v4++) {
            float2 pr = unpack2(acc[u][v4]);
            float vv[2] = {pr.x, pr.y};
#pragma unroll
            for (int e = 0; e < 2; e++) {
                int n = n0 + tx * 8 + v4 * 2 + e;
                float val = vv[e] * alpha;
                if (bias) val += bias[n];
                if (EPI == 1 || EPI == 3) val = gelu_f(val);
                if (EPI == 2) val = 1.f / (1.f + expf(-val));
                if (EPI == 3) val -= extra[(long long)m * ldc + n];
                Cm[(long long)m * ldc + n] = val;
            }
        }
    }
}

// ---------------- direct conv 4x4 s2 p1 + relu (f32x2, double-buffered) ----------------
// grid (32 spatial tiles, 4 oc-blocks, 16 batches), 128 threads
__global__ __launch_bounds__(128) void conv_l1_k(const float* __restrict__ x,
                                                 const float* __restrict__ w,
                                                 const float* __restrict__ bias,
                                                 float* __restrict__ dw) {
    __shared__ float sw[2][2 * 512];        // [buf][ic_l*512 + rs*32 + oc]
    __shared__ float sx[2][2 * 646];        // [buf][ic_l*646 + row*19 + col]
    int tile = blockIdx.x;
    int oc0 = blockIdx.y * 32;
    int b = blockIdx.z;
    int i0 = (tile / 8) * 16;
    int j0 = (tile % 8) * 8;
    int t = threadIdx.x;
    int pg = t % 32, os = t / 32;
    int iL2 = 2 * (pg / 8), jL2 = 2 * (pg % 8);
    int oc_l = t >> 4, rs = t & 15;
    const float* xb = x + (long long)b * CH * HH * WW;

    // x-load descriptors (ic-independent)
    int  xg[10], xs[10];
    bool xv[10];
#pragma unroll
    for (int q = 0; q < 10; q++) {
        int idx = t + 128 * q;                 // < 1224 valid
        int ic_l = idx / 612;
        int r2 = idx % 612;
        int row = r2 / 18, col = r2 % 18;
        int gy = 2 * i0 - 1 + row, gx = 2 * j0 - 1 + col;
        bool inb = (idx < 1224);
        xv[q] = inb && gy >= 0 && gy < HH && gx >= 0 && gx < WW;
        xg[q] = ic_l * HH * WW + gy * WW + gx;
        xs[q] = inb ? (ic_l * 646 + row * 19 + col) : -1;
    }

    ull acc[4][4];
#pragma unroll
    for (int p = 0; p < 4; p++)
#pragma unroll
        for (int m = 0; m < 4; m++) acc[p][m] = 0ULL;

    float xr[10], wr[8];
    // prefetch chunk 0 (ic = 0,1)
#pragma unroll
    for (int q = 0; q < 10; q++) xr[q] = xv[q] ? xb[xg[q]] : 0.f;
#pragma unroll
    for (int il = 0; il < 2; il++)
#pragma unroll
        for (int q = 0; q < 4; q++)
            wr[il * 4 + q] = w[(long long)(oc0 + oc_l + 8 * q) * 2048 + il * 16 + rs];
#pragma unroll
    for (int q = 0; q < 10; q++) if (xs[q] >= 0) sx[0][xs[q]] = xr[q];
#pragma unroll
    for (int il = 0; il < 2; il++)
#pragma unroll
        for (int q = 0; q < 4; q++)
            sw[0][il * 512 + rs * 32 + oc_l + 8 * q] = wr[il * 4 + q];
    __syncthreads();

    for (int icb = 0; icb < 64; icb++) {
        int buf = icb & 1;
        bool nxt = (icb < 63);
        if (nxt) {
            int ic = 2 * (icb + 1);
            const float* xpc = xb + (long long)ic * HH * WW;
#pragma unroll
            for (int q = 0; q < 10; q++) xr[q] = xv[q] ? xpc[xg[q]] : 0.f;
#pragma unroll
            for (int il = 0; il < 2; il++)
#pragma unroll
                for (int q = 0; q < 4; q++)
                    wr[il * 4 + q] = w[(long long)(oc0 + oc_l + 8 * q) * 2048 + (ic + il) * 16 + rs];
        }
#pragma unroll
        for (int il = 0; il < 2; il++) {
            const float* sxp = &sx[buf][il * 646];
            const float* swp = &sw[buf][il * 512];
#pragma unroll
            for (int r = 0; r < 4; r++) {
#pragma unroll
                for (int s = 0; s < 4; s++) {
                    int xo = (iL2 + r) * 19 + jL2 + s;
                    ull xm0 = pack2(sxp[xo],       sxp[xo]);
                    ull xm1 = pack2(sxp[xo + 152], sxp[xo + 152]);
                    ull xm2 = pack2(sxp[xo + 304], sxp[xo + 304]);
                    ull xm3 = pack2(sxp[xo + 456], sxp[xo + 456]);
                    int wbase = (r * 4 + s) * 32 + os * 8;
#pragma unroll
                    for (int p = 0; p < 4; p++) {
                        ull wp = *reinterpret_cast<const ull*>(&swp[wbase + 2 * p]);
                        acc[p][0] = ffma2(wp, xm0, acc[p][0]);
                        acc[p][1] = ffma2(wp, xm1, acc[p][1]);
                        acc[p][2] = ffma2(wp, xm2, acc[p][2]);
                        acc[p][3] = ffma2(wp, xm3, acc[p][3]);
                    }
                }
            }
        }
        if (nxt) {
#pragma unroll
            for (int q = 0; q < 10; q++) if (xs[q] >= 0) sx[buf ^ 1][xs[q]] = xr[q];
#pragma unroll
            for (int il = 0; il < 2; il++)
#pragma unroll
                for (int q = 0; q < 4; q++)
                    sw[buf ^ 1][il * 512 + rs * 32 + oc_l + 8 * q] = wr[il * 4 + q];
        }
        __syncthreads();
    }

#pragma unroll
    for (int p = 0; p < 4; p++) {
        int oca = oc0 + os * 8 + 2 * p;
        float b0 = bias[oca], b1 = bias[oca + 1];
#pragma unroll
        for (int m = 0; m < 4; m++) {
            float2 pr = unpack2(acc[p][m]);
            int i = i0 + pg / 8 + 4 * m;
            int j = j0 + pg % 8;
            long long o0 = (((long long)b * CH + oca) * HO + i) * WO + j;
            dw[o0]                    = fmaxf(pr.x + b0, 0.f);
            dw[o0 + (long long)HO*WO] = fmaxf(pr.y + b1, 0.f);
        }
    }
}

// ---------------- column softmax over q axis ----------------
__global__ void softmax_q_k(float* __restrict__ S) {
    __shared__ float sm[8][32], ss[8][32];
    int g = blockIdx.y;
    int k0 = blockIdx.x * 32;
    int tid = threadIdx.x;
    int kc = tid % 32;
    int qh = tid / 32;
    float* Sg = S + (long long)g * QL * QL + k0 + kc;
    float m = -INFINITY, s = 0.f;
    for (int q = qh; q < QL; q += 8) {
        float v = Sg[(long long)q * QL];
        if (v > m) { s = s * expf(m - v) + 1.f; m = v; }
        else s += expf(v - m);
    }
    sm[qh][kc] = m;
    ss[qh][kc] = s;
    __syncthreads();
    if (tid < 32) {
        float M = sm[0][kc], Sm = ss[0][kc];
#pragma unroll
        for (int r = 1; r < 8; r++) {
            float m2 = sm[r][kc], s2 = ss[r][kc];
            float nm = fmaxf(M, m2);
            Sm = Sm * expf(M - nm) + s2 * expf(m2 - nm);
            M = nm;
        }
        sm[0][kc] = M;
        ss[0][kc] = 1.f / Sm;
    }
    __syncthreads();
    float M = sm[0][kc], inv = ss[0][kc];
    for (int q = qh; q < QL; q += 8) {
        float v = Sg[(long long)q * QL];
        Sg[(long long)q * QL] = expf(v - M) * inv;
    }
}

// ---------------- per-token layernorm ----------------
__global__ void ln_k(const float* __restrict__ X, float* __restrict__ Y,
                     const float* __restrict__ gw, const float* __restrict__ bw) {
    int warp = threadIdx.x / 32, lane = threadIdx.x % 32;
    long long t = (long long)blockIdx.x * 8 + warp;
    const float* xv = X + t * 128;
    float v[4];
    float sum = 0.f;
#pragma unroll
    for (int i = 0; i < 4; i++) { v[i] = xv[lane + 32 * i]; sum += v[i]; }
#pragma unroll
    for (int o = 16; o; o >>= 1) sum += __shfl_xor_sync(0xffffffffu, sum, o);
    float mean = sum * (1.f / 128.f);
    float vs = 0.f;
#pragma unroll
    for (int i = 0; i < 4; i++) { float d = v[i] - mean; vs += d * d; }
#pragma unroll
    for (int o = 16; o; o >>= 1) vs += __shfl_xor_sync(0xffffffffu, vs, o);
    float inv = rsqrtf(vs * (1.f / 128.f) + 1e-5f);
#pragma unroll
    for (int i = 0; i < 4; i++) {
        int c = lane + 32 * i;
        Y[t * 128 + c] = (v[i] - mean) * inv * gw[c] + bw[c];
    }
}

// ---------------- out = gate * LN(x2 + x3) ----------------
__global__ void addlngate_k(const float* __restrict__ X2, const float* __restrict__ X3,
                            const float* __restrict__ G,
                            const float* __restrict__ gw, const float* __restrict__ bw,
                            float* __restrict__ Y) {
    int warp = threadIdx.x / 32, lane = threadIdx.x % 32;
    long long t = (long long)blockIdx.x * 8 + warp;
    float v[4];
    float sum = 0.f;
#pragma unroll
    for (int i = 0; i < 4; i++) {
        int c = lane + 32 * i;
        v[i] = X2[t * 128 + c] + X3[t * 128 + c];
        sum += v[i];
    }
#pragma unroll
    for (int o = 16; o; o >>= 1) sum += __shfl_xor_sync(0xffffffffu, sum, o);
    float mean = sum * (1.f / 128.f);
    float vs = 0.f;
#pragma unroll
    for (int i = 0; i < 4; i++) { float d = v[i] - mean; vs += d * d; }
#pragma unroll
    for (int o = 16; o; o >>= 1) vs += __shfl_xor_sync(0xffffffffu, vs, o);
    float inv = rsqrtf(vs * (1.f / 128.f) + 1e-5f);
#pragma unroll
    for (int i = 0; i < 4; i++) {
        int c = lane + 32 * i;
        float nrm = (v[i] - mean) * inv * gw[c] + bw[c];
        Y[t * 128 + c] = G[t * 128 + c] * nrm;
    }
}

// ---------------- final combine ----------------
__global__ void final_k(const float* __restrict__ x, const float* __restrict__ ffn,
                        const float* __restrict__ ytok, const float* __restrict__ dw,
                        float* __restrict__ out) {
    __shared__ float sf[32][65], sy[32][65];
    int i = blockIdx.x, b = blockIdx.y, tid = threadIdx.x;
    float pos_i = (float)(i * 127) / 63.f;
    int y0 = (int)floorf(pos_i);
    int y1 = min(y0 + 1, 127);
    float wy = pos_i - (float)y0;
    for (int cc = 0; cc < 4; cc++) {
        for (int idx = tid; idx < 64 * 32; idx += 256) {
            int j = idx / 32, cl = idx % 32;
            long long t = (long long)b * TOK + i * 64 + j;
            sf[cl][j] = ffn[t * 128 + cc * 32 + cl];
            sy[cl][j] = ytok[t * 128 + cc * 32 + cl];
        }
        __syncthreads();
        for (int idx = tid; idx < 32 * 64; idx += 256) {
            int cl = idx / 64, j = idx % 64;
            int c = cc * 32 + cl;
            float pos_j = (float)(j * 127) / 63.f;
            int x0 = (int)floorf(pos_j);
            int x1i = min(x0 + 1, 127);
            float wx = pos_j - (float)x0;
            const float* xb = x + (long long)(b * CH + c) * HH * WW;
            float r0 = xb[y0 * WW + x0] * (1.f - wy) + xb[y1 * WW + x0] * wy;
            float r1 = xb[y0 * WW + x1i] * (1.f - wy) + xb[y1 * WW + x1i] * wy;
            float dv = r0 * (1.f - wx) + r1 * wx;
            long long oi = (((long long)b * CH + c) * HO + i) * WO + j;
            float dwv = dw[oi];
            out[oi] = sf[cl][j] * (dv - dwv) + sy[cl][j];
        }
        __syncthreads();
    }
}

// ---------------- launch ----------------
extern "C" void kernel_launch(void* const* d_in, const int* in_sizes, int n_in,
                              void* d_out, int out_size) {
    (void)in_sizes; (void)n_in; (void)out_size;
    const float* x       = (const float*)d_in[0];
    const float* conv1_w = (const float*)d_in[1];
    const float* conv1_b = (const float*)d_in[2];
    const float* l1_w    = (const float*)d_in[3];
    const float* l1_b    = (const float*)d_in[4];
    const float* ln1_g   = (const float*)d_in[5];
    const float* ln1_b   = (const float*)d_in[6];
    const float* fc1_w   = (const float*)d_in[7];
    const float* fc1_b   = (const float*)d_in[8];
    const float* div_w   = (const float*)d_in[9];
    const float* div_b   = (const float*)d_in[10];
    const float* fc2_w   = (const float*)d_in[11];
    const float* fc2_b   = (const float*)d_in[12];
    const float* ln3_g   = (const float*)d_in[13];
    const float* ln3_b   = (const float*)d_in[14];
    const float* fc3a_w  = (const float*)d_in[15];
    const float* fc3a_b  = (const float*)d_in[16];
    const float* fc3b_w  = (const float*)d_in[17];
    const float* fc3b_b  = (const float*)d_in[18];
    const float* lnn_g   = (const float*)d_in[19];
    const float* lnn_b   = (const float*)d_in[20];
    const float* act_w   = (const float*)d_in[21];
    const float* act_b   = (const float*)d_in[22];
    float* out = (float*)d_out;

    float *yL, *yHH, *hlh, *y, *S, *attn, *t0, *t1, *x1, *x2, *x3, *gate, *ffn, *dw;
    cudaGetSymbolAddress((void**)&yL,   g_yL);
    cudaGetSymbolAddress((void**)&yHH,  g_yHH);
    cudaGetSymbolAddress((void**)&hlh,  g_hlh);
    cudaGetSymbolAddress((void**)&y,    g_y);
    cudaGetSymbolAddress((void**)&S,    g_S);
    cudaGetSymbolAddress((void**)&attn, g_attn);
    cudaGetSymbolAddress((void**)&t0,   g_t0);
    cudaGetSymbolAddress((void**)&t1,   g_t1);
    cudaGetSymbolAddress((void**)&x1,   g_x1);
    cudaGetSymbolAddress((void**)&x2,   g_x2);
    cudaGetSymbolAddress((void**)&x3,   g_x3);
    cudaGetSymbolAddress((void**)&gate, g_gate);
    cudaGetSymbolAddress((void**)&ffn,  g_ffn);
    cudaGetSymbolAddress((void**)&dw,   g_dw);

    haar_k<<<dim3(64, 16), 256>>>(x, yL, yHH, hlh);

    gemm_k<true, 0><<<dim3(1, 512, 1), 256>>>(hlh, 0, 256, conv1_w, 0, 256,
                                              y, 0, 128, NT, 128, 256, 1.f, conv1_b, nullptr);

    conv_l1_k<<<dim3(32, 4, 16), 128>>>(x, l1_w, l1_b, dw);

    gemm_k<true, 0><<<dim3(4, 4, NG), 256>>>(yL, (long long)QL * 128, 128,
                                             y, (long long)QL * 128, 128,
                                             S, (long long)QL * QL, QL,
                                             QL, QL, 128, 0.35355339059327373f, nullptr, nullptr);

    softmax_q_k<<<dim3(16, NG), 256>>>(S);

    gemm_k<false, 0><<<dim3(1, 4, NG), 256>>>(S, (long long)QL * QL, QL,
                                              yHH, (long long)QL * 128, 128,
                                              attn, (long long)QL * 128, 128,
                                              QL, 128, QL, 1.f, nullptr, nullptr);

    ln_k<<<8192, 256>>>(attn, t0, ln1_g, ln1_b);
    gemm_k<true, 1><<<dim3(1, 512), 256>>>(t0, 0, 128, fc1_w, 0, 128,
                                           x1, 0, 128, NT, 128, 128, 1.f, fc1_b, nullptr);
    gemm_k<true, 3><<<dim3(1, 512), 256>>>(attn, 0, 128, div_w, 0, 128,
                                           x2, 0, 128, NT, 128, 128, 1.f, div_b, x1);
    gemm_k<true, 1><<<dim3(1, 512), 256>>>(x2, 0, 128, fc2_w, 0, 128,
                                           t1, 0, 128, NT, 128, 128, 1.f, fc2_b, nullptr);
    ln_k<<<8192, 256>>>(attn, t0, ln3_g, ln3_b);
    gemm_k<true, 1><<<dim3(1, 512), 256>>>(t0, 0, 128, fc3a_w, 0, 128,
                                           x2, 0, 128, NT, 128, 128, 1.f, fc3a_b, nullptr);
    gemm_k<true, 0><<<dim3(1, 512), 256>>>(x2, 0, 128, fc3b_w, 0, 128,
                                           x3, 0, 128, NT, 128, 128, 1.f, fc3b_b, nullptr);
    gemm_k<true, 2><<<dim3(1, 512), 256>>>(attn, 0, 128, act_w, 0, 128,
                                           gate, 0, 128, NT, 128, 128, 1.f, act_b, nullptr);
    addlngate_k<<<8192, 256>>>(t1, x3, gate, lnn_g, lnn_b, ffn);

    final_k<<<dim3(64, 16), 256>>>(x, ffn, y, dw, out);
}

// round 6
// speedup vs baseline: 1.3741x; 1.2591x over previous
#include <cuda_runtime.h>
#include <cuda_bf16.h>
#include <math.h>
#include <stdint.h>

// ---------------- problem constants ----------------
#define BB   16
#define CH   128
#define HH   128
#define WW   128
#define HO   64
#define WO   64
#define TOK  4096
#define NT   65536
#define NG   128
#define QL   512

typedef unsigned long long ull;

// ---------------- scratch ----------------
__device__ float g_hlh[(size_t)NT * 256];
__device__ float g_yL [(size_t)NT * 128];
__device__ float g_yHHT[(size_t)NG * 128 * 512];   // V transposed per group [g][c][q]
__device__ float g_y  [(size_t)NT * 128];
__device__ float g_S  [(size_t)NG * QL * QL];
__device__ float g_attn[(size_t)NT * 128];
__device__ float g_t0 [(size_t)NT * 128];
__device__ float g_t1 [(size_t)NT * 128];
__device__ float g_x1 [(size_t)NT * 128];
__device__ float g_x2 [(size_t)NT * 128];
__device__ float g_x3 [(size_t)NT * 128];
__device__ float g_gate[(size_t)NT * 128];
__device__ float g_ffn[(size_t)NT * 128];
__device__ float g_dw [(size_t)BB * CH * HO * WO];

__device__ __forceinline__ float gelu_f(float v) {
    return 0.5f * v * (1.0f + erff(v * 0.70710678118654752f));
}

__device__ __forceinline__ uint32_t smem_u32(const void* p) {
    uint32_t a;
    asm("{ .reg .u64 t; cvta.to.shared.u64 t, %1; cvt.u32.u64 %0, t; }" : "=r"(a) : "l"(p));
    return a;
}
#define SW128(o) ((o) ^ (((o) >> 3) & 0x70))

// ---- mma.sync bf16 helpers (sm_80+ ISA; safe on plain compute_103) ----
__device__ __forceinline__ void ldm_x4(uint32_t* r, uint32_t addr) {
    asm volatile("ldmatrix.sync.aligned.m8n8.x4.shared.b16 {%0,%1,%2,%3}, [%4];"
                 : "=r"(r[0]), "=r"(r[1]), "=r"(r[2]), "=r"(r[3]) : "r"(addr));
}
__device__ __forceinline__ void ldm_x2(uint32_t* r, uint32_t addr) {
    asm volatile("ldmatrix.sync.aligned.m8n8.x2.shared.b16 {%0,%1}, [%2];"
                 : "=r"(r[0]), "=r"(r[1]) : "r"(addr));
}
__device__ __forceinline__ void mma_bf16(float* d, const uint32_t* a, const uint32_t* b) {
    asm volatile("mma.sync.aligned.m16n8k16.row.col.f32.bf16.bf16.f32 "
                 "{%0,%1,%2,%3}, {%4,%5,%6,%7}, {%8,%9}, {%0,%1,%2,%3};"
                 : "+f"(d[0]), "+f"(d[1]), "+f"(d[2]), "+f"(d[3])
                 : "r"(a[0]), "r"(a[1]), "r"(a[2]), "r"(a[3]), "r"(b[0]), "r"(b[1]));
}

// f32x2 helpers (conv path)
__device__ __forceinline__ ull ffma2(ull a, ull b, ull c) {
    ull d;
    asm("fma.rn.f32x2 %0, %1, %2, %3;" : "=l"(d) : "l"(a), "l"(b), "l"(c));
    return d;
}
__device__ __forceinline__ ull pack2(float x, float y) {
    ull r;
    asm("mov.b64 %0, {%1, %2};" : "=l"(r) : "f"(x), "f"(y));
    return r;
}
__device__ __forceinline__ float2 unpack2(ull p) {
    float2 f;
    asm("mov.b64 {%0, %1}, %2;" : "=f"(f.x), "=f"(f.y) : "l"(p));
    return f;
}

// ---------------- Haar DWT -> token layouts (+ V transposed) ----------------
__global__ void haar_k(const float* __restrict__ x,
                       float* __restrict__ yL, float* __restrict__ yHHT,
                       float* __restrict__ hlh) {
    __shared__ float sLL[32][65], sHL[32][65], sLH[32][65], sHH[32][65];
    int i = blockIdx.x, b = blockIdx.y, tid = threadIdx.x;
    for (int cc = 0; cc < 4; cc++) {
        for (int idx = tid; idx < 32 * 64; idx += 256) {
            int cl = idx / 64, j = idx % 64;
            int c = cc * 32 + cl;
            const float* base = x + (((long long)(b * CH + c) * HH + 2 * i) * WW) + 2 * j;
            float a = base[0], bb2 = base[1], cv = base[WW], d = base[WW + 1];
            sLL[cl][j] = (a + bb2 + cv + d) * 0.5f;
            sHL[cl][j] = (a - bb2 + cv - d) * 0.5f;
            sLH[cl][j] = (a + bb2 - cv - d) * 0.5f;
            sHH[cl][j] = (a - bb2 - cv + d) * 0.5f;
        }
        __syncthreads();
        for (int idx = tid; idx < 64 * 32; idx += 256) {
            int j = idx / 32, cl = idx % 32;
            long long t = (long long)b * TOK + i * 64 + j;
            int c = cc * 32 + cl;
            yL [t * 128 + c] = sLL[cl][j];
            hlh[t * 256 + c]       = sHL[cl][j];
            hlh[t * 256 + 128 + c] = sLH[cl][j];
        }
        {
            int g = b * 8 + (i >> 3);
            int qoff = (i & 7) * 64;
            for (int idx = tid; idx < 32 * 64; idx += 256) {
                int cl = idx / 64, j = idx % 64;
                int c = cc * 32 + cl;
                yHHT[((size_t)g * 128 + c) * 512 + qoff + j] = sHH[cl][j];
            }
        }
        __syncthreads();
    }
}

// ---------------- split-bf16 mma.sync GEMM ----------------
// C[128x128 tile] = epi(alpha * A@B^T + bias); A[m][k] fp32, B[n][k] fp32 (K-major)
// EPI: 0 none, 1 gelu, 2 sigmoid, 3 gelu-minus-extra
#define TCG_SMEM 65536

// chunk = 64 cols bf16 -> 128B rows, SW128 swizzle
__device__ __forceinline__ void load_split_tile(const float* __restrict__ G, int ld, int k0,
                                                char* sHi, char* sLo, int t) {
#pragma unroll
    for (int it = 0; it < 8; it++) {
        int idx = t + 256 * it;
        int row = idx >> 4;
        int c4 = (idx & 15) << 2;
        float4 v = *reinterpret_cast<const float4*>(&G[(long long)row * ld + k0 + c4]);
        __nv_bfloat16 h0 = __float2bfloat16(v.x);
        __nv_bfloat16 h1 = __float2bfloat16(v.y);
        __nv_bfloat16 h2 = __float2bfloat16(v.z);
        __nv_bfloat16 h3 = __float2bfloat16(v.w);
        __nv_bfloat16 l0 = __float2bfloat16(v.x - __bfloat162float(h0));
        __nv_bfloat16 l1 = __float2bfloat16(v.y - __bfloat162float(h1));
        __nv_bfloat16 l2 = __float2bfloat16(v.z - __bfloat162float(h2));
        __nv_bfloat16 l3 = __float2bfloat16(v.w - __bfloat162float(h3));
        uint2 hp, lp;
        hp.x = (uint32_t)__bfloat16_as_ushort(h0) | ((uint32_t)__bfloat16_as_ushort(h1) << 16);
        hp.y = (uint32_t)__bfloat16_as_ushort(h2) | ((uint32_t)__bfloat16_as_ushort(h3) << 16);
        lp.x = (uint32_t)__bfloat16_as_ushort(l0) | ((uint32_t)__bfloat16_as_ushort(l1) << 16);
        lp.y = (uint32_t)__bfloat16_as_ushort(l2) | ((uint32_t)__bfloat16_as_ushort(l3) << 16);
        uint32_t byte = (uint32_t)(row * 128 + c4 * 2);
        uint32_t sw = SW128(byte);
        *reinterpret_cast<uint2*>(sHi + sw) = hp;
        *reinterpret_cast<uint2*>(sLo + sw) = lp;
    }
}

template <int EPI>
__global__ __launch_bounds__(256)
void tcgemm_k(const float* __restrict__ A, long long sAg, int lda,
              const float* __restrict__ Bm, long long sBg, int ldb,
              float* __restrict__ Cm, long long sCg, int ldc,
              int K, float alpha,
              const float* __restrict__ bias,
              const float* __restrict__ extra) {
    extern __shared__ char smem[];
    uint32_t sb = smem_u32(smem);
    int t = threadIdx.x;
    int wid = t >> 5, lane = t & 31;
    int n0 = blockIdx.x * 128;
    int m0 = blockIdx.y * 128;
    int g = blockIdx.z;
    A  += (long long)g * sAg + (long long)m0 * lda;
    Bm += (long long)g * sBg + (long long)n0 * ldb;
    Cm += (long long)g * sCg;
    if (EPI == 3) extra += (long long)g * sCg;

    char* aHi = smem;
    char* aLo = smem + 16384;
    char* bHi = smem + 32768;
    char* bLo = smem + 49152;
    uint32_t aHiA = sb, aLoA = sb + 16384, bHiA = sb + 32768, bLoA = sb + 49152;

    // warp tiling: 2x4 warps, each 64x32
    int wm = wid >> 2;            // 0..1 -> m offset 64*wm
    int wn = wid & 3;             // 0..3 -> n offset 32*wn

    float acc[4][4][4];
#pragma unroll
    for (int mi = 0; mi < 4; mi++)
#pragma unroll
        for (int ni = 0; ni < 4; ni++)
#pragma unroll
            for (int e = 0; e < 4; e++) acc[mi][ni][e] = 0.f;

    // ldmatrix source addresses (within a 128-row x 128-byte buffer)
    // A x4: row_in_tile = lane%16, khalf = lane/16 (0/1 -> +8 cols)
    int a_row_l = lane & 15;
    int a_k8    = (lane >> 4) << 3;
    // B x2: row_in_tile = lane%8, khalf = (lane>>3)&1
    int b_row_l = lane & 7;
    int b_k8    = ((lane >> 3) & 1) << 3;

    int nchunks = K >> 6;
    for (int ch = 0; ch < nchunks; ch++) {
        load_split_tile(A,  lda, ch * 64, aHi, aLo, t);
        load_split_tile(Bm, ldb, ch * 64, bHi, bLo, t);
        __syncthreads();

#pragma unroll
        for (int ks = 0; ks < 4; ks++) {
            uint32_t Bh[4][2], Bl[4][2];
#pragma unroll
            for (int ni = 0; ni < 4; ni++) {
                uint32_t byte = (uint32_t)((wn * 32 + ni * 8 + b_row_l) * 128 +
                                           (ks * 16 + b_k8) * 2);
                uint32_t sw = SW128(byte);
                ldm_x2(Bh[ni], bHiA + sw);
                ldm_x2(Bl[ni], bLoA + sw);
            }
#pragma unroll
            for (int mi = 0; mi < 4; mi++) {
                uint32_t Ah[4], Al[4];
                uint32_t byte = (uint32_t)((wm * 64 + mi * 16 + a_row_l) * 128 +
                                           (ks * 16 + a_k8) * 2);
                uint32_t sw = SW128(byte);
                ldm_x4(Ah, aHiA + sw);
                ldm_x4(Al, aLoA + sw);
#pragma unroll
                for (int ni = 0; ni < 4; ni++) {
                    mma_bf16(acc[mi][ni], Ah, Bh[ni]);
                    mma_bf16(acc[mi][ni], Ah, Bl[ni]);
                    mma_bf16(acc[mi][ni], Al, Bh[ni]);
                }
            }
        }
        __syncthreads();
    }

    // epilogue: fragment layout m16n8 — row = lane/4 (+8 for regs 2,3), col = (lane%4)*2
    int rbase = m0 + wm * 64 + (lane >> 2);
    int cbase = n0 + wn * 32 + (lane & 3) * 2;
#pragma unroll
    for (int mi = 0; mi < 4; mi++) {
#pragma unroll
        for (int h = 0; h < 2; h++) {
            int m = rbase + mi * 16 + h * 8;
            float* crow = Cm + (long long)m * ldc;
            const float* erow = (EPI == 3) ? (extra + (long long)m * ldc) : nullptr;
#pragma unroll
            for (int ni = 0; ni < 4; ni++) {
                int c = cbase + ni * 8;
                float v0 = acc[mi][ni][2 * h]     * alpha;
                float v1 = acc[mi][ni][2 * h + 1] * alpha;
                if (bias) { v0 += bias[c]; v1 += bias[c + 1]; }
                if (EPI == 1 || EPI == 3) { v0 = gelu_f(v0); v1 = gelu_f(v1); }
                if (EPI == 2) {
                    v0 = 1.f / (1.f + expf(-v0));
                    v1 = 1.f / (1.f + expf(-v1));
                }
                if (EPI == 3) {
                    float2 ev = *reinterpret_cast<const float2*>(&erow[c]);
                    v0 -= ev.x; v1 -= ev.y;
                }
                float2 o; o.x = v0; o.y = v1;
                *reinterpret_cast<float2*>(&crow[c]) = o;
            }
        }
    }
}

// ---------------- direct conv 4x4 s2 p1 + relu (f32x2) ----------------
__global__ __launch_bounds__(128) void conv_l1_k(const float* __restrict__ x,
                                                 const float* __restrict__ w,
                                                 const float* __restrict__ bias,
                                                 float* __restrict__ dw) {
    __shared__ float sw[2][2 * 512];
    __shared__ float sx[2][2 * 646];
    int tile = blockIdx.x;
    int oc0 = blockIdx.y * 32;
    int b = blockIdx.z;
    int i0 = (tile / 8) * 16;
    int j0 = (tile % 8) * 8;
    int t = threadIdx.x;
    int pg = t % 32, os = t / 32;
    int iL2 = 2 * (pg / 8), jL2 = 2 * (pg % 8);
    int oc_l = t >> 4, rs = t & 15;
    const float* xb = x + (long long)b * CH * HH * WW;

    int  xg[10], xs[10];
    bool xv[10];
#pragma unroll
    for (int q = 0; q < 10; q++) {
        int idx = t + 128 * q;
        int ic_l = idx / 612;
        int r2 = idx % 612;
        int row = r2 / 18, col = r2 % 18;
        int gy = 2 * i0 - 1 + row, gx = 2 * j0 - 1 + col;
        bool inb = (idx < 1224);
        xv[q] = inb && gy >= 0 && gy < HH && gx >= 0 && gx < WW;
        xg[q] = ic_l * HH * WW + gy * WW + gx;
        xs[q] = inb ? (ic_l * 646 + row * 19 + col) : -1;
    }

    ull acc[4][4];
#pragma unroll
    for (int p = 0; p < 4; p++)
#pragma unroll
        for (int m = 0; m < 4; m++) acc[p][m] = 0ULL;

    float xr[10], wr[8];
#pragma unroll
    for (int q = 0; q < 10; q++) xr[q] = xv[q] ? xb[xg[q]] : 0.f;
#pragma unroll
    for (int il = 0; il < 2; il++)
#pragma unroll
        for (int q = 0; q < 4; q++)
            wr[il * 4 + q] = w[(long long)(oc0 + oc_l + 8 * q) * 2048 + il * 16 + rs];
#pragma unroll
    for (int q = 0; q < 10; q++) if (xs[q] >= 0) sx[0][xs[q]] = xr[q];
#pragma unroll
    for (int il = 0; il < 2; il++)
#pragma unroll
        for (int q = 0; q < 4; q++)
            sw[0][il * 512 + rs * 32 + oc_l + 8 * q] = wr[il * 4 + q];
    __syncthreads();

    for (int icb = 0; icb < 64; icb++) {
        int buf = icb & 1;
        bool nxt = (icb < 63);
        if (nxt) {
            int ic = 2 * (icb + 1);
            const float* xpc = xb + (long long)ic * HH * WW;
#pragma unroll
            for (int q = 0; q < 10; q++) xr[q] = xv[q] ? xpc[xg[q]] : 0.f;
#pragma unroll
            for (int il = 0; il < 2; il++)
#pragma unroll
                for (int q = 0; q < 4; q++)
                    wr[il * 4 + q] = w[(long long)(oc0 + oc_l + 8 * q) * 2048 + (ic + il) * 16 + rs];
        }
#pragma unroll
        for (int il = 0; il < 2; il++) {
            const float* sxp = &sx[buf][il * 646];
            const float* swp = &sw[buf][il * 512];
#pragma unroll
            for (int r = 0; r < 4; r++) {
#pragma unroll
                for (int s = 0; s < 4; s++) {
                    int xo = (iL2 + r) * 19 + jL2 + s;
                    ull xm0 = pack2(sxp[xo],       sxp[xo]);
                    ull xm1 = pack2(sxp[xo + 152], sxp[xo + 152]);
                    ull xm2 = pack2(sxp[xo + 304], sxp[xo + 304]);
                    ull xm3 = pack2(sxp[xo + 456], sxp[xo + 456]);
                    int wbase = (r * 4 + s) * 32 + os * 8;
#pragma unroll
                    for (int p = 0; p < 4; p++) {
                        ull wp = *reinterpret_cast<const ull*>(&swp[wbase + 2 * p]);
                        acc[p][0] = ffma2(wp, xm0, acc[p][0]);
                        acc[p][1] = ffma2(wp, xm1, acc[p][1]);
                        acc[p][2] = ffma2(wp, xm2, acc[p][2]);
                        acc[p][3] = ffma2(wp, xm3, acc[p][3]);
                    }
                }
            }
        }
        if (nxt) {
#pragma unroll
            for (int q = 0; q < 10; q++) if (xs[q] >= 0) sx[buf ^ 1][xs[q]] = xr[q];
#pragma unroll
            for (int il = 0; il < 2; il++)
#pragma unroll
                for (int q = 0; q < 4; q++)
                    sw[buf ^ 1][il * 512 + rs * 32 + oc_l + 8 * q] = wr[il * 4 + q];
        }
        __syncthreads();
    }

#pragma unroll
    for (int p = 0; p < 4; p++) {
        int oca = oc0 + os * 8 + 2 * p;
        float b0 = bias[oca], b1 = bias[oca + 1];
#pragma unroll
        for (int m = 0; m < 4; m++) {
            float2 pr = unpack2(acc[p][m]);
            int i = i0 + pg / 8 + 4 * m;
            int j = j0 + pg % 8;
            long long o0 = (((long long)b * CH + oca) * HO + i) * WO + j;
            dw[o0]                      = fmaxf(pr.x + b0, 0.f);
            dw[o0 + (long long)HO * WO] = fmaxf(pr.y + b1, 0.f);
        }
    }
}

// ---------------- column softmax over q axis ----------------
__global__ void softmax_q_k(float* __restrict__ S) {
    __shared__ float sm[8][32], ss[8][32];
    int g = blockIdx.y;
    int k0 = blockIdx.x * 32;
    int tid = threadIdx.x;
    int kc = tid % 32;
    int qh = tid / 32;
    float* Sg = S + (long long)g * QL * QL + k0 + kc;
    float m = -INFINITY, s = 0.f;
    for (int q = qh; q < QL; q += 8) {
        float v = Sg[(long long)q * QL];
        if (v > m) { s = s * expf(m - v) + 1.f; m = v; }
        else s += expf(v - m);
    }
    sm[qh][kc] = m;
    ss[qh][kc] = s;
    __syncthreads();
    if (tid < 32) {
        float M = sm[0][kc], Sm = ss[0][kc];
#pragma unroll
        for (int r = 1; r < 8; r++) {
            float m2 = sm[r][kc], s2 = ss[r][kc];
            float nm = fmaxf(M, m2);
            Sm = Sm * expf(M - nm) + s2 * expf(m2 - nm);
            M = nm;
        }
        sm[0][kc] = M;
        ss[0][kc] = 1.f / Sm;
    }
    __syncthreads();
    float M = sm[0][kc], inv = ss[0][kc];
    for (int q = qh; q < QL; q += 8) {
        float v = Sg[(long long)q * QL];
        Sg[(long long)q * QL] = expf(v - M) * inv;
    }
}

// ---------------- per-token layernorm ----------------
__global__ void ln_k(const float* __restrict__ X, float* __restrict__ Y,
                     const float* __restrict__ gw, const float* __restrict__ bw) {
    int warp = threadIdx.x / 32, lane = threadIdx.x % 32;
    long long t = (long long)blockIdx.x * 8 + warp;
    const float* xv = X + t * 128;
    float v[4];
    float sum = 0.f;
#pragma unroll
    for (int i = 0; i < 4; i++) { v[i] = xv[lane + 32 * i]; sum += v[i]; }
#pragma unroll
    for (int o = 16; o; o >>= 1) sum += __shfl_xor_sync(0xffffffffu, sum, o);
    float mean = sum * (1.f / 128.f);
    float vs = 0.f;
#pragma unroll
    for (int i = 0; i < 4; i++) { float d = v[i] - mean; vs += d * d; }
#pragma unroll
    for (int o = 16; o; o >>= 1) vs += __shfl_xor_sync(0xffffffffu, vs, o);
    float inv = rsqrtf(vs * (1.f / 128.f) + 1e-5f);
#pragma unroll
    for (int i = 0; i < 4; i++) {
        int c = lane + 32 * i;
        Y[t * 128 + c] = (v[i] - mean) * inv * gw[c] + bw[c];
    }
}

// ---------------- out = gate * LN(x2 + x3) ----------------
__global__ void addlngate_k(const float* __restrict__ X2, const float* __restrict__ X3,
                            const float* __restrict__ G,
                            const float* __restrict__ gw, const float* __restrict__ bw,
                            float* __restrict__ Y) {
    int warp = threadIdx.x / 32, lane = threadIdx.x % 32;
    long long t = (long long)blockIdx.x * 8 + warp;
    float v[4];
    float sum = 0.f;
#pragma unroll
    for (int i = 0; i < 4; i++) {
        int c = lane + 32 * i;
        v[i] = X2[t * 128 + c] + X3[t * 128 + c];
        sum += v[i];
    }
#pragma unroll
    for (int o = 16; o; o >>= 1) sum += __shfl_xor_sync(0xffffffffu, sum, o);
    float mean = sum * (1.f / 128.f);
    float vs = 0.f;
#pragma unroll
    for (int i = 0; i < 4; i++) { float d = v[i] - mean; vs += d * d; }
#pragma unroll
    for (int o = 16; o; o >>= 1) vs += __shfl_xor_sync(0xffffffffu, vs, o);
    float inv = rsqrtf(vs * (1.f / 128.f) + 1e-5f);
#pragma unroll
    for (int i = 0; i < 4; i++) {
        int c = lane + 32 * i;
        float nrm = (v[i] - mean) * inv * gw[c] + bw[c];
        Y[t * 128 + c] = G[t * 128 + c] * nrm;
    }
}

// ---------------- final combine ----------------
__global__ void final_k(const float* __restrict__ x, const float* __restrict__ ffn,
                        const float* __restrict__ ytok, const float* __restrict__ dw,
                        float* __restrict__ out) {
    __shared__ float sf[32][65], sy[32][65];
    int i = blockIdx.x, b = blockIdx.y, tid = threadIdx.x;
    float pos_i = (float)(i * 127) / 63.f;
    int y0 = (int)floorf(pos_i);
    int y1 = min(y0 + 1, 127);
    float wy = pos_i - (float)y0;
    for (int cc = 0; cc < 4; cc++) {
        for (int idx = tid; idx < 64 * 32; idx += 256) {
            int j = idx / 32, cl = idx % 32;
            long long t = (long long)b * TOK + i * 64 + j;
            sf[cl][j] = ffn[t * 128 + cc * 32 + cl];
            sy[cl][j] = ytok[t * 128 + cc * 32 + cl];
        }
        __syncthreads();
        for (int idx = tid; idx < 32 * 64; idx += 256) {
            int cl = idx / 64, j = idx % 64;
            int c = cc * 32 + cl;
            float pos_j = (float)(j * 127) / 63.f;
            int x0 = (int)floorf(pos_j);
            int x1i = min(x0 + 1, 127);
            float wx = pos_j - (float)x0;
            const float* xb = x + (long long)(b * CH + c) * HH * WW;
            float r0 = xb[y0 * WW + x0] * (1.f - wy) + xb[y1 * WW + x0] * wy;
            float r1 = xb[y0 * WW + x1i] * (1.f - wy) + xb[y1 * WW + x1i] * wy;
            float dv = r0 * (1.f - wx) + r1 * wx;
            long long oi = (((long long)b * CH + c) * HO + i) * WO + j;
            float dwv = dw[oi];
            out[oi] = sf[cl][j] * (dv - dwv) + sy[cl][j];
        }
        __syncthreads();
    }
}

// ---------------- launch ----------------
extern "C" void kernel_launch(void* const* d_in, const int* in_sizes, int n_in,
                              void* d_out, int out_size) {
    (void)in_sizes; (void)n_in; (void)out_size;
    const float* x       = (const float*)d_in[0];
    const float* conv1_w = (const float*)d_in[1];
    const float* conv1_b = (const float*)d_in[2];
    const float* l1_w    = (const float*)d_in[3];
    const float* l1_b    = (const float*)d_in[4];
    const float* ln1_g   = (const float*)d_in[5];
    const float* ln1_b   = (const float*)d_in[6];
    const float* fc1_w   = (const float*)d_in[7];
    const float* fc1_b   = (const float*)d_in[8];
    const float* div_w   = (const float*)d_in[9];
    const float* div_b   = (const float*)d_in[10];
    const float* fc2_w   = (const float*)d_in[11];
    const float* fc2_b   = (const float*)d_in[12];
    const float* ln3_g   = (const float*)d_in[13];
    const float* ln3_b   = (const float*)d_in[14];
    const float* fc3a_w  = (const float*)d_in[15];
    const float* fc3a_b  = (const float*)d_in[16];
    const float* fc3b_w  = (const float*)d_in[17];
    const float* fc3b_b  = (const float*)d_in[18];
    const float* lnn_g   = (const float*)d_in[19];
    const float* lnn_b   = (const float*)d_in[20];
    const float* act_w   = (const float*)d_in[21];
    const float* act_b   = (const float*)d_in[22];
    float* out = (float*)d_out;

    float *yL, *yHHT, *hlh, *y, *S, *attn, *t0, *t1, *x1, *x2, *x3, *gate, *ffn, *dw;
    cudaGetSymbolAddress((void**)&yL,   g_yL);
    cudaGetSymbolAddress((void**)&yHHT, g_yHHT);
    cudaGetSymbolAddress((void**)&hlh,  g_hlh);
    cudaGetSymbolAddress((void**)&y,    g_y);
    cudaGetSymbolAddress((void**)&S,    g_S);
    cudaGetSymbolAddress((void**)&attn, g_attn);
    cudaGetSymbolAddress((void**)&t0,   g_t0);
    cudaGetSymbolAddress((void**)&t1,   g_t1);
    cudaGetSymbolAddress((void**)&x1,   g_x1);
    cudaGetSymbolAddress((void**)&x2,   g_x2);
    cudaGetSymbolAddress((void**)&x3,   g_x3);
    cudaGetSymbolAddress((void**)&gate, g_gate);
    cudaGetSymbolAddress((void**)&ffn,  g_ffn);
    cudaGetSymbolAddress((void**)&dw,   g_dw);

    cudaFuncSetAttribute(tcgemm_k<0>, cudaFuncAttributeMaxDynamicSharedMemorySize, TCG_SMEM);
    cudaFuncSetAttribute(tcgemm_k<1>, cudaFuncAttributeMaxDynamicSharedMemorySize, TCG_SMEM);
    cudaFuncSetAttribute(tcgemm_k<2>, cudaFuncAttributeMaxDynamicSharedMemorySize, TCG_SMEM);
    cudaFuncSetAttribute(tcgemm_k<3>, cudaFuncAttributeMaxDynamicSharedMemorySize, TCG_SMEM);

    haar_k<<<dim3(64, 16), 256>>>(x, yL, yHHT, hlh);

    // 1x1 conv: y = hlh @ conv1_w^T + b   (K=256)
    tcgemm_k<0><<<dim3(1, 512, 1), 256, TCG_SMEM>>>(hlh, 0, 256, conv1_w, 0, 256,
                                                    y, 0, 128, 256, 1.f, conv1_b, nullptr);

    conv_l1_k<<<dim3(32, 4, 16), 128>>>(x, l1_w, l1_b, dw);

    // S = scale * Q @ K^T
    tcgemm_k<0><<<dim3(4, 4, NG), 256, TCG_SMEM>>>(yL, (long long)QL * 128, 128,
                                                   y, (long long)QL * 128, 128,
                                                   S, (long long)QL * QL, QL,
                                                   128, 0.35355339059327373f, nullptr, nullptr);

    softmax_q_k<<<dim3(16, NG), 256>>>(S);

    // attn = P @ V  (B = V^T per group, K=512)
    tcgemm_k<0><<<dim3(1, 4, NG), 256, TCG_SMEM>>>(S, (long long)QL * QL, QL,
                                                   yHHT, (long long)128 * 512, 512,
                                                   attn, (long long)QL * 128, 128,
                                                   512, 1.f, nullptr, nullptr);

    ln_k<<<8192, 256>>>(attn, t0, ln1_g, ln1_b);
    tcgemm_k<1><<<dim3(1, 512), 256, TCG_SMEM>>>(t0, 0, 128, fc1_w, 0, 128,
                                                 x1, 0, 128, 128, 1.f, fc1_b, nullptr);
    tcgemm_k<3><<<dim3(1, 512), 256, TCG_SMEM>>>(attn, 0, 128, div_w, 0, 128,
                                                 x2, 0, 128, 128, 1.f, div_b, x1);
    tcgemm_k<1><<<dim3(1, 512), 256, TCG_SMEM>>>(x2, 0, 128, fc2_w, 0, 128,
                                                 t1, 0, 128, 128, 1.f, fc2_b, nullptr);
    ln_k<<<8192, 256>>>(attn, t0, ln3_g, ln3_b);
    tcgemm_k<1><<<dim3(1, 512), 256, TCG_SMEM>>>(t0, 0, 128, fc3a_w, 0, 128,
                                                 x2, 0, 128, 128, 1.f, fc3a_b, nullptr);
    tcgemm_k<0><<<dim3(1, 512), 256, TCG_SMEM>>>(x2, 0, 128, fc3b_w, 0, 128,
                                                 x3, 0, 128, 128, 1.f, fc3b_b, nullptr);
    tcgemm_k<2><<<dim3(1, 512), 256, TCG_SMEM>>>(attn, 0, 128, act_w, 0, 128,
                                                 gate, 0, 128, 128, 1.f, act_b, nullptr);
    addlngate_k<<<8192, 256>>>(t1, x3, gate, lnn_g, lnn_b, ffn);

    final_k<<<dim3(64, 16), 256>>>(x, ffn, y, dw, out);
}

// round 7
// speedup vs baseline: 1.4502x; 1.0554x over previous
#include <cuda_runtime.h>
#include <cuda_bf16.h>
#include <math.h>
#include <stdint.h>

// ---------------- problem constants ----------------
#define BB   16
#define CH   128
#define HH   128
#define WW   128
#define HO   64
#define WO   64
#define TOK  4096
#define NT   65536
#define NG   128
#define QL   512

typedef unsigned long long ull;
typedef __nv_bfloat16 bf16;

// ---------------- fp32 scratch (consumed by elementwise) ----------------
__device__ __align__(256) float g_y  [(size_t)NT * 128];
__device__ __align__(256) float g_x1 [(size_t)NT * 128];
__device__ __align__(256) float g_t1 [(size_t)NT * 128];
__device__ __align__(256) float g_x3 [(size_t)NT * 128];
__device__ __align__(256) float g_gate[(size_t)NT * 128];
__device__ __align__(256) float g_ffn[(size_t)NT * 128];
__device__ __align__(256) float g_dw [(size_t)BB * CH * HO * WO];

// ---------------- split bf16 scratch (GEMM operands) ----------------
__device__ __align__(256) bf16 syL_h [(size_t)NT * 128];
__device__ __align__(256) bf16 syL_l [(size_t)NT * 128];
__device__ __align__(256) bf16 shlh_h[(size_t)NT * 256];
__device__ __align__(256) bf16 shlh_l[(size_t)NT * 256];
__device__ __align__(256) bf16 sy_h  [(size_t)NT * 128];
__device__ __align__(256) bf16 sy_l  [(size_t)NT * 128];
__device__ __align__(256) bf16 sS_h  [(size_t)NG * QL * QL];
__device__ __align__(256) bf16 sS_l  [(size_t)NG * QL * QL];
__device__ __align__(256) bf16 syT_h [(size_t)NG * 128 * 512];
__device__ __align__(256) bf16 syT_l [(size_t)NG * 128 * 512];
__device__ __align__(256) bf16 sattn_h[(size_t)NT * 128];
__device__ __align__(256) bf16 sattn_l[(size_t)NT * 128];
__device__ __align__(256) bf16 st0_h [(size_t)NT * 128];
__device__ __align__(256) bf16 st0_l [(size_t)NT * 128];
__device__ __align__(256) bf16 sx2_h [(size_t)NT * 128];
__device__ __align__(256) bf16 sx2_l [(size_t)NT * 128];
__device__ __align__(256) bf16 sW_h  [131072];
__device__ __align__(256) bf16 sW_l  [131072];

__device__ __forceinline__ float gelu_f(float v) {
    return 0.5f * v * (1.0f + erff(v * 0.70710678118654752f));
}
__device__ __forceinline__ uint32_t smem_u32(const void* p) {
    uint32_t a;
    asm("{ .reg .u64 t; cvta.to.shared.u64 t, %1; cvt.u32.u64 %0, t; }" : "=r"(a) : "l"(p));
    return a;
}
#define SW128(o) ((o) ^ (((o) >> 3) & 0x70))

__device__ __forceinline__ void st_split(bf16* H, bf16* L, size_t off, float v) {
    bf16 h = __float2bfloat16(v);
    H[off] = h;
    L[off] = __float2bfloat16(v - __bfloat162float(h));
}

// ---- mma.sync bf16 + ldmatrix + cp.async (sm_80+ ISA; safe on compute_103) ----
__device__ __forceinline__ void ldm_x4(uint32_t* r, uint32_t addr) {
    asm volatile("ldmatrix.sync.aligned.m8n8.x4.shared.b16 {%0,%1,%2,%3}, [%4];"
                 : "=r"(r[0]), "=r"(r[1]), "=r"(r[2]), "=r"(r[3]) : "r"(addr));
}
__device__ __forceinline__ void ldm_x2(uint32_t* r, uint32_t addr) {
    asm volatile("ldmatrix.sync.aligned.m8n8.x2.shared.b16 {%0,%1}, [%2];"
                 : "=r"(r[0]), "=r"(r[1]) : "r"(addr));
}
__device__ __forceinline__ void mma_bf16(float* d, const uint32_t* a, const uint32_t* b) {
    asm volatile("mma.sync.aligned.m16n8k16.row.col.f32.bf16.bf16.f32 "
                 "{%0,%1,%2,%3}, {%4,%5,%6,%7}, {%8,%9}, {%0,%1,%2,%3};"
                 : "+f"(d[0]), "+f"(d[1]), "+f"(d[2]), "+f"(d[3])
                 : "r"(a[0]), "r"(a[1]), "r"(a[2]), "r"(a[3]), "r"(b[0]), "r"(b[1]));
}
__device__ __forceinline__ void cp16(uint32_t dst, const void* src) {
    asm volatile("cp.async.cg.shared.global [%0], [%1], 16;" :: "r"(dst), "l"(src));
}

// f32x2 helpers (conv path)
__device__ __forceinline__ ull ffma2(ull a, ull b, ull c) {
    ull d;
    asm("fma.rn.f32x2 %0, %1, %2, %3;" : "=l"(d) : "l"(a), "l"(b), "l"(c));
    return d;
}
__device__ __forceinline__ ull pack2(float x, float y) {
    ull r;
    asm("mov.b64 %0, {%1, %2};" : "=l"(r) : "f"(x), "f"(y));
    return r;
}
__device__ __forceinline__ float2 unpack2(ull p) {
    float2 f;
    asm("mov.b64 {%0, %1}, %2;" : "=f"(f.x), "=f"(f.y) : "l"(p));
    return f;
}

// ---------------- weight split ----------------
__global__ void wsplit_k(const float* __restrict__ conv1_w, const float* __restrict__ fc1_w,
                         const float* __restrict__ div_w, const float* __restrict__ fc2_w,
                         const float* __restrict__ fc3a_w, const float* __restrict__ fc3b_w,
                         const float* __restrict__ act_w,
                         bf16* __restrict__ WH, bf16* __restrict__ WL) {
    int i = blockIdx.x * 256 + threadIdx.x;
    float v;
    if      (i <  32768) v = conv1_w[i];
    else if (i <  49152) v = fc1_w [i - 32768];
    else if (i <  65536) v = div_w [i - 49152];
    else if (i <  81920) v = fc2_w [i - 65536];
    else if (i <  98304) v = fc3a_w[i - 81920];
    else if (i < 114688) v = fc3b_w[i - 98304];
    else                 v = act_w [i - 114688];
    bf16 h = __float2bfloat16(v);
    WH[i] = h;
    WL[i] = __float2bfloat16(v - __bfloat162float(h));
}

// ---------------- Haar DWT -> split token layouts ----------------
__global__ void haar_k(const float* __restrict__ x,
                       bf16* __restrict__ yLh, bf16* __restrict__ yLl,
                       bf16* __restrict__ yTh, bf16* __restrict__ yTl,
                       bf16* __restrict__ hlhh, bf16* __restrict__ hlhl) {
    __shared__ float sLL[32][65], sHL[32][65], sLH[32][65], sHH[32][65];
    int i = blockIdx.x, b = blockIdx.y, tid = threadIdx.x;
    for (int cc = 0; cc < 4; cc++) {
        for (int idx = tid; idx < 32 * 64; idx += 256) {
            int cl = idx / 64, j = idx % 64;
            int c = cc * 32 + cl;
            const float* base = x + (((long long)(b * CH + c) * HH + 2 * i) * WW) + 2 * j;
            float a = base[0], bb2 = base[1], cv = base[WW], d = base[WW + 1];
            sLL[cl][j] = (a + bb2 + cv + d) * 0.5f;
            sHL[cl][j] = (a - bb2 + cv - d) * 0.5f;
            sLH[cl][j] = (a + bb2 - cv - d) * 0.5f;
            sHH[cl][j] = (a - bb2 - cv + d) * 0.5f;
        }
        __syncthreads();
        for (int idx = tid; idx < 64 * 32; idx += 256) {
            int j = idx / 32, cl = idx % 32;
            size_t t = (size_t)b * TOK + i * 64 + j;
            int c = cc * 32 + cl;
            st_split(yLh, yLl, t * 128 + c, sLL[cl][j]);
            st_split(hlhh, hlhl, t * 256 + c, sHL[cl][j]);
            st_split(hlhh, hlhl, t * 256 + 128 + c, sLH[cl][j]);
        }
        {
            int g = b * 8 + (i >> 3);
            int qoff = (i & 7) * 64;
            for (int idx = tid; idx < 32 * 64; idx += 256) {
                int cl = idx / 64, j = idx % 64;
                int c = cc * 32 + cl;
                st_split(yTh, yTl, ((size_t)g * 128 + c) * 512 + qoff + j, sHH[cl][j]);
            }
        }
        __syncthreads();
    }
}

// ---------------- split-bf16 cp.async pipelined GEMM ----------------
// C = epi(alpha * A@B^T + bias); A,B pre-split bf16, K-major rows.
// EPI: 0 none, 1 gelu, 2 sigmoid, 3 gelu-minus-extra
// OMODE bit0: fp32 out, bit1: split bf16 out
#define BGE_SMEM 131072

__device__ __forceinline__ void issue_chunk(
    const bf16* __restrict__ Ahi, const bf16* __restrict__ Alo, int lda,
    const bf16* __restrict__ Bhi, const bf16* __restrict__ Blo, int ldb,
    int k0, uint32_t base, int t) {
#pragma unroll
    for (int q = 0; q < 4; q++) {
        int idx = q * 256 + t;
        int row = idx >> 3, gg = idx & 7;
        uint32_t sw = SW128((uint32_t)(row * 128 + gg * 16));
        const bf16* a0 = Ahi + (long long)row * lda + k0 + gg * 8;
        const bf16* a1 = Alo + (long long)row * lda + k0 + gg * 8;
        const bf16* b0 = Bhi + (long long)row * ldb + k0 + gg * 8;
        const bf16* b1 = Blo + (long long)row * ldb + k0 + gg * 8;
        cp16(base + sw,         a0);
        cp16(base + 16384 + sw, a1);
        cp16(base + 32768 + sw, b0);
        cp16(base + 49152 + sw, b1);
    }
}

template <int EPI, int OMODE>
__global__ __launch_bounds__(256)
void bgemm_k(const bf16* __restrict__ Ahi, const bf16* __restrict__ Alo, long long sAg, int lda,
             const bf16* __restrict__ Bhi, const bf16* __restrict__ Blo, long long sBg, int ldb,
             float* __restrict__ Cf, bf16* __restrict__ Chi, bf16* __restrict__ Clo,
             long long sCg, int ldc, int K, float alpha,
             const float* __restrict__ bias, const float* __restrict__ extra) {
    extern __shared__ char smem[];
    uint32_t sb = smem_u32(smem);
    int t = threadIdx.x;
    int wid = t >> 5, lane = t & 31;
    int n0 = blockIdx.x * 128;
    int m0 = blockIdx.y * 128;
    int g = blockIdx.z;
    Ahi += (long long)g * sAg + (long long)m0 * lda;
    Alo += (long long)g * sAg + (long long)m0 * lda;
    Bhi += (long long)g * sBg + (long long)n0 * ldb;
    Blo += (long long)g * sBg + (long long)n0 * ldb;
    long long co = (long long)g * sCg;

    int wm = wid >> 2;
    int wn = wid & 3;

    float acc[4][4][4];
#pragma unroll
    for (int mi = 0; mi < 4; mi++)
#pragma unroll
        for (int ni = 0; ni < 4; ni++)
#pragma unroll
            for (int e = 0; e < 4; e++) acc[mi][ni][e] = 0.f;

    int a_row_l = lane & 15;
    int a_k8    = (lane >> 4) << 3;
    int b_row_l = lane & 7;
    int b_k8    = ((lane >> 3) & 1) << 3;

    int nchunks = K >> 6;
    issue_chunk(Ahi, Alo, lda, Bhi, Blo, ldb, 0, sb, t);
    asm volatile("cp.async.commit_group;" ::: "memory");

    for (int ch = 0; ch < nchunks; ch++) {
        if (ch + 1 < nchunks) {
            issue_chunk(Ahi, Alo, lda, Bhi, Blo, ldb, (ch + 1) * 64,
                        sb + ((ch + 1) & 1) * 65536, t);
            asm volatile("cp.async.commit_group;" ::: "memory");
            asm volatile("cp.async.wait_group 1;" ::: "memory");
        } else {
            asm volatile("cp.async.wait_group 0;" ::: "memory");
        }
        __syncthreads();
        uint32_t base = sb + (ch & 1) * 65536;
        uint32_t aHiA = base, aLoA = base + 16384, bHiA = base + 32768, bLoA = base + 49152;
#pragma unroll
        for (int ks = 0; ks < 4; ks++) {
            uint32_t Bh[4][2], Bl[4][2];
#pragma unroll
            for (int ni = 0; ni < 4; ni++) {
                uint32_t byte = (uint32_t)((wn * 32 + ni * 8 + b_row_l) * 128 +
                                           (ks * 16 + b_k8) * 2);
                uint32_t sw = SW128(byte);
                ldm_x2(Bh[ni], bHiA + sw);
                ldm_x2(Bl[ni], bLoA + sw);
            }
#pragma unroll
            for (int mi = 0; mi < 4; mi++) {
                uint32_t Ah[4], Al[4];
                uint32_t byte = (uint32_t)((wm * 64 + mi * 16 + a_row_l) * 128 +
                                           (ks * 16 + a_k8) * 2);
                uint32_t sw = SW128(byte);
                ldm_x4(Ah, aHiA + sw);
                ldm_x4(Al, aLoA + sw);
#pragma unroll
                for (int ni = 0; ni < 4; ni++) {
                    mma_bf16(acc[mi][ni], Ah, Bh[ni]);
                    mma_bf16(acc[mi][ni], Ah, Bl[ni]);
                    mma_bf16(acc[mi][ni], Al, Bh[ni]);
                }
            }
        }
        __syncthreads();
    }

    int rbase = m0 + wm * 64 + (lane >> 2);
    int cbase = n0 + wn * 32 + (lane & 3) * 2;
#pragma unroll
    for (int mi = 0; mi < 4; mi++) {
#pragma unroll
        for (int h = 0; h < 2; h++) {
            int m = rbase + mi * 16 + h * 8;
            long long rowoff = co + (long long)m * ldc;
#pragma unroll
            for (int ni = 0; ni < 4; ni++) {
                int c = cbase + ni * 8;
                float v0 = acc[mi][ni][2 * h]     * alpha;
                float v1 = acc[mi][ni][2 * h + 1] * alpha;
                if (bias) { v0 += bias[c]; v1 += bias[c + 1]; }
                if (EPI == 1 || EPI == 3) { v0 = gelu_f(v0); v1 = gelu_f(v1); }
                if (EPI == 2) {
                    v0 = 1.f / (1.f + expf(-v0));
                    v1 = 1.f / (1.f + expf(-v1));
                }
                if (EPI == 3) {
                    float2 ev = *reinterpret_cast<const float2*>(&extra[rowoff + c]);
                    v0 -= ev.x; v1 -= ev.y;
                }
                if (OMODE & 1) {
                    float2 o; o.x = v0; o.y = v1;
                    *reinterpret_cast<float2*>(&Cf[rowoff + c]) = o;
                }
                if (OMODE & 2) {
                    bf16 h0 = __float2bfloat16(v0), h1 = __float2bfloat16(v1);
                    __nv_bfloat162 hp, lp;
                    hp.x = h0; hp.y = h1;
                    lp.x = __float2bfloat16(v0 - __bfloat162float(h0));
                    lp.y = __float2bfloat16(v1 - __bfloat162float(h1));
                    *reinterpret_cast<__nv_bfloat162*>(&Chi[rowoff + c]) = hp;
                    *reinterpret_cast<__nv_bfloat162*>(&Clo[rowoff + c]) = lp;
                }
            }
        }
    }
}

// ---------------- direct conv 4x4 s2 p1 + relu (f32x2) ----------------
__global__ __launch_bounds__(128) void conv_l1_k(const float* __restrict__ x,
                                                 const float* __restrict__ w,
                                                 const float* __restrict__ bias,
                                                 float* __restrict__ dw) {
    __shared__ float sw[2][2 * 512];
    __shared__ float sx[2][2 * 646];
    int tile = blockIdx.x;
    int oc0 = blockIdx.y * 32;
    int b = blockIdx.z;
    int i0 = (tile / 8) * 16;
    int j0 = (tile % 8) * 8;
    int t = threadIdx.x;
    int pg = t % 32, os = t / 32;
    int iL2 = 2 * (pg / 8), jL2 = 2 * (pg % 8);
    int oc_l = t >> 4, rs = t & 15;
    const float* xb = x + (long long)b * CH * HH * WW;

    int  xg[10], xs[10];
    bool xv[10];
#pragma unroll
    for (int q = 0; q < 10; q++) {
        int idx = t + 128 * q;
        int ic_l = idx / 612;
        int r2 = idx % 612;
        int row = r2 / 18, col = r2 % 18;
        int gy = 2 * i0 - 1 + row, gx = 2 * j0 - 1 + col;
        bool inb = (idx < 1224);
        xv[q] = inb && gy >= 0 && gy < HH && gx >= 0 && gx < WW;
        xg[q] = ic_l * HH * WW + gy * WW + gx;
        xs[q] = inb ? (ic_l * 646 + row * 19 + col) : -1;
    }

    ull acc[4][4];
#pragma unroll
    for (int p = 0; p < 4; p++)
#pragma unroll
        for (int m = 0; m < 4; m++) acc[p][m] = 0ULL;

    float xr[10], wr[8];
#pragma unroll
    for (int q = 0; q < 10; q++) xr[q] = xv[q] ? xb[xg[q]] : 0.f;
#pragma unroll
    for (int il = 0; il < 2; il++)
#pragma unroll
        for (int q = 0; q < 4; q++)
            wr[il * 4 + q] = w[(long long)(oc0 + oc_l + 8 * q) * 2048 + il * 16 + rs];
#pragma unroll
    for (int q = 0; q < 10; q++) if (xs[q] >= 0) sx[0][xs[q]] = xr[q];
#pragma unroll
    for (int il = 0; il < 2; il++)
#pragma unroll
        for (int q = 0; q < 4; q++)
            sw[0][il * 512 + rs * 32 + oc_l + 8 * q] = wr[il * 4 + q];
    __syncthreads();

    for (int icb = 0; icb < 64; icb++) {
        int buf = icb & 1;
        bool nxt = (icb < 63);
        if (nxt) {
            int ic = 2 * (icb + 1);
            const float* xpc = xb + (long long)ic * HH * WW;
#pragma unroll
            for (int q = 0; q < 10; q++) xr[q] = xv[q] ? xpc[xg[q]] : 0.f;
#pragma unroll
            for (int il = 0; il < 2; il++)
#pragma unroll
                for (int q = 0; q < 4; q++)
                    wr[il * 4 + q] = w[(long long)(oc0 + oc_l + 8 * q) * 2048 + (ic + il) * 16 + rs];
        }
#pragma unroll
        for (int il = 0; il < 2; il++) {
            const float* sxp = &sx[buf][il * 646];
            const float* swp = &sw[buf][il * 512];
#pragma unroll
            for (int r = 0; r < 4; r++) {
#pragma unroll
                for (int s = 0; s < 4; s++) {
                    int xo = (iL2 + r) * 19 + jL2 + s;
                    ull xm0 = pack2(sxp[xo],       sxp[xo]);
                    ull xm1 = pack2(sxp[xo + 152], sxp[xo + 152]);
                    ull xm2 = pack2(sxp[xo + 304], sxp[xo + 304]);
                    ull xm3 = pack2(sxp[xo + 456], sxp[xo + 456]);
                    int wbase = (r * 4 + s) * 32 + os * 8;
#pragma unroll
                    for (int p = 0; p < 4; p++) {
                        ull wp = *reinterpret_cast<const ull*>(&swp[wbase + 2 * p]);
                        acc[p][0] = ffma2(wp, xm0, acc[p][0]);
                        acc[p][1] = ffma2(wp, xm1, acc[p][1]);
                        acc[p][2] = ffma2(wp, xm2, acc[p][2]);
                        acc[p][3] = ffma2(wp, xm3, acc[p][3]);
                    }
                }
            }
        }
        if (nxt) {
#pragma unroll
            for (int q = 0; q < 10; q++) if (xs[q] >= 0) sx[buf ^ 1][xs[q]] = xr[q];
#pragma unroll
            for (int il = 0; il < 2; il++)
#pragma unroll
                for (int q = 0; q < 4; q++)
                    sw[buf ^ 1][il * 512 + rs * 32 + oc_l + 8 * q] = wr[il * 4 + q];
        }
        __syncthreads();
    }

#pragma unroll
    for (int p = 0; p < 4; p++) {
        int oca = oc0 + os * 8 + 2 * p;
        float b0 = bias[oca], b1 = bias[oca + 1];
#pragma unroll
        for (int m = 0; m < 4; m++) {
            float2 pr = unpack2(acc[p][m]);
            int i = i0 + pg / 8 + 4 * m;
            int j = j0 + pg % 8;
            long long o0 = (((long long)b * CH + oca) * HO + i) * WO + j;
            dw[o0]                      = fmaxf(pr.x + b0, 0.f);
            dw[o0 + (long long)HO * WO] = fmaxf(pr.y + b1, 0.f);
        }
    }
}

// ---------------- column softmax over q axis (split in/out) ----------------
__global__ void softmax_q_k(bf16* __restrict__ Sh, bf16* __restrict__ Sl) {
    __shared__ float sm[8][32], ss[8][32];
    int g = blockIdx.y;
    int k0 = blockIdx.x * 32;
    int tid = threadIdx.x;
    int kc = tid % 32;
    int qh = tid / 32;
    size_t base = (size_t)g * QL * QL + k0 + kc;
    float m = -INFINITY, s = 0.f;
    for (int q = qh; q < QL; q += 8) {
        size_t off = base + (size_t)q * QL;
        float v = __bfloat162float(Sh[off]) + __bfloat162float(Sl[off]);
        if (v > m) { s = s * expf(m - v) + 1.f; m = v; }
        else s += expf(v - m);
    }
    sm[qh][kc] = m;
    ss[qh][kc] = s;
    __syncthreads();
    if (tid < 32) {
        float M = sm[0][kc], Sm = ss[0][kc];
#pragma unroll
        for (int r = 1; r < 8; r++) {
            float m2 = sm[r][kc], s2 = ss[r][kc];
            float nm = fmaxf(M, m2);
            Sm = Sm * expf(M - nm) + s2 * expf(m2 - nm);
            M = nm;
        }
        sm[0][kc] = M;
        ss[0][kc] = 1.f / Sm;
    }
    __syncthreads();
    float M = sm[0][kc], inv = ss[0][kc];
    for (int q = qh; q < QL; q += 8) {
        size_t off = base + (size_t)q * QL;
        float v = __bfloat162float(Sh[off]) + __bfloat162float(Sl[off]);
        float p = expf(v - M) * inv;
        bf16 h = __float2bfloat16(p);
        Sh[off] = h;
        Sl[off] = __float2bfloat16(p - __bfloat162float(h));
    }
}

// ---------------- per-token layernorm (split in/out) ----------------
__global__ void ln_k(const bf16* __restrict__ Xh, const bf16* __restrict__ Xl,
                     bf16* __restrict__ Yh, bf16* __restrict__ Yl,
                     const float* __restrict__ gw, const float* __restrict__ bw) {
    int warp = threadIdx.x / 32, lane = threadIdx.x % 32;
    size_t t = (size_t)blockIdx.x * 8 + warp;
    float v[4];
    float sum = 0.f;
#pragma unroll
    for (int i = 0; i < 4; i++) {
        size_t off = t * 128 + lane + 32 * i;
        v[i] = __bfloat162float(Xh[off]) + __bfloat162float(Xl[off]);
        sum += v[i];
    }
#pragma unroll
    for (int o = 16; o; o >>= 1) sum += __shfl_xor_sync(0xffffffffu, sum, o);
    float mean = sum * (1.f / 128.f);
    float vs = 0.f;
#pragma unroll
    for (int i = 0; i < 4; i++) { float d = v[i] - mean; vs += d * d; }
#pragma unroll
    for (int o = 16; o; o >>= 1) vs += __shfl_xor_sync(0xffffffffu, vs, o);
    float inv = rsqrtf(vs * (1.f / 128.f) + 1e-5f);
#pragma unroll
    for (int i = 0; i < 4; i++) {
        int c = lane + 32 * i;
        float r = (v[i] - mean) * inv * gw[c] + bw[c];
        st_split(Yh, Yl, t * 128 + c, r);
    }
}

// ---------------- out = gate * LN(x2 + x3) ----------------
__global__ void addlngate_k(const float* __restrict__ X2, const float* __restrict__ X3,
                            const float* __restrict__ G,
                            const float* __restrict__ gw, const float* __restrict__ bw,
                            float* __restrict__ Y) {
    int warp = threadIdx.x / 32, lane = threadIdx.x % 32;
    size_t t = (size_t)blockIdx.x * 8 + warp;
    float v[4];
    float sum = 0.f;
#pragma unroll
    for (int i = 0; i < 4; i++) {
        size_t c = t * 128 + lane + 32 * i;
        v[i] = X2[c] + X3[c];
        sum += v[i];
    }
#pragma unroll
    for (int o = 16; o; o >>= 1) sum += __shfl_xor_sync(0xffffffffu, sum, o);
    float mean = sum * (1.f / 128.f);
    float vs = 0.f;
#pragma unroll
    for (int i = 0; i < 4; i++) { float d = v[i] - mean; vs += d * d; }
#pragma unroll
    for (int o = 16; o; o >>= 1) vs += __shfl_xor_sync(0xffffffffu, vs, o);
    float inv = rsqrtf(vs * (1.f / 128.f) + 1e-5f);
#pragma unroll
    for (int i = 0; i < 4; i++) {
        int c = lane + 32 * i;
        float nrm = (v[i] - mean) * inv * gw[c] + bw[c];
        Y[t * 128 + c] = G[t * 128 + c] * nrm;
    }
}

// ---------------- final combine ----------------
__global__ void final_k(const float* __restrict__ x, const float* __restrict__ ffn,
                        const float* __restrict__ ytok, const float* __restrict__ dw,
                        float* __restrict__ out) {
    __shared__ float sf[32][65], sy[32][65];
    int i = blockIdx.x, b = blockIdx.y, tid = threadIdx.x;
    float pos_i = (float)(i * 127) / 63.f;
    int y0 = (int)floorf(pos_i);
    int y1 = min(y0 + 1, 127);
    float wy = pos_i - (float)y0;
    for (int cc = 0; cc < 4; cc++) {
        for (int idx = tid; idx < 64 * 32; idx += 256) {
            int j = idx / 32, cl = idx % 32;
            size_t t = (size_t)b * TOK + i * 64 + j;
            sf[cl][j] = ffn[t * 128 + cc * 32 + cl];
            sy[cl][j] = ytok[t * 128 + cc * 32 + cl];
        }
        __syncthreads();
        for (int idx = tid; idx < 32 * 64; idx += 256) {
            int cl = idx / 64, j = idx % 64;
            int c = cc * 32 + cl;
            float pos_j = (float)(j * 127) / 63.f;
            int x0 = (int)floorf(pos_j);
            int x1i = min(x0 + 1, 127);
            float wx = pos_j - (float)x0;
            const float* xb = x + (long long)(b * CH + c) * HH * WW;
            float r0 = xb[y0 * WW + x0] * (1.f - wy) + xb[y1 * WW + x0] * wy;
            float r1 = xb[y0 * WW + x1i] * (1.f - wy) + xb[y1 * WW + x1i] * wy;
            float dv = r0 * (1.f - wx) + r1 * wx;
            long long oi = (((long long)b * CH + c) * HO + i) * WO + j;
            float dwv = dw[oi];
            out[oi] = sf[cl][j] * (dv - dwv) + sy[cl][j];
        }
        __syncthreads();
    }
}

// ---------------- launch ----------------
extern "C" void kernel_launch(void* const* d_in, const int* in_sizes, int n_in,
                              void* d_out, int out_size) {
    (void)in_sizes; (void)n_in; (void)out_size;
    const float* x       = (const float*)d_in[0];
    const float* conv1_w = (const float*)d_in[1];
    const float* conv1_b = (const float*)d_in[2];
    const float* l1_w    = (const float*)d_in[3];
    const float* l1_b    = (const float*)d_in[4];
    const float* ln1_g   = (const float*)d_in[5];
    const float* ln1_b   = (const float*)d_in[6];
    const float* fc1_b   = (const float*)d_in[8];
    const float* div_b   = (const float*)d_in[10];
    const float* fc2_b   = (const float*)d_in[12];
    const float* ln3_g   = (const float*)d_in[13];
    const float* ln3_b   = (const float*)d_in[14];
    const float* fc3a_b  = (const float*)d_in[16];
    const float* fc3b_b  = (const float*)d_in[18];
    const float* lnn_g   = (const float*)d_in[19];
    const float* lnn_b   = (const float*)d_in[20];
    const float* act_b   = (const float*)d_in[22];
    float* out = (float*)d_out;

    float *y, *x1, *t1, *x3, *gate, *ffn, *dw;
    cudaGetSymbolAddress((void**)&y,    g_y);
    cudaGetSymbolAddress((void**)&x1,   g_x1);
    cudaGetSymbolAddress((void**)&t1,   g_t1);
    cudaGetSymbolAddress((void**)&x3,   g_x3);
    cudaGetSymbolAddress((void**)&gate, g_gate);
    cudaGetSymbolAddress((void**)&ffn,  g_ffn);
    cudaGetSymbolAddress((void**)&dw,   g_dw);

    bf16 *yLh, *yLl, *hlhh, *hlhl, *yh, *yl, *Sh, *Sl, *yTh, *yTl;
    bf16 *attnh, *attnl, *t0h, *t0l, *x2h, *x2l, *Wh, *Wl;
    cudaGetSymbolAddress((void**)&yLh,   syL_h);
    cudaGetSymbolAddress((void**)&yLl,   syL_l);
    cudaGetSymbolAddress((void**)&hlhh,  shlh_h);
    cudaGetSymbolAddress((void**)&hlhl,  shlh_l);
    cudaGetSymbolAddress((void**)&yh,    sy_h);
    cudaGetSymbolAddress((void**)&yl,    sy_l);
    cudaGetSymbolAddress((void**)&Sh,    sS_h);
    cudaGetSymbolAddress((void**)&Sl,    sS_l);
    cudaGetSymbolAddress((void**)&yTh,   syT_h);
    cudaGetSymbolAddress((void**)&yTl,   syT_l);
    cudaGetSymbolAddress((void**)&attnh, sattn_h);
    cudaGetSymbolAddress((void**)&attnl, sattn_l);
    cudaGetSymbolAddress((void**)&t0h,   st0_h);
    cudaGetSymbolAddress((void**)&t0l,   st0_l);
    cudaGetSymbolAddress((void**)&x2h,   sx2_h);
    cudaGetSymbolAddress((void**)&x2l,   sx2_l);
    cudaGetSymbolAddress((void**)&Wh,    sW_h);
    cudaGetSymbolAddress((void**)&Wl,    sW_l);

    cudaFuncSetAttribute(bgemm_k<0,3>, cudaFuncAttributeMaxDynamicSharedMemorySize, BGE_SMEM);
    cudaFuncSetAttribute(bgemm_k<0,2>, cudaFuncAttributeMaxDynamicSharedMemorySize, BGE_SMEM);
    cudaFuncSetAttribute(bgemm_k<1,1>, cudaFuncAttributeMaxDynamicSharedMemorySize, BGE_SMEM);
    cudaFuncSetAttribute(bgemm_k<1,2>, cudaFuncAttributeMaxDynamicSharedMemorySize, BGE_SMEM);
    cudaFuncSetAttribute(bgemm_k<3,2>, cudaFuncAttributeMaxDynamicSharedMemorySize, BGE_SMEM);
    cudaFuncSetAttribute(bgemm_k<0,1>, cudaFuncAttributeMaxDynamicSharedMemorySize, BGE_SMEM);
    cudaFuncSetAttribute(bgemm_k<2,1>, cudaFuncAttributeMaxDynamicSharedMemorySize, BGE_SMEM);

    const float* w0 = (const float*)d_in[1];
    const float* w1 = (const float*)d_in[7];
    const float* w2 = (const float*)d_in[9];
    const float* w3 = (const float*)d_in[11];
    const float* w4 = (const float*)d_in[15];
    const float* w5 = (const float*)d_in[17];
    const float* w6 = (const float*)d_in[21];
    (void)conv1_w;
    wsplit_k<<<512, 256>>>(w0, w1, w2, w3, w4, w5, w6, Wh, Wl);

    haar_k<<<dim3(64, 16), 256>>>(x, yLh, yLl, yTh, yTl, hlhh, hlhl);

    // 1x1 conv: y = hlh @ conv1_w^T + b (K=256) -> fp32 y + split y
    bgemm_k<0,3><<<dim3(1, 512, 1), 256, BGE_SMEM>>>(
        hlhh, hlhl, 0, 256, Wh, Wl, 0, 256,
        y, yh, yl, 0, 128, 256, 1.f, conv1_b, nullptr);

    conv_l1_k<<<dim3(32, 4, 16), 128>>>(x, l1_w, l1_b, dw);

    // S = scale * Q @ K^T -> split S
    bgemm_k<0,2><<<dim3(4, 4, NG), 256, BGE_SMEM>>>(
        yLh, yLl, (long long)QL * 128, 128, yh, yl, (long long)QL * 128, 128,
        nullptr, Sh, Sl, (long long)QL * QL, QL, 128, 0.35355339059327373f, nullptr, nullptr);

    softmax_q_k<<<dim3(16, NG), 256>>>(Sh, Sl);

    // attn = P @ V (K=512) -> split attn
    bgemm_k<0,2><<<dim3(1, 4, NG), 256, BGE_SMEM>>>(
        Sh, Sl, (long long)QL * QL, QL, yTh, yTl, (long long)128 * 512, 512,
        nullptr, attnh, attnl, (long long)QL * 128, 128, 512, 1.f, nullptr, nullptr);

    ln_k<<<8192, 256>>>(attnh, attnl, t0h, t0l, ln1_g, ln1_b);
    bgemm_k<1,1><<<dim3(1, 512), 256, BGE_SMEM>>>(
        t0h, t0l, 0, 128, Wh + 32768, Wl + 32768, 0, 128,
        x1, nullptr, nullptr, 0, 128, 128, 1.f, fc1_b, nullptr);
    bgemm_k<3,2><<<dim3(1, 512), 256, BGE_SMEM>>>(
        attnh, attnl, 0, 128, Wh + 49152, Wl + 49152, 0, 128,
        nullptr, x2h, x2l, 0, 128, 128, 1.f, div_b, x1);
    bgemm_k<1,1><<<dim3(1, 512), 256, BGE_SMEM>>>(
        x2h, x2l, 0, 128, Wh + 65536, Wl + 65536, 0, 128,
        t1, nullptr, nullptr, 0, 128, 128, 1.f, fc2_b, nullptr);
    ln_k<<<8192, 256>>>(attnh, attnl, t0h, t0l, ln3_g, ln3_b);
    bgemm_k<1,2><<<dim3(1, 512), 256, BGE_SMEM>>>(
        t0h, t0l, 0, 128, Wh + 81920, Wl + 81920, 0, 128,
        nullptr, x2h, x2l, 0, 128, 128, 1.f, fc3a_b, nullptr);
    bgemm_k<0,1><<<dim3(1, 512), 256, BGE_SMEM>>>(
        x2h, x2l, 0, 128, Wh + 98304, Wl + 98304, 0, 128,
        x3, nullptr, nullptr, 0, 128, 128, 1.f, fc3b_b, nullptr);
    bgemm_k<2,1><<<dim3(1, 512), 256, BGE_SMEM>>>(
        attnh, attnl, 0, 128, Wh + 114688, Wl + 114688, 0, 128,
        gate, nullptr, nullptr, 0, 128, 128, 1.f, act_b, nullptr);
    addlngate_k<<<8192, 256>>>(t1, x3, gate, lnn_g, lnn_b, ffn);

    final_k<<<dim3(64, 16), 256>>>(x, ffn, y, dw, out);
}

// round 9
// speedup vs baseline: 2.3641x; 1.6302x over previous
#include <cuda_runtime.h>
#include <cuda_bf16.h>
#include <math.h>
#include <stdint.h>

// ---------------- problem constants ----------------
#define BB   16
#define CH   128
#define HH   128
#define WW   128
#define HO   64
#define WO   64
#define TOK  4096
#define NT   65536
#define NG   128
#define QL   512

typedef unsigned long long ull;
typedef __nv_bfloat16 bf16;

// ---------------- fp32 scratch ----------------
__device__ __align__(256) float g_y  [(size_t)NT * 128];
__device__ __align__(256) float g_x1 [(size_t)NT * 128];
__device__ __align__(256) float g_t1 [(size_t)NT * 128];
__device__ __align__(256) float g_x3 [(size_t)NT * 128];
__device__ __align__(256) float g_gate[(size_t)NT * 128];
__device__ __align__(256) float g_ffn[(size_t)NT * 128];
__device__ __align__(256) float g_dwt[(size_t)NT * 128];       // conv out, token-major

// ---------------- split bf16 scratch ----------------
__device__ __align__(256) bf16 syL_h [(size_t)NT * 128];
__device__ __align__(256) bf16 syL_l [(size_t)NT * 128];
__device__ __align__(256) bf16 shlh_h[(size_t)NT * 256];
__device__ __align__(256) bf16 shlh_l[(size_t)NT * 256];
__device__ __align__(256) bf16 sy_h  [(size_t)NT * 128];
__device__ __align__(256) bf16 sy_l  [(size_t)NT * 128];
__device__ __align__(256) bf16 sS_h  [(size_t)NG * QL * QL];
__device__ __align__(256) bf16 sS_l  [(size_t)NG * QL * QL];
__device__ __align__(256) bf16 syT_h [(size_t)NG * 128 * 512];
__device__ __align__(256) bf16 syT_l [(size_t)NG * 128 * 512];
__device__ __align__(256) bf16 sattn_h[(size_t)NT * 128];
__device__ __align__(256) bf16 sattn_l[(size_t)NT * 128];
__device__ __align__(256) bf16 st0_h [(size_t)NT * 128];
__device__ __align__(256) bf16 st0_l [(size_t)NT * 128];
__device__ __align__(256) bf16 sx2_h [(size_t)NT * 128];
__device__ __align__(256) bf16 sx2_l [(size_t)NT * 128];
__device__ __align__(256) bf16 sW_h  [131072];
__device__ __align__(256) bf16 sW_l  [131072];
__device__ __align__(256) bf16 sWc_h [262144];                  // conv w [oc][(r*4+s)*128+ic]
__device__ __align__(256) bf16 sWc_l [262144];
__device__ __align__(256) bf16 sxt_h [(size_t)BB * HH * WW * CH]; // x NHWC split
__device__ __align__(256) bf16 sxt_l [(size_t)BB * HH * WW * CH];

__device__ __forceinline__ float gelu_f(float v) {
    return 0.5f * v * (1.0f + erff(v * 0.70710678118654752f));
}
__device__ __forceinline__ uint32_t smem_u32(const void* p) {
    uint32_t a;
    asm("{ .reg .u64 t; cvta.to.shared.u64 t, %1; cvt.u32.u64 %0, t; }" : "=r"(a) : "l"(p));
    return a;
}
#define SW128(o) ((o) ^ (((o) >> 3) & 0x70))

__device__ __forceinline__ void st_split(bf16* H, bf16* L, size_t off, float v) {
    bf16 h = __float2bfloat16(v);
    H[off] = h;
    L[off] = __float2bfloat16(v - __bfloat162float(h));
}

// ---- mma.sync bf16 + ldmatrix + cp.async ----
__device__ __forceinline__ void ldm_x4(uint32_t* r, uint32_t addr) {
    asm volatile("ldmatrix.sync.aligned.m8n8.x4.shared.b16 {%0,%1,%2,%3}, [%4];"
                 : "=r"(r[0]), "=r"(r[1]), "=r"(r[2]), "=r"(r[3]) : "r"(addr));
}
__device__ __forceinline__ void ldm_x2(uint32_t* r, uint32_t addr) {
    asm volatile("ldmatrix.sync.aligned.m8n8.x2.shared.b16 {%0,%1}, [%2];"
                 : "=r"(r[0]), "=r"(r[1]) : "r"(addr));
}
__device__ __forceinline__ void mma_bf16(float* d, const uint32_t* a, const uint32_t* b) {
    asm volatile("mma.sync.aligned.m16n8k16.row.col.f32.bf16.bf16.f32 "
                 "{%0,%1,%2,%3}, {%4,%5,%6,%7}, {%8,%9}, {%0,%1,%2,%3};"
                 : "+f"(d[0]), "+f"(d[1]), "+f"(d[2]), "+f"(d[3])
                 : "r"(a[0]), "r"(a[1]), "r"(a[2]), "r"(a[3]), "r"(b[0]), "r"(b[1]));
}
__device__ __forceinline__ void cp16(uint32_t dst, const void* src) {
    asm volatile("cp.async.cg.shared.global [%0], [%1], 16;" :: "r"(dst), "l"(src));
}
__device__ __forceinline__ void cp16z(uint32_t dst, const void* src, int sz) {
    asm volatile("cp.async.cg.shared.global [%0], [%1], 16, %2;" :: "r"(dst), "l"(src), "r"(sz));
}

// ---------------- weight splits ----------------
__global__ void wsplit_k(const float* __restrict__ conv1_w, const float* __restrict__ fc1_w,
                         const float* __restrict__ div_w, const float* __restrict__ fc2_w,
                         const float* __restrict__ fc3a_w, const float* __restrict__ fc3b_w,
                         const float* __restrict__ act_w,
                         bf16* __restrict__ WH, bf16* __restrict__ WL) {
    int i = blockIdx.x * 256 + threadIdx.x;
    float v;
    if      (i <  32768) v = conv1_w[i];
    else if (i <  49152) v = fc1_w [i - 32768];
    else if (i <  65536) v = div_w [i - 49152];
    else if (i <  81920) v = fc2_w [i - 65536];
    else if (i <  98304) v = fc3a_w[i - 81920];
    else if (i < 114688) v = fc3b_w[i - 98304];
    else                 v = act_w [i - 114688];
    bf16 h = __float2bfloat16(v);
    WH[i] = h;
    WL[i] = __float2bfloat16(v - __bfloat162float(h));
}

__global__ void wconv_k(const float* __restrict__ l1_w,
                        bf16* __restrict__ WH, bf16* __restrict__ WL) {
    int i = blockIdx.x * 256 + threadIdx.x;   // 262144
    int oc = i >> 11;
    int k = i & 2047;
    int tap = k >> 7, ic = k & 127;
    float v = l1_w[oc * 2048 + ic * 16 + tap];
    bf16 h = __float2bfloat16(v);
    WH[i] = h;
    WL[i] = __float2bfloat16(v - __bfloat162float(h));
}

// ---------------- x NCHW -> NHWC split ----------------
__global__ void nhwc_k(const float* __restrict__ x,
                       bf16* __restrict__ xh, bf16* __restrict__ xl) {
    __shared__ float tile[32][129];
    int h = blockIdx.x, b = blockIdx.y, tid = threadIdx.x;
    for (int cc = 0; cc < 4; cc++) {
        for (int idx = tid; idx < 32 * 128; idx += 256) {
            int cl = idx >> 7, w = idx & 127;
            tile[cl][w] = x[(((size_t)b * CH + cc * 32 + cl) * HH + h) * WW + w];
        }
        __syncthreads();
        for (int idx = tid; idx < 128 * 32; idx += 256) {
            int w = idx >> 5, cl = idx & 31;
            size_t o = (((size_t)b * HH + h) * WW + w) * CH + cc * 32 + cl;
            st_split(xh, xl, o, tile[cl][w]);
        }
        __syncthreads();
    }
}

// ---------------- Haar DWT -> split token layouts ----------------
__global__ void haar_k(const float* __restrict__ x,
                       bf16* __restrict__ yLh, bf16* __restrict__ yLl,
                       bf16* __restrict__ yTh, bf16* __restrict__ yTl,
                       bf16* __restrict__ hlhh, bf16* __restrict__ hlhl) {
    __shared__ float sLL[32][65], sHL[32][65], sLH[32][65], sHH[32][65];
    int i = blockIdx.x, b = blockIdx.y, tid = threadIdx.x;
    for (int cc = 0; cc < 4; cc++) {
        for (int idx = tid; idx < 32 * 64; idx += 256) {
            int cl = idx / 64, j = idx % 64;
            int c = cc * 32 + cl;
            const float* base = x + (((long long)(b * CH + c) * HH + 2 * i) * WW) + 2 * j;
            float a = base[0], bb2 = base[1], cv = base[WW], d = base[WW + 1];
            sLL[cl][j] = (a + bb2 + cv + d) * 0.5f;
            sHL[cl][j] = (a - bb2 + cv - d) * 0.5f;
            sLH[cl][j] = (a + bb2 - cv - d) * 0.5f;
            sHH[cl][j] = (a - bb2 - cv + d) * 0.5f;
        }
        __syncthreads();
        for (int idx = tid; idx < 64 * 32; idx += 256) {
            int j = idx / 32, cl = idx % 32;
            size_t t = (size_t)b * TOK + i * 64 + j;
            int c = cc * 32 + cl;
            st_split(yLh, yLl, t * 128 + c, sLL[cl][j]);
            st_split(hlhh, hlhl, t * 256 + c, sHL[cl][j]);
            st_split(hlhh, hlhl, t * 256 + 128 + c, sLH[cl][j]);
        }
        {
            int g = b * 8 + (i >> 3);
            int qoff = (i & 7) * 64;
            for (int idx = tid; idx < 32 * 64; idx += 256) {
                int cl = idx / 64, j = idx % 64;
                int c = cc * 32 + cl;
                st_split(yTh, yTl, ((size_t)g * 128 + c) * 512 + qoff + j, sHH[cl][j]);
            }
        }
        __syncthreads();
    }
}

// ---------------- split-bf16 cp.async pipelined GEMM ----------------
#define BGE_SMEM 131072

__device__ __forceinline__ void issue_chunk(
    const bf16* __restrict__ Ahi, const bf16* __restrict__ Alo, int lda,
    const bf16* __restrict__ Bhi, const bf16* __restrict__ Blo, int ldb,
    int k0, uint32_t base, int t) {
#pragma unroll
    for (int q = 0; q < 4; q++) {
        int idx = q * 256 + t;
        int row = idx >> 3, gg = idx & 7;
        uint32_t sw = SW128((uint32_t)(row * 128 + gg * 16));
        cp16(base + sw,         Ahi + (long long)row * lda + k0 + gg * 8);
        cp16(base + 16384 + sw, Alo + (long long)row * lda + k0 + gg * 8);
        cp16(base + 32768 + sw, Bhi + (long long)row * ldb + k0 + gg * 8);
        cp16(base + 49152 + sw, Blo + (long long)row * ldb + k0 + gg * 8);
    }
}

template <int EPI, int OMODE>
__global__ __launch_bounds__(256)
void bgemm_k(const bf16* __restrict__ Ahi, const bf16* __restrict__ Alo, long long sAg, int lda,
             const bf16* __restrict__ Bhi, const bf16* __restrict__ Blo, long long sBg, int ldb,
             float* __restrict__ Cf, bf16* __restrict__ Chi, bf16* __restrict__ Clo,
             long long sCg, int ldc, int K, float alpha,
             const float* __restrict__ bias, const float* __restrict__ extra) {
    extern __shared__ char smem[];
    uint32_t sb = smem_u32(smem);
    int t = threadIdx.x;
    int wid = t >> 5, lane = t & 31;
    int n0 = blockIdx.x * 128;
    int m0 = blockIdx.y * 128;
    int g = blockIdx.z;
    Ahi += (long long)g * sAg + (long long)m0 * lda;
    Alo += (long long)g * sAg + (long long)m0 * lda;
    Bhi += (long long)g * sBg + (long long)n0 * ldb;
    Blo += (long long)g * sBg + (long long)n0 * ldb;
    long long co = (long long)g * sCg;

    int wm = wid >> 2;
    int wn = wid & 3;

    float acc[4][4][4];
#pragma unroll
    for (int mi = 0; mi < 4; mi++)
#pragma unroll
        for (int ni = 0; ni < 4; ni++)
#pragma unroll
            for (int e = 0; e < 4; e++) acc[mi][ni][e] = 0.f;

    int a_row_l = lane & 15;
    int a_k8    = (lane >> 4) << 3;
    int b_row_l = lane & 7;
    int b_k8    = ((lane >> 3) & 1) << 3;

    int nchunks = K >> 6;
    issue_chunk(Ahi, Alo, lda, Bhi, Blo, ldb, 0, sb, t);
    asm volatile("cp.async.commit_group;" ::: "memory");

    for (int ch = 0; ch < nchunks; ch++) {
        if (ch + 1 < nchunks) {
            issue_chunk(Ahi, Alo, lda, Bhi, Blo, ldb, (ch + 1) * 64,
                        sb + ((ch + 1) & 1) * 65536, t);
            asm volatile("cp.async.commit_group;" ::: "memory");
            asm volatile("cp.async.wait_group 1;" ::: "memory");
        } else {
            asm volatile("cp.async.wait_group 0;" ::: "memory");
        }
        __syncthreads();
        uint32_t base = sb + (ch & 1) * 65536;
        uint32_t aHiA = base, aLoA = base + 16384, bHiA = base + 32768, bLoA = base + 49152;
#pragma unroll
        for (int ks = 0; ks < 4; ks++) {
            uint32_t Bh[4][2], Bl[4][2];
#pragma unroll
            for (int ni = 0; ni < 4; ni++) {
                uint32_t byte = (uint32_t)((wn * 32 + ni * 8 + b_row_l) * 128 +
                                           (ks * 16 + b_k8) * 2);
                uint32_t sw = SW128(byte);
                ldm_x2(Bh[ni], bHiA + sw);
                ldm_x2(Bl[ni], bLoA + sw);
            }
#pragma unroll
            for (int mi = 0; mi < 4; mi++) {
                uint32_t Ah[4], Al[4];
                uint32_t byte = (uint32_t)((wm * 64 + mi * 16 + a_row_l) * 128 +
                                           (ks * 16 + a_k8) * 2);
                uint32_t sw = SW128(byte);
                ldm_x4(Ah, aHiA + sw);
                ldm_x4(Al, aLoA + sw);
#pragma unroll
                for (int ni = 0; ni < 4; ni++) {
                    mma_bf16(acc[mi][ni], Ah, Bh[ni]);
                    mma_bf16(acc[mi][ni], Ah, Bl[ni]);
                    mma_bf16(acc[mi][ni], Al, Bh[ni]);
                }
            }
        }
        __syncthreads();
    }

    int rbase = m0 + wm * 64 + (lane >> 2);
    int cbase = n0 + wn * 32 + (lane & 3) * 2;
#pragma unroll
    for (int mi = 0; mi < 4; mi++) {
#pragma unroll
        for (int h = 0; h < 2; h++) {
            int m = rbase + mi * 16 + h * 8;
            long long rowoff = co + (long long)m * ldc;
#pragma unroll
            for (int ni = 0; ni < 4; ni++) {
                int c = cbase + ni * 8;
                float v0 = acc[mi][ni][2 * h]     * alpha;
                float v1 = acc[mi][ni][2 * h + 1] * alpha;
                if (bias) { v0 += bias[c]; v1 += bias[c + 1]; }
                if (EPI == 1 || EPI == 3) { v0 = gelu_f(v0); v1 = gelu_f(v1); }
                if (EPI == 2) {
                    v0 = 1.f / (1.f + expf(-v0));
                    v1 = 1.f / (1.f + expf(-v1));
                }
                if (EPI == 3) {
                    float2 ev = *reinterpret_cast<const float2*>(&extra[rowoff + c]);
                    v0 -= ev.x; v1 -= ev.y;
                }
                if (OMODE & 1) {
                    float2 o; o.x = v0; o.y = v1;
                    *reinterpret_cast<float2*>(&Cf[rowoff + c]) = o;
                }
                if (OMODE & 2) {
                    bf16 h0 = __float2bfloat16(v0), h1 = __float2bfloat16(v1);
                    __nv_bfloat162 hp, lp;
                    hp.x = h0; hp.y = h1;
                    lp.x = __float2bfloat16(v0 - __bfloat162float(h0));
                    lp.y = __float2bfloat16(v1 - __bfloat162float(h1));
                    *reinterpret_cast<__nv_bfloat162*>(&Chi[rowoff + c]) = hp;
                    *reinterpret_cast<__nv_bfloat162*>(&Clo[rowoff + c]) = lp;
                }
            }
        }
    }
}

// ---------------- conv 4x4 s2 p1 as implicit GEMM (split-bf16 mma) ----------------
// A[m=(b,i,j)][k=(tap,ic)] gathered from NHWC x; B = conv weights [oc][2048]; out relu -> dwt token-major
__device__ __forceinline__ void issue_conv_chunk(
    const bf16* __restrict__ xh, const bf16* __restrict__ xl,
    const bf16* __restrict__ wh, const bf16* __restrict__ wl,
    int b, const int* iq, const int* jq, int ch, uint32_t base, int t) {
    int tap = ch >> 1;
    int icH = (ch & 1) * 64;
    int r = tap >> 2, s = tap & 3;
#pragma unroll
    for (int q = 0; q < 4; q++) {
        int idx = q * 256 + t;
        int row = idx >> 3, gg = idx & 7;
        uint32_t sw = SW128((uint32_t)(row * 128 + gg * 16));
        int yy = 2 * iq[q] - 1 + r;
        int xx = 2 * jq[q] - 1 + s;
        bool ok = ((unsigned)yy < 128u) && ((unsigned)xx < 128u);
        int yyc = ok ? yy : 0, xxc = ok ? xx : 0;
        size_t off = ((((size_t)b * HH + yyc) * WW + xxc) * CH) + icH + gg * 8;
        int sz = ok ? 16 : 0;
        cp16z(base + sw,         xh + off, sz);
        cp16z(base + 16384 + sw, xl + off, sz);
        size_t woff = (size_t)row * 2048 + ch * 64 + gg * 8;
        cp16(base + 32768 + sw, wh + woff);
        cp16(base + 49152 + sw, wl + woff);
    }
}

__global__ __launch_bounds__(256)
void cgemm_k(const bf16* __restrict__ xh, const bf16* __restrict__ xl,
             const bf16* __restrict__ wh, const bf16* __restrict__ wl,
             const float* __restrict__ bias, float* __restrict__ dwt) {
    extern __shared__ char smem[];
    uint32_t sb = smem_u32(smem);
    int t = threadIdx.x;
    int wid = t >> 5, lane = t & 31;
    int my = blockIdx.y;      // 0..31 m-tile within batch
    int b = blockIdx.z;
    int wm = wid >> 2;
    int wn = wid & 3;

    int iq[4], jq[4];
#pragma unroll
    for (int q = 0; q < 4; q++) {
        int idx = q * 256 + t;
        int m = my * 128 + (idx >> 3);
        iq[q] = m >> 6;
        jq[q] = m & 63;
    }

    float acc[4][4][4];
#pragma unroll
    for (int mi = 0; mi < 4; mi++)
#pragma unroll
        for (int ni = 0; ni < 4; ni++)
#pragma unroll
            for (int e = 0; e < 4; e++) acc[mi][ni][e] = 0.f;

    int a_row_l = lane & 15;
    int a_k8    = (lane >> 4) << 3;
    int b_row_l = lane & 7;
    int b_k8    = ((lane >> 3) & 1) << 3;

    issue_conv_chunk(xh, xl, wh, wl, b, iq, jq, 0, sb, t);
    asm volatile("cp.async.commit_group;" ::: "memory");

    for (int ch = 0; ch < 32; ch++) {
        if (ch + 1 < 32) {
            issue_conv_chunk(xh, xl, wh, wl, b, iq, jq, ch + 1,
                             sb + ((ch + 1) & 1) * 65536, t);
            asm volatile("cp.async.commit_group;" ::: "memory");
            asm volatile("cp.async.wait_group 1;" ::: "memory");
        } else {
            asm volatile("cp.async.wait_group 0;" ::: "memory");
        }
        __syncthreads();
        uint32_t base = sb + (ch & 1) * 65536;
        uint32_t aHiA = base, aLoA = base + 16384, bHiA = base + 32768, bLoA = base + 49152;
#pragma unroll
        for (int ks = 0; ks < 4; ks++) {
            uint32_t Bh[4][2], Bl[4][2];
#pragma unroll
            for (int ni = 0; ni < 4; ni++) {
                uint32_t byte = (uint32_t)((wn * 32 + ni * 8 + b_row_l) * 128 +
                                           (ks * 16 + b_k8) * 2);
                uint32_t sw = SW128(byte);
                ldm_x2(Bh[ni], bHiA + sw);
                ldm_x2(Bl[ni], bLoA + sw);
            }
#pragma unroll
            for (int mi = 0; mi < 4; mi++) {
                uint32_t Ah[4], Al[4];
                uint32_t byte = (uint32_t)((wm * 64 + mi * 16 + a_row_l) * 128 +
                                           (ks * 16 + a_k8) * 2);
                uint32_t sw = SW128(byte);
                ldm_x4(Ah, aHiA + sw);
                ldm_x4(Al, aLoA + sw);
#pragma unroll
                for (int ni = 0; ni < 4; ni++) {
                    mma_bf16(acc[mi][ni], Ah, Bh[ni]);
                    mma_bf16(acc[mi][ni], Ah, Bl[ni]);
                    mma_bf16(acc[mi][ni], Al, Bh[ni]);
                }
            }
        }
        __syncthreads();
    }

    int rbase = my * 128 + wm * 64 + (lane >> 2);
    int cbase = wn * 32 + (lane & 3) * 2;
#pragma unroll
    for (int mi = 0; mi < 4; mi++) {
#pragma unroll
        for (int h = 0; h < 2; h++) {
            int m = rbase + mi * 16 + h * 8;
            size_t rowoff = ((size_t)b * TOK + m) * 128;
#pragma unroll
            for (int ni = 0; ni < 4; ni++) {
                int c = cbase + ni * 8;
                float v0 = acc[mi][ni][2 * h]     + bias[c];
                float v1 = acc[mi][ni][2 * h + 1] + bias[c + 1];
                float2 o;
                o.x = fmaxf(v0, 0.f);
                o.y = fmaxf(v1, 0.f);
                *reinterpret_cast<float2*>(&dwt[rowoff + c]) = o;
            }
        }
    }
}

// ---------------- column softmax over q axis (split in/out) ----------------
__global__ void softmax_q_k(bf16* __restrict__ Sh, bf16* __restrict__ Sl) {
    __shared__ float sm[8][32], ss[8][32];
    int g = blockIdx.y;
    int k0 = blockIdx.x * 32;
    int tid = threadIdx.x;
    int kc = tid % 32;
    int qh = tid / 32;
    size_t base = (size_t)g * QL * QL + k0 + kc;
    float m = -INFINITY, s = 0.f;
    for (int q = qh; q < QL; q += 8) {
        size_t off = base + (size_t)q * QL;
        float v = __bfloat162float(Sh[off]) + __bfloat162float(Sl[off]);
        if (v > m) { s = s * expf(m - v) + 1.f; m = v; }
        else s += expf(v - m);
    }
    sm[qh][kc] = m;
    ss[qh][kc] = s;
    __syncthreads();
    if (tid < 32) {
        float M = sm[0][kc], Sm = ss[0][kc];
#pragma unroll
        for (int r = 1; r < 8; r++) {
            float m2 = sm[r][kc], s2 = ss[r][kc];
            float nm = fmaxf(M, m2);
            Sm = Sm * expf(M - nm) + s2 * expf(m2 - nm);
            M = nm;
        }
        sm[0][kc] = M;
        ss[0][kc] = 1.f / Sm;
    }
    __syncthreads();
    float M = sm[0][kc], inv = ss[0][kc];
    for (int q = qh; q < QL; q += 8) {
        size_t off = base + (size_t)q * QL;
        float v = __bfloat162float(Sh[off]) + __bfloat162float(Sl[off]);
        float p = expf(v - M) * inv;
        bf16 h = __float2bfloat16(p);
        Sh[off] = h;
        Sl[off] = __float2bfloat16(p - __bfloat162float(h));
    }
}

// ---------------- per-token layernorm (split in/out) ----------------
__global__ void ln_k(const bf16* __restrict__ Xh, const bf16* __restrict__ Xl,
                     bf16* __restrict__ Yh, bf16* __restrict__ Yl,
                     const float* __restrict__ gw, const float* __restrict__ bw) {
    int warp = threadIdx.x / 32, lane = threadIdx.x % 32;
    size_t t = (size_t)blockIdx.x * 8 + warp;
    float v[4];
    float sum = 0.f;
#pragma unroll
    for (int i = 0; i < 4; i++) {
        size_t off = t * 128 + lane + 32 * i;
        v[i] = __bfloat162float(Xh[off]) + __bfloat162float(Xl[off]);
        sum += v[i];
    }
#pragma unroll
    for (int o = 16; o; o >>= 1) sum += __shfl_xor_sync(0xffffffffu, sum, o);
    float mean = sum * (1.f / 128.f);
    float vs = 0.f;
#pragma unroll
    for (int i = 0; i < 4; i++) { float d = v[i] - mean; vs += d * d; }
#pragma unroll
    for (int o = 16; o; o >>= 1) vs += __shfl_xor_sync(0xffffffffu, vs, o);
    float inv = rsqrtf(vs * (1.f / 128.f) + 1e-5f);
#pragma unroll
    for (int i = 0; i < 4; i++) {
        int c = lane + 32 * i;
        float r = (v[i] - mean) * inv * gw[c] + bw[c];
        st_split(Yh, Yl, t * 128 + c, r);
    }
}

// ---------------- out = gate * LN(x2 + x3) ----------------
__global__ void addlngate_k(const float* __restrict__ X2, const float* __restrict__ X3,
                            const float* __restrict__ G,
                            const float* __restrict__ gw, const float* __restrict__ bw,
                            float* __restrict__ Y) {
    int warp = threadIdx.x / 32, lane = threadIdx.x % 32;
    size_t t = (size_t)blockIdx.x * 8 + warp;
    float v[4];
    float sum = 0.f;
#pragma unroll
    for (int i = 0; i < 4; i++) {
        size_t c = t * 128 + lane + 32 * i;
        v[i] = X2[c] + X3[c];
        sum += v[i];
    }
#pragma unroll
    for (int o = 16; o; o >>= 1) sum += __shfl_xor_sync(0xffffffffu, sum, o);
    float mean = sum * (1.f / 128.f);
    float vs = 0.f;
#pragma unroll
    for (int i = 0; i < 4; i++) { float d = v[i] - mean; vs += d * d; }
#pragma unroll
    for (int o = 16; o; o >>= 1) vs += __shfl_xor_sync(0xffffffffu, vs, o);
    float inv = rsqrtf(vs * (1.f / 128.f) + 1e-5f);
#pragma unroll
    for (int i = 0; i < 4; i++) {
        int c = lane + 32 * i;
        float nrm = (v[i] - mean) * inv * gw[c] + bw[c];
        Y[t * 128 + c] = G[t * 128 + c] * nrm;
    }
}

// ---------------- final combine (dwt token-major) ----------------
__global__ void final_k(const float* __restrict__ x, const float* __restrict__ ffn,
                        const float* __restrict__ ytok, const float* __restrict__ dwt,
                        float* __restrict__ out) {
    __shared__ float sf[32][65], sy[32][65], sd[32][65];
    int i = blockIdx.x, b = blockIdx.y, tid = threadIdx.x;
    float pos_i = (float)(i * 127) / 63.f;
    int y0 = (int)floorf(pos_i);
    int y1 = min(y0 + 1, 127);
    float wy = pos_i - (float)y0;
    for (int cc = 0; cc < 4; cc++) {
        for (int idx = tid; idx < 64 * 32; idx += 256) {
            int j = idx / 32, cl = idx % 32;
            size_t t = (size_t)b * TOK + i * 64 + j;
            sf[cl][j] = ffn[t * 128 + cc * 32 + cl];
            sy[cl][j] = ytok[t * 128 + cc * 32 + cl];
            sd[cl][j] = dwt[t * 128 + cc * 32 + cl];
        }
        __syncthreads();
        for (int idx = tid; idx < 32 * 64; idx += 256) {
            int cl = idx / 64, j = idx % 64;
            int c = cc * 32 + cl;
            float pos_j = (float)(j * 127) / 63.f;
            int x0 = (int)floorf(pos_j);
            int x1i = min(x0 + 1, 127);
            float wx = pos_j - (float)x0;
            const float* xb = x + (long long)(b * CH + c) * HH * WW;
            float r0 = xb[y0 * WW + x0] * (1.f - wy) + xb[y1 * WW + x0] * wy;
            float r1 = xb[y0 * WW + x1i] * (1.f - wy) + xb[y1 * WW + x1i] * wy;
            float dv = r0 * (1.f - wx) + r1 * wx;
            long long oi = (((long long)b * CH + c) * HO + i) * WO + j;
            out[oi] = sf[cl][j] * (dv - sd[cl][j]) + sy[cl][j];
        }
        __syncthreads();
    }
}

// ---------------- launch ----------------
extern "C" void kernel_launch(void* const* d_in, const int* in_sizes, int n_in,
                              void* d_out, int out_size) {
    (void)in_sizes; (void)n_in; (void)out_size;
    const float* x       = (const float*)d_in[0];
    const float* conv1_b = (const float*)d_in[2];
    const float* l1_w    = (const float*)d_in[3];
    const float* l1_b    = (const float*)d_in[4];
    const float* ln1_g   = (const float*)d_in[5];
    const float* ln1_b   = (const float*)d_in[6];
    const float* fc1_b   = (const float*)d_in[8];
    const float* div_b   = (const float*)d_in[10];
    const float* fc2_b   = (const float*)d_in[12];
    const float* ln3_g   = (const float*)d_in[13];
    const float* ln3_b   = (const float*)d_in[14];
    const float* fc3a_b  = (const float*)d_in[16];
    const float* fc3b_b  = (const float*)d_in[18];
    const float* lnn_g   = (const float*)d_in[19];
    const float* lnn_b   = (const float*)d_in[20];
    const float* act_b   = (const float*)d_in[22];
    float* out = (float*)d_out;

    float *y, *x1, *t1, *x3, *gate, *ffn, *dwt;
    cudaGetSymbolAddress((void**)&y,    g_y);
    cudaGetSymbolAddress((void**)&x1,   g_x1);
    cudaGetSymbolAddress((void**)&t1,   g_t1);
    cudaGetSymbolAddress((void**)&x3,   g_x3);
    cudaGetSymbolAddress((void**)&gate, g_gate);
    cudaGetSymbolAddress((void**)&ffn,  g_ffn);
    cudaGetSymbolAddress((void**)&dwt,  g_dwt);

    bf16 *yLh, *yLl, *hlhh, *hlhl, *yh, *yl, *Sh, *Sl, *yTh, *yTl;
    bf16 *attnh, *attnl, *t0h, *t0l, *x2h, *x2l, *Wh, *Wl, *Wch, *Wcl, *xth, *xtl;
    cudaGetSymbolAddress((void**)&yLh,   syL_h);
    cudaGetSymbolAddress((void**)&yLl,   syL_l);
    cudaGetSymbolAddress((void**)&hlhh,  shlh_h);
    cudaGetSymbolAddress((void**)&hlhl,  shlh_l);
    cudaGetSymbolAddress((void**)&yh,    sy_h);
    cudaGetSymbolAddress((void**)&yl,    sy_l);
    cudaGetSymbolAddress((void**)&Sh,    sS_h);
    cudaGetSymbolAddress((void**)&Sl,    sS_l);
    cudaGetSymbolAddress((void**)&yTh,   syT_h);
    cudaGetSymbolAddress((void**)&yTl,   syT_l);
    cudaGetSymbolAddress((void**)&attnh, sattn_h);
    cudaGetSymbolAddress((void**)&attnl, sattn_l);
    cudaGetSymbolAddress((void**)&t0h,   st0_h);
    cudaGetSymbolAddress((void**)&t0l,   st0_l);
    cudaGetSymbolAddress((void**)&x2h,   sx2_h);
    cudaGetSymbolAddress((void**)&x2l,   sx2_l);
    cudaGetSymbolAddress((void**)&Wh,    sW_h);
    cudaGetSymbolAddress((void**)&Wl,    sW_l);
    cudaGetSymbolAddress((void**)&Wch,   sWc_h);
    cudaGetSymbolAddress((void**)&Wcl,   sWc_l);
    cudaGetSymbolAddress((void**)&xth,   sxt_h);
    cudaGetSymbolAddress((void**)&xtl,   sxt_l);

    cudaFuncSetAttribute(bgemm_k<0,3>, cudaFuncAttributeMaxDynamicSharedMemorySize, BGE_SMEM);
    cudaFuncSetAttribute(bgemm_k<0,2>, cudaFuncAttributeMaxDynamicSharedMemorySize, BGE_SMEM);
    cudaFuncSetAttribute(bgemm_k<1,1>, cudaFuncAttributeMaxDynamicSharedMemorySize, BGE_SMEM);
    cudaFuncSetAttribute(bgemm_k<1,2>, cudaFuncAttributeMaxDynamicSharedMemorySize, BGE_SMEM);
    cudaFuncSetAttribute(bgemm_k<3,2>, cudaFuncAttributeMaxDynamicSharedMemorySize, BGE_SMEM);
    cudaFuncSetAttribute(bgemm_k<0,1>, cudaFuncAttributeMaxDynamicSharedMemorySize, BGE_SMEM);
    cudaFuncSetAttribute(bgemm_k<2,1>, cudaFuncAttributeMaxDynamicSharedMemorySize, BGE_SMEM);
    cudaFuncSetAttribute(cgemm_k, cudaFuncAttributeMaxDynamicSharedMemorySize, BGE_SMEM);

    const float* w0 = (const float*)d_in[1];
    const float* w1 = (const float*)d_in[7];
    const float* w2 = (const float*)d_in[9];
    const float* w3 = (const float*)d_in[11];
    const float* w4 = (const float*)d_in[15];
    const float* w5 = (const float*)d_in[17];
    const float* w6 = (const float*)d_in[21];
    wsplit_k<<<512, 256>>>(w0, w1, w2, w3, w4, w5, w6, Wh, Wl);
    wconv_k<<<1024, 256>>>(l1_w, Wch, Wcl);
    nhwc_k<<<dim3(128, 16), 256>>>(x, xth, xtl);

    haar_k<<<dim3(64, 16), 256>>>(x, yLh, yLl, yTh, yTl, hlhh, hlhl);

    // 1x1 conv: y = hlh @ conv1_w^T + b (K=256)
    bgemm_k<0,3><<<dim3(1, 512, 1), 256, BGE_SMEM>>>(
        hlhh, hlhl, 0, 256, Wh, Wl, 0, 256,
        y, yh, yl, 0, 128, 256, 1.f, conv1_b, nullptr);

    // strided conv as implicit GEMM
    cgemm_k<<<dim3(1, 32, 16), 256, BGE_SMEM>>>(xth, xtl, Wch, Wcl, l1_b, dwt);

    // S = scale * Q @ K^T
    bgemm_k<0,2><<<dim3(4, 4, NG), 256, BGE_SMEM>>>(
        yLh, yLl, (long long)QL * 128, 128, yh, yl, (long long)QL * 128, 128,
        nullptr, Sh, Sl, (long long)QL * QL, QL, 128, 0.35355339059327373f, nullptr, nullptr);

    softmax_q_k<<<dim3(16, NG), 256>>>(Sh, Sl);

    // attn = P @ V (K=512)
    bgemm_k<0,2><<<dim3(1, 4, NG), 256, BGE_SMEM>>>(
        Sh, Sl, (long long)QL * QL, QL, yTh, yTl, (long long)128 * 512, 512,
        nullptr, attnh, attnl, (long long)QL * 128, 128, 512, 1.f, nullptr, nullptr);

    ln_k<<<8192, 256>>>(attnh, attnl, t0h, t0l, ln1_g, ln1_b);
    bgemm_k<1,1><<<dim3(1, 512), 256, BGE_SMEM>>>(
        t0h, t0l, 0, 128, Wh + 32768, Wl + 32768, 0, 128,
        x1, nullptr, nullptr, 0, 128, 128, 1.f, fc1_b, nullptr);
    bgemm_k<3,2><<<dim3(1, 512), 256, BGE_SMEM>>>(
        attnh, attnl, 0, 128, Wh + 49152, Wl + 49152, 0, 128,
        nullptr, x2h, x2l, 0, 128, 128, 1.f, div_b, x1);
    bgemm_k<1,1><<<dim3(1, 512), 256, BGE_SMEM>>>(
        x2h, x2l, 0, 128, Wh + 65536, Wl + 65536, 0, 128,
        t1, nullptr, nullptr, 0, 128, 128, 1.f, fc2_b, nullptr);
    ln_k<<<8192, 256>>>(attnh, attnl, t0h, t0l, ln3_g, ln3_b);
    bgemm_k<1,2><<<dim3(1, 512), 256, BGE_SMEM>>>(
        t0h, t0l, 0, 128, Wh + 81920, Wl + 81920, 0, 128,
        nullptr, x2h, x2l, 0, 128, 128, 1.f, fc3a_b, nullptr);
    bgemm_k<0,1><<<dim3(1, 512), 256, BGE_SMEM>>>(
        x2h, x2l, 0, 128, Wh + 98304, Wl + 98304, 0, 128,
        x3, nullptr, nullptr, 0, 128, 128, 1.f, fc3b_b, nullptr);
    bgemm_k<2,1><<<dim3(1, 512), 256, BGE_SMEM>>>(
        attnh, attnl, 0, 128, Wh + 114688, Wl + 114688, 0, 128,
        gate, nullptr, nullptr, 0, 128, 128, 1.f, act_b, nullptr);
    addlngate_k<<<8192, 256>>>(t1, x3, gate, lnn_g, lnn_b, ffn);

    final_k<<<dim3(64, 16), 256>>>(x, ffn, y, dwt, out);
}

// round 10
// speedup vs baseline: 2.5603x; 1.0830x over previous
#include <cuda_runtime.h>
#include <cuda_bf16.h>
#include <math.h>
#include <stdint.h>

// ---------------- problem constants ----------------
#define BB   16
#define CH   128
#define HH   128
#define WW   128
#define HO   64
#define WO   64
#define TOK  4096
#define NT   65536
#define NG   128
#define QL   512

typedef unsigned long long ull;
typedef __nv_bfloat16 bf16;

// ---------------- fp32 scratch ----------------
__device__ __align__(256) float g_y  [(size_t)NT * 128];
__device__ __align__(256) float g_x1 [(size_t)NT * 128];
__device__ __align__(256) float g_t1 [(size_t)NT * 128];
__device__ __align__(256) float g_x3 [(size_t)NT * 128];
__device__ __align__(256) float g_gate[(size_t)NT * 128];
__device__ __align__(256) float g_ffn[(size_t)NT * 128];
__device__ __align__(256) float g_dwt[(size_t)NT * 128];       // conv out, token-major

// ---------------- split bf16 scratch ----------------
__device__ __align__(256) bf16 syL_h [(size_t)NT * 128];
__device__ __align__(256) bf16 syL_l [(size_t)NT * 128];
__device__ __align__(256) bf16 shlh_h[(size_t)NT * 256];
__device__ __align__(256) bf16 shlh_l[(size_t)NT * 256];
__device__ __align__(256) bf16 sy_h  [(size_t)NT * 128];
__device__ __align__(256) bf16 sy_l  [(size_t)NT * 128];
__device__ __align__(256) bf16 sS_h  [(size_t)NG * QL * QL];
__device__ __align__(256) bf16 sS_l  [(size_t)NG * QL * QL];
__device__ __align__(256) bf16 syT_h [(size_t)NG * 128 * 512];
__device__ __align__(256) bf16 syT_l [(size_t)NG * 128 * 512];
__device__ __align__(256) bf16 sattn_h[(size_t)NT * 128];
__device__ __align__(256) bf16 sattn_l[(size_t)NT * 128];
__device__ __align__(256) bf16 st0_h [(size_t)NT * 128];
__device__ __align__(256) bf16 st0_l [(size_t)NT * 128];
__device__ __align__(256) bf16 st0b_h[(size_t)NT * 128];
__device__ __align__(256) bf16 st0b_l[(size_t)NT * 128];
__device__ __align__(256) bf16 sx2_h [(size_t)NT * 128];
__device__ __align__(256) bf16 sx2_l [(size_t)NT * 128];
__device__ __align__(256) bf16 sx2b_h[(size_t)NT * 128];
__device__ __align__(256) bf16 sx2b_l[(size_t)NT * 128];
__device__ __align__(256) bf16 sW_h  [131072];
__device__ __align__(256) bf16 sW_l  [131072];
__device__ __align__(256) bf16 sWc_h [262144];                  // conv w [oc][(r*4+s)*128+ic]
__device__ __align__(256) bf16 sWc_l [262144];
__device__ __align__(256) bf16 sxt_h [(size_t)BB * HH * WW * CH]; // x NHWC split
__device__ __align__(256) bf16 sxt_l [(size_t)BB * HH * WW * CH];

__device__ __forceinline__ float gelu_f(float v) {
    return 0.5f * v * (1.0f + erff(v * 0.70710678118654752f));
}
__device__ __forceinline__ uint32_t smem_u32(const void* p) {
    uint32_t a;
    asm("{ .reg .u64 t; cvta.to.shared.u64 t, %1; cvt.u32.u64 %0, t; }" : "=r"(a) : "l"(p));
    return a;
}
#define SW128(o) ((o) ^ (((o) >> 3) & 0x70))

__device__ __forceinline__ void st_split(bf16* H, bf16* L, size_t off, float v) {
    bf16 h = __float2bfloat16(v);
    H[off] = h;
    L[off] = __float2bfloat16(v - __bfloat162float(h));
}

// ---- mma.sync bf16 + ldmatrix + cp.async ----
__device__ __forceinline__ void ldm_x4(uint32_t* r, uint32_t addr) {
    asm volatile("ldmatrix.sync.aligned.m8n8.x4.shared.b16 {%0,%1,%2,%3}, [%4];"
                 : "=r"(r[0]), "=r"(r[1]), "=r"(r[2]), "=r"(r[3]) : "r"(addr));
}
__device__ __forceinline__ void ldm_x2(uint32_t* r, uint32_t addr) {
    asm volatile("ldmatrix.sync.aligned.m8n8.x2.shared.b16 {%0,%1}, [%2];"
                 : "=r"(r[0]), "=r"(r[1]) : "r"(addr));
}
__device__ __forceinline__ void mma_bf16(float* d, const uint32_t* a, const uint32_t* b) {
    asm volatile("mma.sync.aligned.m16n8k16.row.col.f32.bf16.bf16.f32 "
                 "{%0,%1,%2,%3}, {%4,%5,%6,%7}, {%8,%9}, {%0,%1,%2,%3};"
                 : "+f"(d[0]), "+f"(d[1]), "+f"(d[2]), "+f"(d[3])
                 : "r"(a[0]), "r"(a[1]), "r"(a[2]), "r"(a[3]), "r"(b[0]), "r"(b[1]));
}
__device__ __forceinline__ void cp16(uint32_t dst, const void* src) {
    asm volatile("cp.async.cg.shared.global [%0], [%1], 16;" :: "r"(dst), "l"(src));
}
__device__ __forceinline__ void cp16z(uint32_t dst, const void* src, int sz) {
    asm volatile("cp.async.cg.shared.global [%0], [%1], 16, %2;" :: "r"(dst), "l"(src), "r"(sz));
}

// ---------------- weight splits ----------------
__global__ void wsplit_k(const float* __restrict__ conv1_w, const float* __restrict__ fc1_w,
                         const float* __restrict__ div_w, const float* __restrict__ fc2_w,
                         const float* __restrict__ fc3a_w, const float* __restrict__ fc3b_w,
                         const float* __restrict__ act_w,
                         bf16* __restrict__ WH, bf16* __restrict__ WL) {
    int i = blockIdx.x * 256 + threadIdx.x;
    float v;
    if      (i <  32768) v = conv1_w[i];
    else if (i <  49152) v = fc1_w [i - 32768];
    else if (i <  65536) v = div_w [i - 49152];
    else if (i <  81920) v = fc2_w [i - 65536];
    else if (i <  98304) v = fc3a_w[i - 81920];
    else if (i < 114688) v = fc3b_w[i - 98304];
    else                 v = act_w [i - 114688];
    bf16 h = __float2bfloat16(v);
    WH[i] = h;
    WL[i] = __float2bfloat16(v - __bfloat162float(h));
}

__global__ void wconv_k(const float* __restrict__ l1_w,
                        bf16* __restrict__ WH, bf16* __restrict__ WL) {
    int i = blockIdx.x * 256 + threadIdx.x;   // 262144
    int oc = i >> 11;
    int k = i & 2047;
    int tap = k >> 7, ic = k & 127;
    float v = l1_w[oc * 2048 + ic * 16 + tap];
    bf16 h = __float2bfloat16(v);
    WH[i] = h;
    WL[i] = __float2bfloat16(v - __bfloat162float(h));
}

// ---------------- x NCHW -> NHWC split ----------------
__global__ void nhwc_k(const float* __restrict__ x,
                       bf16* __restrict__ xh, bf16* __restrict__ xl) {
    __shared__ float tile[32][129];
    int h = blockIdx.x, b = blockIdx.y, tid = threadIdx.x;
    for (int cc = 0; cc < 4; cc++) {
        for (int idx = tid; idx < 32 * 128; idx += 256) {
            int cl = idx >> 7, w = idx & 127;
            tile[cl][w] = x[(((size_t)b * CH + cc * 32 + cl) * HH + h) * WW + w];
        }
        __syncthreads();
        for (int idx = tid; idx < 128 * 32; idx += 256) {
            int w = idx >> 5, cl = idx & 31;
            size_t o = (((size_t)b * HH + h) * WW + w) * CH + cc * 32 + cl;
            st_split(xh, xl, o, tile[cl][w]);
        }
        __syncthreads();
    }
}

// ---------------- Haar DWT -> split token layouts ----------------
__global__ void haar_k(const float* __restrict__ x,
                       bf16* __restrict__ yLh, bf16* __restrict__ yLl,
                       bf16* __restrict__ yTh, bf16* __restrict__ yTl,
                       bf16* __restrict__ hlhh, bf16* __restrict__ hlhl) {
    __shared__ float sLL[32][65], sHL[32][65], sLH[32][65], sHH[32][65];
    int i = blockIdx.x, b = blockIdx.y, tid = threadIdx.x;
    for (int cc = 0; cc < 4; cc++) {
        for (int idx = tid; idx < 32 * 64; idx += 256) {
            int cl = idx / 64, j = idx % 64;
            int c = cc * 32 + cl;
            const float* base = x + (((long long)(b * CH + c) * HH + 2 * i) * WW) + 2 * j;
            float a = base[0], bb2 = base[1], cv = base[WW], d = base[WW + 1];
            sLL[cl][j] = (a + bb2 + cv + d) * 0.5f;
            sHL[cl][j] = (a - bb2 + cv - d) * 0.5f;
            sLH[cl][j] = (a + bb2 - cv - d) * 0.5f;
            sHH[cl][j] = (a - bb2 - cv + d) * 0.5f;
        }
        __syncthreads();
        for (int idx = tid; idx < 64 * 32; idx += 256) {
            int j = idx / 32, cl = idx % 32;
            size_t t = (size_t)b * TOK + i * 64 + j;
            int c = cc * 32 + cl;
            st_split(yLh, yLl, t * 128 + c, sLL[cl][j]);
            st_split(hlhh, hlhl, t * 256 + c, sHL[cl][j]);
            st_split(hlhh, hlhl, t * 256 + 128 + c, sLH[cl][j]);
        }
        {
            int g = b * 8 + (i >> 3);
            int qoff = (i & 7) * 64;
            for (int idx = tid; idx < 32 * 64; idx += 256) {
                int cl = idx / 64, j = idx % 64;
                int c = cc * 32 + cl;
                st_split(yTh, yTl, ((size_t)g * 128 + c) * 512 + qoff + j, sHH[cl][j]);
            }
        }
        __syncthreads();
    }
}

// ---------------- split-bf16 cp.async pipelined GEMM ----------------
#define BGE_SMEM 131072

__device__ __forceinline__ void issue_chunk(
    const bf16* __restrict__ Ahi, const bf16* __restrict__ Alo, int lda,
    const bf16* __restrict__ Bhi, const bf16* __restrict__ Blo, int ldb,
    int k0, uint32_t base, int t) {
#pragma unroll
    for (int q = 0; q < 4; q++) {
        int idx = q * 256 + t;
        int row = idx >> 3, gg = idx & 7;
        uint32_t sw = SW128((uint32_t)(row * 128 + gg * 16));
        cp16(base + sw,         Ahi + (long long)row * lda + k0 + gg * 8);
        cp16(base + 16384 + sw, Alo + (long long)row * lda + k0 + gg * 8);
        cp16(base + 32768 + sw, Bhi + (long long)row * ldb + k0 + gg * 8);
        cp16(base + 49152 + sw, Blo + (long long)row * ldb + k0 + gg * 8);
    }
}

template <int EPI, int OMODE>
__global__ __launch_bounds__(256)
void bgemm_k(const bf16* __restrict__ Ahi, const bf16* __restrict__ Alo, long long sAg, int lda,
             const bf16* __restrict__ Bhi, const bf16* __restrict__ Blo, long long sBg, int ldb,
             float* __restrict__ Cf, bf16* __restrict__ Chi, bf16* __restrict__ Clo,
             long long sCg, int ldc, int K, float alpha,
             const float* __restrict__ bias, const float* __restrict__ extra) {
    extern __shared__ char smem[];
    uint32_t sb = smem_u32(smem);
    int t = threadIdx.x;
    int wid = t >> 5, lane = t & 31;
    int n0 = blockIdx.x * 128;
    int m0 = blockIdx.y * 128;
    int g = blockIdx.z;
    Ahi += (long long)g * sAg + (long long)m0 * lda;
    Alo += (long long)g * sAg + (long long)m0 * lda;
    Bhi += (long long)g * sBg + (long long)n0 * ldb;
    Blo += (long long)g * sBg + (long long)n0 * ldb;
    long long co = (long long)g * sCg;

    int wm = wid >> 2;
    int wn = wid & 3;

    float acc[4][4][4];
#pragma unroll
    for (int mi = 0; mi < 4; mi++)
#pragma unroll
        for (int ni = 0; ni < 4; ni++)
#pragma unroll
            for (int e = 0; e < 4; e++) acc[mi][ni][e] = 0.f;

    int a_row_l = lane & 15;
    int a_k8    = (lane >> 4) << 3;
    int b_row_l = lane & 7;
    int b_k8    = ((lane >> 3) & 1) << 3;

    int nchunks = K >> 6;
    issue_chunk(Ahi, Alo, lda, Bhi, Blo, ldb, 0, sb, t);
    asm volatile("cp.async.commit_group;" ::: "memory");

    for (int ch = 0; ch < nchunks; ch++) {
        if (ch + 1 < nchunks) {
            issue_chunk(Ahi, Alo, lda, Bhi, Blo, ldb, (ch + 1) * 64,
                        sb + ((ch + 1) & 1) * 65536, t);
            asm volatile("cp.async.commit_group;" ::: "memory");
            asm volatile("cp.async.wait_group 1;" ::: "memory");
        } else {
            asm volatile("cp.async.wait_group 0;" ::: "memory");
        }
        __syncthreads();
        uint32_t base = sb + (ch & 1) * 65536;
        uint32_t aHiA = base, aLoA = base + 16384, bHiA = base + 32768, bLoA = base + 49152;
#pragma unroll
        for (int ks = 0; ks < 4; ks++) {
            uint32_t Bh[4][2], Bl[4][2];
#pragma unroll
            for (int ni = 0; ni < 4; ni++) {
                uint32_t byte = (uint32_t)((wn * 32 + ni * 8 + b_row_l) * 128 +
                                           (ks * 16 + b_k8) * 2);
                uint32_t sw = SW128(byte);
                ldm_x2(Bh[ni], bHiA + sw);
                ldm_x2(Bl[ni], bLoA + sw);
            }
#pragma unroll
            for (int mi = 0; mi < 4; mi++) {
                uint32_t Ah[4], Al[4];
                uint32_t byte = (uint32_t)((wm * 64 + mi * 16 + a_row_l) * 128 +
                                           (ks * 16 + a_k8) * 2);
                uint32_t sw = SW128(byte);
                ldm_x4(Ah, aHiA + sw);
                ldm_x4(Al, aLoA + sw);
#pragma unroll
                for (int ni = 0; ni < 4; ni++) {
                    mma_bf16(acc[mi][ni], Ah, Bh[ni]);
                    mma_bf16(acc[mi][ni], Ah, Bl[ni]);
                    mma_bf16(acc[mi][ni], Al, Bh[ni]);
                }
            }
        }
        __syncthreads();
    }

    int rbase = m0 + wm * 64 + (lane >> 2);
    int cbase = n0 + wn * 32 + (lane & 3) * 2;
#pragma unroll
    for (int mi = 0; mi < 4; mi++) {
#pragma unroll
        for (int h = 0; h < 2; h++) {
            int m = rbase + mi * 16 + h * 8;
            long long rowoff = co + (long long)m * ldc;
#pragma unroll
            for (int ni = 0; ni < 4; ni++) {
                int c = cbase + ni * 8;
                float v0 = acc[mi][ni][2 * h]     * alpha;
                float v1 = acc[mi][ni][2 * h + 1] * alpha;
                if (bias) { v0 += bias[c]; v1 += bias[c + 1]; }
                if (EPI == 1 || EPI == 3) { v0 = gelu_f(v0); v1 = gelu_f(v1); }
                if (EPI == 2) {
                    v0 = 1.f / (1.f + expf(-v0));
                    v1 = 1.f / (1.f + expf(-v1));
                }
                if (EPI == 3) {
                    float2 ev = *reinterpret_cast<const float2*>(&extra[rowoff + c]);
                    v0 -= ev.x; v1 -= ev.y;
                }
                if (OMODE & 1) {
                    float2 o; o.x = v0; o.y = v1;
                    *reinterpret_cast<float2*>(&Cf[rowoff + c]) = o;
                }
                if (OMODE & 2) {
                    bf16 h0 = __float2bfloat16(v0), h1 = __float2bfloat16(v1);
                    __nv_bfloat162 hp, lp;
                    hp.x = h0; hp.y = h1;
                    lp.x = __float2bfloat16(v0 - __bfloat162float(h0));
                    lp.y = __float2bfloat16(v1 - __bfloat162float(h1));
                    *reinterpret_cast<__nv_bfloat162*>(&Chi[rowoff + c]) = hp;
                    *reinterpret_cast<__nv_bfloat162*>(&Clo[rowoff + c]) = lp;
                }
            }
        }
    }
}

// ---------------- conv 4x4 s2 p1 as implicit GEMM ----------------
__device__ __forceinline__ void issue_conv_chunk(
    const bf16* __restrict__ xh, const bf16* __restrict__ xl,
    const bf16* __restrict__ wh, const bf16* __restrict__ wl,
    int b, const int* iq, const int* jq, int ch, uint32_t base, int t) {
    int tap = ch >> 1;
    int icH = (ch & 1) * 64;
    int r = tap >> 2, s = tap & 3;
#pragma unroll
    for (int q = 0; q < 4; q++) {
        int idx = q * 256 + t;
        int row = idx >> 3, gg = idx & 7;
        uint32_t sw = SW128((uint32_t)(row * 128 + gg * 16));
        int yy = 2 * iq[q] - 1 + r;
        int xx = 2 * jq[q] - 1 + s;
        bool ok = ((unsigned)yy < 128u) && ((unsigned)xx < 128u);
        int yyc = ok ? yy : 0, xxc = ok ? xx : 0;
        size_t off = ((((size_t)b * HH + yyc) * WW + xxc) * CH) + icH + gg * 8;
        int sz = ok ? 16 : 0;
        cp16z(base + sw,         xh + off, sz);
        cp16z(base + 16384 + sw, xl + off, sz);
        size_t woff = (size_t)row * 2048 + ch * 64 + gg * 8;
        cp16(base + 32768 + sw, wh + woff);
        cp16(base + 49152 + sw, wl + woff);
    }
}

__global__ __launch_bounds__(256)
void cgemm_k(const bf16* __restrict__ xh, const bf16* __restrict__ xl,
             const bf16* __restrict__ wh, const bf16* __restrict__ wl,
             const float* __restrict__ bias, float* __restrict__ dwt) {
    extern __shared__ char smem[];
    uint32_t sb = smem_u32(smem);
    int t = threadIdx.x;
    int wid = t >> 5, lane = t & 31;
    int my = blockIdx.y;
    int b = blockIdx.z;
    int wm = wid >> 2;
    int wn = wid & 3;

    int iq[4], jq[4];
#pragma unroll
    for (int q = 0; q < 4; q++) {
        int idx = q * 256 + t;
        int m = my * 128 + (idx >> 3);
        iq[q] = m >> 6;
        jq[q] = m & 63;
    }

    float acc[4][4][4];
#pragma unroll
    for (int mi = 0; mi < 4; mi++)
#pragma unroll
        for (int ni = 0; ni < 4; ni++)
#pragma unroll
            for (int e = 0; e < 4; e++) acc[mi][ni][e] = 0.f;

    int a_row_l = lane & 15;
    int a_k8    = (lane >> 4) << 3;
    int b_row_l = lane & 7;
    int b_k8    = ((lane >> 3) & 1) << 3;

    issue_conv_chunk(xh, xl, wh, wl, b, iq, jq, 0, sb, t);
    asm volatile("cp.async.commit_group;" ::: "memory");

    for (int ch = 0; ch < 32; ch++) {
        if (ch + 1 < 32) {
            issue_conv_chunk(xh, xl, wh, wl, b, iq, jq, ch + 1,
                             sb + ((ch + 1) & 1) * 65536, t);
            asm volatile("cp.async.commit_group;" ::: "memory");
            asm volatile("cp.async.wait_group 1;" ::: "memory");
        } else {
            asm volatile("cp.async.wait_group 0;" ::: "memory");
        }
        __syncthreads();
        uint32_t base = sb + (ch & 1) * 65536;
        uint32_t aHiA = base, aLoA = base + 16384, bHiA = base + 32768, bLoA = base + 49152;
#pragma unroll
        for (int ks = 0; ks < 4; ks++) {
            uint32_t Bh[4][2], Bl[4][2];
#pragma unroll
            for (int ni = 0; ni < 4; ni++) {
                uint32_t byte = (uint32_t)((wn * 32 + ni * 8 + b_row_l) * 128 +
                                           (ks * 16 + b_k8) * 2);
                uint32_t sw = SW128(byte);
                ldm_x2(Bh[ni], bHiA + sw);
                ldm_x2(Bl[ni], bLoA + sw);
            }
#pragma unroll
            for (int mi = 0; mi < 4; mi++) {
                uint32_t Ah[4], Al[4];
                uint32_t byte = (uint32_t)((wm * 64 + mi * 16 + a_row_l) * 128 +
                                           (ks * 16 + a_k8) * 2);
                uint32_t sw = SW128(byte);
                ldm_x4(Ah, aHiA + sw);
                ldm_x4(Al, aLoA + sw);
#pragma unroll
                for (int ni = 0; ni < 4; ni++) {
                    mma_bf16(acc[mi][ni], Ah, Bh[ni]);
                    mma_bf16(acc[mi][ni], Ah, Bl[ni]);
                    mma_bf16(acc[mi][ni], Al, Bh[ni]);
                }
            }
        }
        __syncthreads();
    }

    int rbase = my * 128 + wm * 64 + (lane >> 2);
    int cbase = wn * 32 + (lane & 3) * 2;
#pragma unroll
    for (int mi = 0; mi < 4; mi++) {
#pragma unroll
        for (int h = 0; h < 2; h++) {
            int m = rbase + mi * 16 + h * 8;
            size_t rowoff = ((size_t)b * TOK + m) * 128;
#pragma unroll
            for (int ni = 0; ni < 4; ni++) {
                int c = cbase + ni * 8;
                float v0 = acc[mi][ni][2 * h]     + bias[c];
                float v1 = acc[mi][ni][2 * h + 1] + bias[c + 1];
                float2 o;
                o.x = fmaxf(v0, 0.f);
                o.y = fmaxf(v1, 0.f);
                *reinterpret_cast<float2*>(&dwt[rowoff + c]) = o;
            }
        }
    }
}

// ---------------- column softmax over q axis ----------------
__global__ void softmax_q_k(bf16* __restrict__ Sh, bf16* __restrict__ Sl) {
    __shared__ float sm[8][32], ss[8][32];
    int g = blockIdx.y;
    int k0 = blockIdx.x * 32;
    int tid = threadIdx.x;
    int kc = tid % 32;
    int qh = tid / 32;
    size_t base = (size_t)g * QL * QL + k0 + kc;
    float m = -INFINITY, s = 0.f;
    for (int q = qh; q < QL; q += 8) {
        size_t off = base + (size_t)q * QL;
        float v = __bfloat162float(Sh[off]) + __bfloat162float(Sl[off]);
        if (v > m) { s = s * expf(m - v) + 1.f; m = v; }
        else s += expf(v - m);
    }
    sm[qh][kc] = m;
    ss[qh][kc] = s;
    __syncthreads();
    if (tid < 32) {
        float M = sm[0][kc], Sm = ss[0][kc];
#pragma unroll
        for (int r = 1; r < 8; r++) {
            float m2 = sm[r][kc], s2 = ss[r][kc];
            float nm = fmaxf(M, m2);
            Sm = Sm * expf(M - nm) + s2 * expf(m2 - nm);
            M = nm;
        }
        sm[0][kc] = M;
        ss[0][kc] = 1.f / Sm;
    }
    __syncthreads();
    float M = sm[0][kc], inv = ss[0][kc];
    for (int q = qh; q < QL; q += 8) {
        size_t off = base + (size_t)q * QL;
        float v = __bfloat162float(Sh[off]) + __bfloat162float(Sl[off]);
        float p = expf(v - M) * inv;
        bf16 h = __float2bfloat16(p);
        Sh[off] = h;
        Sl[off] = __float2bfloat16(p - __bfloat162float(h));
    }
}

// ---------------- per-token layernorm (split in/out) ----------------
__global__ void ln_k(const bf16* __restrict__ Xh, const bf16* __restrict__ Xl,
                     bf16* __restrict__ Yh, bf16* __restrict__ Yl,
                     const float* __restrict__ gw, const float* __restrict__ bw) {
    int warp = threadIdx.x / 32, lane = threadIdx.x % 32;
    size_t t = (size_t)blockIdx.x * 8 + warp;
    float v[4];
    float sum = 0.f;
#pragma unroll
    for (int i = 0; i < 4; i++) {
        size_t off = t * 128 + lane + 32 * i;
        v[i] = __bfloat162float(Xh[off]) + __bfloat162float(Xl[off]);
        sum += v[i];
    }
#pragma unroll
    for (int o = 16; o; o >>= 1) sum += __shfl_xor_sync(0xffffffffu, sum, o);
    float mean = sum * (1.f / 128.f);
    float vs = 0.f;
#pragma unroll
    for (int i = 0; i < 4; i++) { float d = v[i] - mean; vs += d * d; }
#pragma unroll
    for (int o = 16; o; o >>= 1) vs += __shfl_xor_sync(0xffffffffu, vs, o);
    float inv = rsqrtf(vs * (1.f / 128.f) + 1e-5f);
#pragma unroll
    for (int i = 0; i < 4; i++) {
        int c = lane + 32 * i;
        float r = (v[i] - mean) * inv * gw[c] + bw[c];
        st_split(Yh, Yl, t * 128 + c, r);
    }
}

// ---------------- out = gate * LN(x2 + x3) ----------------
__global__ void addlngate_k(const float* __restrict__ X2, const float* __restrict__ X3,
                            const float* __restrict__ G,
                            const float* __restrict__ gw, const float* __restrict__ bw,
                            float* __restrict__ Y) {
    int warp = threadIdx.x / 32, lane = threadIdx.x % 32;
    size_t t = (size_t)blockIdx.x * 8 + warp;
    float v[4];
    float sum = 0.f;
#pragma unroll
    for (int i = 0; i < 4; i++) {
        size_t c = t * 128 + lane + 32 * i;
        v[i] = X2[c] + X3[c];
        sum += v[i];
    }
#pragma unroll
    for (int o = 16; o; o >>= 1) sum += __shfl_xor_sync(0xffffffffu, sum, o);
    float mean = sum * (1.f / 128.f);
    float vs = 0.f;
#pragma unroll
    for (int i = 0; i < 4; i++) { float d = v[i] - mean; vs += d * d; }
#pragma unroll
    for (int o = 16; o; o >>= 1) vs += __shfl_xor_sync(0xffffffffu, vs, o);
    float inv = rsqrtf(vs * (1.f / 128.f) + 1e-5f);
#pragma unroll
    for (int i = 0; i < 4; i++) {
        int c = lane + 32 * i;
        float nrm = (v[i] - mean) * inv * gw[c] + bw[c];
        Y[t * 128 + c] = G[t * 128 + c] * nrm;
    }
}

// ---------------- final combine ----------------
__global__ void final_k(const float* __restrict__ x, const float* __restrict__ ffn,
                        const float* __restrict__ ytok, const float* __restrict__ dwt,
                        float* __restrict__ out) {
    __shared__ float sf[32][65], sy[32][65], sd[32][65];
    int i = blockIdx.x, b = blockIdx.y, tid = threadIdx.x;
    float pos_i = (float)(i * 127) / 63.f;
    int y0 = (int)floorf(pos_i);
    int y1 = min(y0 + 1, 127);
    float wy = pos_i - (float)y0;
    for (int cc = 0; cc < 4; cc++) {
        for (int idx = tid; idx < 64 * 32; idx += 256) {
            int j = idx / 32, cl = idx % 32;
            size_t t = (size_t)b * TOK + i * 64 + j;
            sf[cl][j] = ffn[t * 128 + cc * 32 + cl];
            sy[cl][j] = ytok[t * 128 + cc * 32 + cl];
            sd[cl][j] = dwt[t * 128 + cc * 32 + cl];
        }
        __syncthreads();
        for (int idx = tid; idx < 32 * 64; idx += 256) {
            int cl = idx / 64, j = idx % 64;
            int c = cc * 32 + cl;
            float pos_j = (float)(j * 127) / 63.f;
            int x0 = (int)floorf(pos_j);
            int x1i = min(x0 + 1, 127);
            float wx = pos_j - (float)x0;
            const float* xb = x + (long long)(b * CH + c) * HH * WW;
            float r0 = xb[y0 * WW + x0] * (1.f - wy) + xb[y1 * WW + x0] * wy;
            float r1 = xb[y0 * WW + x1i] * (1.f - wy) + xb[y1 * WW + x1i] * wy;
            float dv = r0 * (1.f - wx) + r1 * wx;
            long long oi = (((long long)b * CH + c) * HO + i) * WO + j;
            out[oi] = sf[cl][j] * (dv - sd[cl][j]) + sy[cl][j];
        }
        __syncthreads();
    }
}

// ---------------- launch (stream-parallel graph branches) ----------------
extern "C" void kernel_launch(void* const* d_in, const int* in_sizes, int n_in,
                              void* d_out, int out_size) {
    (void)in_sizes; (void)n_in; (void)out_size;
    const float* x       = (const float*)d_in[0];
    const float* conv1_b = (const float*)d_in[2];
    const float* l1_w    = (const float*)d_in[3];
    const float* l1_b    = (const float*)d_in[4];
    const float* ln1_g   = (const float*)d_in[5];
    const float* ln1_b   = (const float*)d_in[6];
    const float* fc1_b   = (const float*)d_in[8];
    const float* div_b   = (const float*)d_in[10];
    const float* fc2_b   = (const float*)d_in[12];
    const float* ln3_g   = (const float*)d_in[13];
    const float* ln3_b   = (const float*)d_in[14];
    const float* fc3a_b  = (const float*)d_in[16];
    const float* fc3b_b  = (const float*)d_in[18];
    const float* lnn_g   = (const float*)d_in[19];
    const float* lnn_b   = (const float*)d_in[20];
    const float* act_b   = (const float*)d_in[22];
    float* out = (float*)d_out;

    float *y, *x1, *t1, *x3, *gate, *ffn, *dwt;
    cudaGetSymbolAddress((void**)&y,    g_y);
    cudaGetSymbolAddress((void**)&x1,   g_x1);
    cudaGetSymbolAddress((void**)&t1,   g_t1);
    cudaGetSymbolAddress((void**)&x3,   g_x3);
    cudaGetSymbolAddress((void**)&gate, g_gate);
    cudaGetSymbolAddress((void**)&ffn,  g_ffn);
    cudaGetSymbolAddress((void**)&dwt,  g_dwt);

    bf16 *yLh, *yLl, *hlhh, *hlhl, *yh, *yl, *Sh, *Sl, *yTh, *yTl;
    bf16 *attnh, *attnl, *t0h, *t0l, *t0bh, *t0bl, *x2h, *x2l, *x2bh, *x2bl;
    bf16 *Wh, *Wl, *Wch, *Wcl, *xth, *xtl;
    cudaGetSymbolAddress((void**)&yLh,   syL_h);
    cudaGetSymbolAddress((void**)&yLl,   syL_l);
    cudaGetSymbolAddress((void**)&hlhh,  shlh_h);
    cudaGetSymbolAddress((void**)&hlhl,  shlh_l);
    cudaGetSymbolAddress((void**)&yh,    sy_h);
    cudaGetSymbolAddress((void**)&yl,    sy_l);
    cudaGetSymbolAddress((void**)&Sh,    sS_h);
    cudaGetSymbolAddress((void**)&Sl,    sS_l);
    cudaGetSymbolAddress((void**)&yTh,   syT_h);
    cudaGetSymbolAddress((void**)&yTl,   syT_l);
    cudaGetSymbolAddress((void**)&attnh, sattn_h);
    cudaGetSymbolAddress((void**)&attnl, sattn_l);
    cudaGetSymbolAddress((void**)&t0h,   st0_h);
    cudaGetSymbolAddress((void**)&t0l,   st0_l);
    cudaGetSymbolAddress((void**)&t0bh,  st0b_h);
    cudaGetSymbolAddress((void**)&t0bl,  st0b_l);
    cudaGetSymbolAddress((void**)&x2h,   sx2_h);
    cudaGetSymbolAddress((void**)&x2l,   sx2_l);
    cudaGetSymbolAddress((void**)&x2bh,  sx2b_h);
    cudaGetSymbolAddress((void**)&x2bl,  sx2b_l);
    cudaGetSymbolAddress((void**)&Wh,    sW_h);
    cudaGetSymbolAddress((void**)&Wl,    sW_l);
    cudaGetSymbolAddress((void**)&Wch,   sWc_h);
    cudaGetSymbolAddress((void**)&Wcl,   sWc_l);
    cudaGetSymbolAddress((void**)&xth,   sxt_h);
    cudaGetSymbolAddress((void**)&xtl,   sxt_l);

    cudaFuncSetAttribute(bgemm_k<0,3>, cudaFuncAttributeMaxDynamicSharedMemorySize, BGE_SMEM);
    cudaFuncSetAttribute(bgemm_k<0,2>, cudaFuncAttributeMaxDynamicSharedMemorySize, BGE_SMEM);
    cudaFuncSetAttribute(bgemm_k<1,1>, cudaFuncAttributeMaxDynamicSharedMemorySize, BGE_SMEM);
    cudaFuncSetAttribute(bgemm_k<1,2>, cudaFuncAttributeMaxDynamicSharedMemorySize, BGE_SMEM);
    cudaFuncSetAttribute(bgemm_k<3,2>, cudaFuncAttributeMaxDynamicSharedMemorySize, BGE_SMEM);
    cudaFuncSetAttribute(bgemm_k<0,1>, cudaFuncAttributeMaxDynamicSharedMemorySize, BGE_SMEM);
    cudaFuncSetAttribute(bgemm_k<2,1>, cudaFuncAttributeMaxDynamicSharedMemorySize, BGE_SMEM);
    cudaFuncSetAttribute(cgemm_k, cudaFuncAttributeMaxDynamicSharedMemorySize, BGE_SMEM);

    // streams/events created once (first call = uncaptured correctness run)
    static cudaStream_t sConv = nullptr, sB = nullptr, sC = nullptr;
    static cudaEvent_t eFork = nullptr, eConvDone = nullptr, eAttn = nullptr,
                       eBDone = nullptr, eCDone = nullptr;
    if (!sConv) {
        cudaStreamCreateWithFlags(&sConv, cudaStreamNonBlocking);
        cudaStreamCreateWithFlags(&sB, cudaStreamNonBlocking);
        cudaStreamCreateWithFlags(&sC, cudaStreamNonBlocking);
        cudaEventCreateWithFlags(&eFork, cudaEventDisableTiming);
        cudaEventCreateWithFlags(&eConvDone, cudaEventDisableTiming);
        cudaEventCreateWithFlags(&eAttn, cudaEventDisableTiming);
        cudaEventCreateWithFlags(&eBDone, cudaEventDisableTiming);
        cudaEventCreateWithFlags(&eCDone, cudaEventDisableTiming);
    }

    const float* w0 = (const float*)d_in[1];
    const float* w1 = (const float*)d_in[7];
    const float* w2 = (const float*)d_in[9];
    const float* w3 = (const float*)d_in[11];
    const float* w4 = (const float*)d_in[15];
    const float* w5 = (const float*)d_in[17];
    const float* w6 = (const float*)d_in[21];

    // ---- fork conv branch off the main (default) stream ----
    cudaEventRecord(eFork, 0);
    cudaStreamWaitEvent(sConv, eFork, 0);
    nhwc_k<<<dim3(128, 16), 256, 0, sConv>>>(x, xth, xtl);
    wconv_k<<<1024, 256, 0, sConv>>>(l1_w, Wch, Wcl);
    cgemm_k<<<dim3(1, 32, 16), 256, BGE_SMEM, sConv>>>(xth, xtl, Wch, Wcl, l1_b, dwt);
    cudaEventRecord(eConvDone, sConv);

    // ---- main attention chain ----
    wsplit_k<<<512, 256>>>(w0, w1, w2, w3, w4, w5, w6, Wh, Wl);
    haar_k<<<dim3(64, 16), 256>>>(x, yLh, yLl, yTh, yTl, hlhh, hlhl);

    bgemm_k<0,3><<<dim3(1, 512, 1), 256, BGE_SMEM>>>(
        hlhh, hlhl, 0, 256, Wh, Wl, 0, 256,
        y, yh, yl, 0, 128, 256, 1.f, conv1_b, nullptr);

    bgemm_k<0,2><<<dim3(4, 4, NG), 256, BGE_SMEM>>>(
        yLh, yLl, (long long)QL * 128, 128, yh, yl, (long long)QL * 128, 128,
        nullptr, Sh, Sl, (long long)QL * QL, QL, 128, 0.35355339059327373f, nullptr, nullptr);

    softmax_q_k<<<dim3(16, NG), 256>>>(Sh, Sl);

    bgemm_k<0,2><<<dim3(1, 4, NG), 256, BGE_SMEM>>>(
        Sh, Sl, (long long)QL * QL, QL, yTh, yTl, (long long)128 * 512, 512,
        nullptr, attnh, attnl, (long long)QL * 128, 128, 512, 1.f, nullptr, nullptr);
    cudaEventRecord(eAttn, 0);

    // ---- FFN side chain B: ln3 -> fc3a -> fc3b ----
    cudaStreamWaitEvent(sB, eAttn, 0);
    ln_k<<<8192, 256, 0, sB>>>(attnh, attnl, t0bh, t0bl, ln3_g, ln3_b);
    bgemm_k<1,2><<<dim3(1, 512), 256, BGE_SMEM, sB>>>(
        t0bh, t0bl, 0, 128, Wh + 81920, Wl + 81920, 0, 128,
        nullptr, x2bh, x2bl, 0, 128, 128, 1.f, fc3a_b, nullptr);
    bgemm_k<0,1><<<dim3(1, 512), 256, BGE_SMEM, sB>>>(
        x2bh, x2bl, 0, 128, Wh + 98304, Wl + 98304, 0, 128,
        x3, nullptr, nullptr, 0, 128, 128, 1.f, fc3b_b, nullptr);
    cudaEventRecord(eBDone, sB);

    // ---- FFN side chain C: gate ----
    cudaStreamWaitEvent(sC, eAttn, 0);
    bgemm_k<2,1><<<dim3(1, 512), 256, BGE_SMEM, sC>>>(
        attnh, attnl, 0, 128, Wh + 114688, Wl + 114688, 0, 128,
        gate, nullptr, nullptr, 0, 128, 128, 1.f, act_b, nullptr);
    cudaEventRecord(eCDone, sC);

    // ---- FFN main chain: ln1 -> fc1 -> div -> fc2 ----
    ln_k<<<8192, 256>>>(attnh, attnl, t0h, t0l, ln1_g, ln1_b);
    bgemm_k<1,1><<<dim3(1, 512), 256, BGE_SMEM>>>(
        t0h, t0l, 0, 128, Wh + 32768, Wl + 32768, 0, 128,
        x1, nullptr, nullptr, 0, 128, 128, 1.f, fc1_b, nullptr);
    bgemm_k<3,2><<<dim3(1, 512), 256, BGE_SMEM>>>(
        attnh, attnl, 0, 128, Wh + 49152, Wl + 49152, 0, 128,
        nullptr, x2h, x2l, 0, 128, 128, 1.f, div_b, x1);
    bgemm_k<1,1><<<dim3(1, 512), 256, BGE_SMEM>>>(
        x2h, x2l, 0, 128, Wh + 65536, Wl + 65536, 0, 128,
        t1, nullptr, nullptr, 0, 128, 128, 1.f, fc2_b, nullptr);

    // ---- join ----
    cudaStreamWaitEvent(0, eBDone, 0);
    cudaStreamWaitEvent(0, eCDone, 0);
    addlngate_k<<<8192, 256>>>(t1, x3, gate, lnn_g, lnn_b, ffn);
    cudaStreamWaitEvent(0, eConvDone, 0);
    final_k<<<dim3(64, 16), 256>>>(x, ffn, y, dwt, out);
}

// round 12
// speedup vs baseline: 2.8054x; 1.0957x over previous
#include <cuda_runtime.h>
#include <cuda_bf16.h>
#include <math.h>
#include <stdint.h>

// ---------------- problem constants ----------------
#define BB   16
#define CH   128
#define HH   128
#define WW   128
#define HO   64
#define WO   64
#define TOK  4096
#define NT   65536
#define NG   128
#define QL   512

typedef unsigned long long ull;
typedef __nv_bfloat16 bf16;

// ---------------- fp32 scratch ----------------
__device__ __align__(256) float g_y  [(size_t)NT * 128];
__device__ __align__(256) float g_x1 [(size_t)NT * 128];
__device__ __align__(256) float g_t1 [(size_t)NT * 128];
__device__ __align__(256) float g_x3 [(size_t)NT * 128];
__device__ __align__(256) float g_gate[(size_t)NT * 128];
__device__ __align__(256) float g_dwt[(size_t)NT * 128];       // conv out, token-major
__device__ __align__(256) float g_Sf [(size_t)NG * QL * QL];   // raw scores fp32

// ---------------- split bf16 scratch ----------------
__device__ __align__(256) bf16 syL_h [(size_t)NT * 128];
__device__ __align__(256) bf16 syL_l [(size_t)NT * 128];
__device__ __align__(256) bf16 shlh_h[(size_t)NT * 256];
__device__ __align__(256) bf16 shlh_l[(size_t)NT * 256];
__device__ __align__(256) bf16 sy_h  [(size_t)NT * 128];
__device__ __align__(256) bf16 sy_l  [(size_t)NT * 128];
__device__ __align__(256) bf16 sS_h  [(size_t)NG * QL * QL];
__device__ __align__(256) bf16 sS_l  [(size_t)NG * QL * QL];
__device__ __align__(256) bf16 syT_h [(size_t)NG * 128 * 512];
__device__ __align__(256) bf16 syT_l [(size_t)NG * 128 * 512];
__device__ __align__(256) bf16 sattn_h[(size_t)NT * 128];
__device__ __align__(256) bf16 sattn_l[(size_t)NT * 128];
__device__ __align__(256) bf16 st0_h [(size_t)NT * 128];
__device__ __align__(256) bf16 st0_l [(size_t)NT * 128];
__device__ __align__(256) bf16 st0b_h[(size_t)NT * 128];
__device__ __align__(256) bf16 st0b_l[(size_t)NT * 128];
__device__ __align__(256) bf16 sx2_h [(size_t)NT * 128];
__device__ __align__(256) bf16 sx2_l [(size_t)NT * 128];
__device__ __align__(256) bf16 sx2b_h[(size_t)NT * 128];
__device__ __align__(256) bf16 sx2b_l[(size_t)NT * 128];
__device__ __align__(256) bf16 sW_h  [131072];
__device__ __align__(256) bf16 sW_l  [131072];
__device__ __align__(256) bf16 sWc_h [262144];                  // conv w [oc][(r*4+s)*128+ic]
__device__ __align__(256) bf16 sWc_l [262144];
__device__ __align__(256) bf16 sxt_h [(size_t)BB * HH * WW * CH]; // x NHWC split
__device__ __align__(256) bf16 sxt_l [(size_t)BB * HH * WW * CH];

__device__ __forceinline__ float gelu_f(float v) {
    return 0.5f * v * (1.0f + erff(v * 0.70710678118654752f));
}
__device__ __forceinline__ uint32_t smem_u32(const void* p) {
    uint32_t a;
    asm("{ .reg .u64 t; cvta.to.shared.u64 t, %1; cvt.u32.u64 %0, t; }" : "=r"(a) : "l"(p));
    return a;
}
#define SW128(o) ((o) ^ (((o) >> 3) & 0x70))

__device__ __forceinline__ void st_split(bf16* H, bf16* L, size_t off, float v) {
    bf16 h = __float2bfloat16(v);
    H[off] = h;
    L[off] = __float2bfloat16(v - __bfloat162float(h));
}

// ---- mma.sync bf16 + ldmatrix + cp.async ----
__device__ __forceinline__ void ldm_x4(uint32_t* r, uint32_t addr) {
    asm volatile("ldmatrix.sync.aligned.m8n8.x4.shared.b16 {%0,%1,%2,%3}, [%4];"
                 : "=r"(r[0]), "=r"(r[1]), "=r"(r[2]), "=r"(r[3]) : "r"(addr));
}
__device__ __forceinline__ void ldm_x2(uint32_t* r, uint32_t addr) {
    asm volatile("ldmatrix.sync.aligned.m8n8.x2.shared.b16 {%0,%1}, [%2];"
                 : "=r"(r[0]), "=r"(r[1]) : "r"(addr));
}
__device__ __forceinline__ void mma_bf16(float* d, const uint32_t* a, const uint32_t* b) {
    asm volatile("mma.sync.aligned.m16n8k16.row.col.f32.bf16.bf16.f32 "
                 "{%0,%1,%2,%3}, {%4,%5,%6,%7}, {%8,%9}, {%0,%1,%2,%3};"
                 : "+f"(d[0]), "+f"(d[1]), "+f"(d[2]), "+f"(d[3])
                 : "r"(a[0]), "r"(a[1]), "r"(a[2]), "r"(a[3]), "r"(b[0]), "r"(b[1]));
}
__device__ __forceinline__ void cp16(uint32_t dst, const void* src) {
    asm volatile("cp.async.cg.shared.global [%0], [%1], 16;" :: "r"(dst), "l"(src));
}
__device__ __forceinline__ void cp16z(uint32_t dst, const void* src, int sz) {
    asm volatile("cp.async.cg.shared.global [%0], [%1], 16, %2;" :: "r"(dst), "l"(src), "r"(sz));
}

// ---------------- weight splits ----------------
__global__ void wsplit_k(const float* __restrict__ conv1_w, const float* __restrict__ fc1_w,
                         const float* __restrict__ div_w, const float* __restrict__ fc2_w,
                         const float* __restrict__ fc3a_w, const float* __restrict__ fc3b_w,
                         const float* __restrict__ act_w,
                         bf16* __restrict__ WH, bf16* __restrict__ WL) {
    int i = blockIdx.x * 256 + threadIdx.x;
    float v;
    if      (i <  32768) v = conv1_w[i];
    else if (i <  49152) v = fc1_w [i - 32768];
    else if (i <  65536) v = div_w [i - 49152];
    else if (i <  81920) v = fc2_w [i - 65536];
    else if (i <  98304) v = fc3a_w[i - 81920];
    else if (i < 114688) v = fc3b_w[i - 98304];
    else                 v = act_w [i - 114688];
    bf16 h = __float2bfloat16(v);
    WH[i] = h;
    WL[i] = __float2bfloat16(v - __bfloat162float(h));
}

__global__ void wconv_k(const float* __restrict__ l1_w,
                        bf16* __restrict__ WH, bf16* __restrict__ WL) {
    int i = blockIdx.x * 256 + threadIdx.x;   // 262144
    int oc = i >> 11;
    int k = i & 2047;
    int tap = k >> 7, ic = k & 127;
    float v = l1_w[oc * 2048 + ic * 16 + tap];
    bf16 h = __float2bfloat16(v);
    WH[i] = h;
    WL[i] = __float2bfloat16(v - __bfloat162float(h));
}

// ---------------- x NCHW -> NHWC split ----------------
__global__ void nhwc_k(const float* __restrict__ x,
                       bf16* __restrict__ xh, bf16* __restrict__ xl) {
    __shared__ float tile[32][129];
    int h = blockIdx.x, b = blockIdx.y, tid = threadIdx.x;
    for (int cc = 0; cc < 4; cc++) {
        for (int idx = tid; idx < 32 * 128; idx += 256) {
            int cl = idx >> 7, w = idx & 127;
            tile[cl][w] = x[(((size_t)b * CH + cc * 32 + cl) * HH + h) * WW + w];
        }
        __syncthreads();
        for (int idx = tid; idx < 128 * 32; idx += 256) {
            int w = idx >> 5, cl = idx & 31;
            size_t o = (((size_t)b * HH + h) * WW + w) * CH + cc * 32 + cl;
            st_split(xh, xl, o, tile[cl][w]);
        }
        __syncthreads();
    }
}

// ---------------- Haar DWT -> split token layouts ----------------
__global__ void haar_k(const float* __restrict__ x,
                       bf16* __restrict__ yLh, bf16* __restrict__ yLl,
                       bf16* __restrict__ yTh, bf16* __restrict__ yTl,
                       bf16* __restrict__ hlhh, bf16* __restrict__ hlhl) {
    __shared__ float sLL[32][65], sHL[32][65], sLH[32][65], sHH[32][65];
    int i = blockIdx.x, b = blockIdx.y, tid = threadIdx.x;
    for (int cc = 0; cc < 4; cc++) {
        for (int idx = tid; idx < 32 * 64; idx += 256) {
            int cl = idx / 64, j = idx % 64;
            int c = cc * 32 + cl;
            const float* base = x + (((long long)(b * CH + c) * HH + 2 * i) * WW) + 2 * j;
            float a = base[0], bb2 = base[1], cv = base[WW], d = base[WW + 1];
            sLL[cl][j] = (a + bb2 + cv + d) * 0.5f;
            sHL[cl][j] = (a - bb2 + cv - d) * 0.5f;
            sLH[cl][j] = (a + bb2 - cv - d) * 0.5f;
            sHH[cl][j] = (a - bb2 - cv + d) * 0.5f;
        }
        __syncthreads();
        for (int idx = tid; idx < 64 * 32; idx += 256) {
            int j = idx / 32, cl = idx % 32;
            size_t t = (size_t)b * TOK + i * 64 + j;
            int c = cc * 32 + cl;
            st_split(yLh, yLl, t * 128 + c, sLL[cl][j]);
            st_split(hlhh, hlhl, t * 256 + c, sHL[cl][j]);
            st_split(hlhh, hlhl, t * 256 + 128 + c, sLH[cl][j]);
        }
        {
            int g = b * 8 + (i >> 3);
            int qoff = (i & 7) * 64;
            for (int idx = tid; idx < 32 * 64; idx += 256) {
                int cl = idx / 64, j = idx % 64;
                int c = cc * 32 + cl;
                st_split(yTh, yTl, ((size_t)g * 128 + c) * 512 + qoff + j, sHH[cl][j]);
            }
        }
        __syncthreads();
    }
}

// ---------------- split-bf16 cp.async pipelined GEMM ----------------
#define BGE_SMEM 131072

__device__ __forceinline__ void issue_chunk(
    const bf16* __restrict__ Ahi, const bf16* __restrict__ Alo, int lda,
    const bf16* __restrict__ Bhi, const bf16* __restrict__ Blo, int ldb,
    int k0, uint32_t base, int t) {
#pragma unroll
    for (int q = 0; q < 4; q++) {
        int idx = q * 256 + t;
        int row = idx >> 3, gg = idx & 7;
        uint32_t sw = SW128((uint32_t)(row * 128 + gg * 16));
        cp16(base + sw,         Ahi + (long long)row * lda + k0 + gg * 8);
        cp16(base + 16384 + sw, Alo + (long long)row * lda + k0 + gg * 8);
        cp16(base + 32768 + sw, Bhi + (long long)row * ldb + k0 + gg * 8);
        cp16(base + 49152 + sw, Blo + (long long)row * ldb + k0 + gg * 8);
    }
}

template <int EPI, int OMODE>
__global__ __launch_bounds__(256)
void bgemm_k(const bf16* __restrict__ Ahi, const bf16* __restrict__ Alo, long long sAg, int lda,
             const bf16* __restrict__ Bhi, const bf16* __restrict__ Blo, long long sBg, int ldb,
             float* __restrict__ Cf, bf16* __restrict__ Chi, bf16* __restrict__ Clo,
             long long sCg, int ldc, int K, float alpha,
             const float* __restrict__ bias, const float* __restrict__ extra) {
    extern __shared__ char smem[];
    uint32_t sb = smem_u32(smem);
    int t = threadIdx.x;
    int wid = t >> 5, lane = t & 31;
    int n0 = blockIdx.x * 128;
    int m0 = blockIdx.y * 128;
    int g = blockIdx.z;
    Ahi += (long long)g * sAg + (long long)m0 * lda;
    Alo += (long long)g * sAg + (long long)m0 * lda;
    Bhi += (long long)g * sBg + (long long)n0 * ldb;
    Blo += (long long)g * sBg + (long long)n0 * ldb;
    long long co = (long long)g * sCg;

    int wm = wid >> 2;
    int wn = wid & 3;

    float acc[4][4][4];
#pragma unroll
    for (int mi = 0; mi < 4; mi++)
#pragma unroll
        for (int ni = 0; ni < 4; ni++)
#pragma unroll
            for (int e = 0; e < 4; e++) acc[mi][ni][e] = 0.f;

    int a_row_l = lane & 15;
    int a_k8    = (lane >> 4) << 3;
    int b_row_l = lane & 7;
    int b_k8    = ((lane >> 3) & 1) << 3;

    int nchunks = K >> 6;
    issue_chunk(Ahi, Alo, lda, Bhi, Blo, ldb, 0, sb, t);
    asm volatile("cp.async.commit_group;" ::: "memory");

    for (int ch = 0; ch < nchunks; ch++) {
        if (ch + 1 < nchunks) {
            issue_chunk(Ahi, Alo, lda, Bhi, Blo, ldb, (ch + 1) * 64,
                        sb + ((ch + 1) & 1) * 65536, t);
            asm volatile("cp.async.commit_group;" ::: "memory");
            asm volatile("cp.async.wait_group 1;" ::: "memory");
        } else {
            asm volatile("cp.async.wait_group 0;" ::: "memory");
        }
        __syncthreads();
        uint32_t base = sb + (ch & 1) * 65536;
        uint32_t aHiA = base, aLoA = base + 16384, bHiA = base + 32768, bLoA = base + 49152;
#pragma unroll
        for (int ks = 0; ks < 4; ks++) {
            uint32_t Bh[4][2], Bl[4][2];
#pragma unroll
            for (int ni = 0; ni < 4; ni++) {
                uint32_t byte = (uint32_t)((wn * 32 + ni * 8 + b_row_l) * 128 +
                                           (ks * 16 + b_k8) * 2);
                uint32_t sw = SW128(byte);
                ldm_x2(Bh[ni], bHiA + sw);
                ldm_x2(Bl[ni], bLoA + sw);
            }
#pragma unroll
            for (int mi = 0; mi < 4; mi++) {
                uint32_t Ah[4], Al[4];
                uint32_t byte = (uint32_t)((wm * 64 + mi * 16 + a_row_l) * 128 +
                                           (ks * 16 + a_k8) * 2);
                uint32_t sw = SW128(byte);
                ldm_x4(Ah, aHiA + sw);
                ldm_x4(Al, aLoA + sw);
#pragma unroll
                for (int ni = 0; ni < 4; ni++) {
                    mma_bf16(acc[mi][ni], Ah, Bh[ni]);
                    mma_bf16(acc[mi][ni], Ah, Bl[ni]);
                    mma_bf16(acc[mi][ni], Al, Bh[ni]);
                }
            }
        }
        __syncthreads();
    }

    int rbase = m0 + wm * 64 + (lane >> 2);
    int cbase = n0 + wn * 32 + (lane & 3) * 2;
#pragma unroll
    for (int mi = 0; mi < 4; mi++) {
#pragma unroll
        for (int h = 0; h < 2; h++) {
            int m = rbase + mi * 16 + h * 8;
            long long rowoff = co + (long long)m * ldc;
#pragma unroll
            for (int ni = 0; ni < 4; ni++) {
                int c = cbase + ni * 8;
                float v0 = acc[mi][ni][2 * h]     * alpha;
                float v1 = acc[mi][ni][2 * h + 1] * alpha;
                if (bias) { v0 += bias[c]; v1 += bias[c + 1]; }
                if (EPI == 1 || EPI == 3) { v0 = gelu_f(v0); v1 = gelu_f(v1); }
                if (EPI == 2) {
                    v0 = 1.f / (1.f + expf(-v0));
                    v1 = 1.f / (1.f + expf(-v1));
                }
                if (EPI == 3) {
                    float2 ev = *reinterpret_cast<const float2*>(&extra[rowoff + c]);
                    v0 -= ev.x; v1 -= ev.y;
                }
                if (OMODE & 1) {
                    float2 o; o.x = v0; o.y = v1;
                    *reinterpret_cast<float2*>(&Cf[rowoff + c]) = o;
                }
                if (OMODE & 2) {
                    bf16 h0 = __float2bfloat16(v0), h1 = __float2bfloat16(v1);
                    __nv_bfloat162 hp, lp;
                    hp.x = h0; hp.y = h1;
                    lp.x = __float2bfloat16(v0 - __bfloat162float(h0));
                    lp.y = __float2bfloat16(v1 - __bfloat162float(h1));
                    *reinterpret_cast<__nv_bfloat162*>(&Chi[rowoff + c]) = hp;
                    *reinterpret_cast<__nv_bfloat162*>(&Clo[rowoff + c]) = lp;
                }
            }
        }
    }
}

// ---------------- conv 4x4 s2 p1 as implicit GEMM ----------------
__device__ __forceinline__ void issue_conv_chunk(
    const bf16* __restrict__ xh, const bf16* __restrict__ xl,
    const bf16* __restrict__ wh, const bf16* __restrict__ wl,
    int b, const int* iq, const int* jq, int ch, uint32_t base, int t) {
    int tap = ch >> 1;
    int icH = (ch & 1) * 64;
    int r = tap >> 2, s = tap & 3;
#pragma unroll
    for (int q = 0; q < 4; q++) {
        int idx = q * 256 + t;
        int row = idx >> 3, gg = idx & 7;
        uint32_t sw = SW128((uint32_t)(row * 128 + gg * 16));
        int yy = 2 * iq[q] - 1 + r;
        int xx = 2 * jq[q] - 1 + s;
        bool ok = ((unsigned)yy < 128u) && ((unsigned)xx < 128u);
        int yyc = ok ? yy : 0, xxc = ok ? xx : 0;
        size_t off = ((((size_t)b * HH + yyc) * WW + xxc) * CH) + icH + gg * 8;
        int sz = ok ? 16 : 0;
        cp16z(base + sw,         xh + off, sz);
        cp16z(base + 16384 + sw, xl + off, sz);
        size_t woff = (size_t)row * 2048 + ch * 64 + gg * 8;
        cp16(base + 32768 + sw, wh + woff);
        cp16(base + 49152 + sw, wl + woff);
    }
}

__global__ __launch_bounds__(256)
void cgemm_k(const bf16* __restrict__ xh, const bf16* __restrict__ xl,
             const bf16* __restrict__ wh, const bf16* __restrict__ wl,
             const float* __restrict__ bias, float* __restrict__ dwt) {
    extern __shared__ char smem[];
    uint32_t sb = smem_u32(smem);
    int t = threadIdx.x;
    int wid = t >> 5, lane = t & 31;
    int my = blockIdx.y;
    int b = blockIdx.z;
    int wm = wid >> 2;
    int wn = wid & 3;

    int iq[4], jq[4];
#pragma unroll
    for (int q = 0; q < 4; q++) {
        int idx = q * 256 + t;
        int m = my * 128 + (idx >> 3);
        iq[q] = m >> 6;
        jq[q] = m & 63;
    }

    float acc[4][4][4];
#pragma unroll
    for (int mi = 0; mi < 4; mi++)
#pragma unroll
        for (int ni = 0; ni < 4; ni++)
#pragma unroll
            for (int e = 0; e < 4; e++) acc[mi][ni][e] = 0.f;

    int a_row_l = lane & 15;
    int a_k8    = (lane >> 4) << 3;
    int b_row_l = lane & 7;
    int b_k8    = ((lane >> 3) & 1) << 3;

    issue_conv_chunk(xh, xl, wh, wl, b, iq, jq, 0, sb, t);
    asm volatile("cp.async.commit_group;" ::: "memory");

    for (int ch = 0; ch < 32; ch++) {
        if (ch + 1 < 32) {
            issue_conv_chunk(xh, xl, wh, wl, b, iq, jq, ch + 1,
                             sb + ((ch + 1) & 1) * 65536, t);
            asm volatile("cp.async.commit_group;" ::: "memory");
            asm volatile("cp.async.wait_group 1;" ::: "memory");
        } else {
            asm volatile("cp.async.wait_group 0;" ::: "memory");
        }
        __syncthreads();
        uint32_t base = sb + (ch & 1) * 65536;
        uint32_t aHiA = base, aLoA = base + 16384, bHiA = base + 32768, bLoA = base + 49152;
#pragma unroll
        for (int ks = 0; ks < 4; ks++) {
            uint32_t Bh[4][2], Bl[4][2];
#pragma unroll
            for (int ni = 0; ni < 4; ni++) {
                uint32_t byte = (uint32_t)((wn * 32 + ni * 8 + b_row_l) * 128 +
                                           (ks * 16 + b_k8) * 2);
                uint32_t sw = SW128(byte);
                ldm_x2(Bh[ni], bHiA + sw);
                ldm_x2(Bl[ni], bLoA + sw);
            }
#pragma unroll
            for (int mi = 0; mi < 4; mi++) {
                uint32_t Ah[4], Al[4];
                uint32_t byte = (uint32_t)((wm * 64 + mi * 16 + a_row_l) * 128 +
                                           (ks * 16 + a_k8) * 2);
                uint32_t sw = SW128(byte);
                ldm_x4(Ah, aHiA + sw);
                ldm_x4(Al, aLoA + sw);
#pragma unroll
                for (int ni = 0; ni < 4; ni++) {
                    mma_bf16(acc[mi][ni], Ah, Bh[ni]);
                    mma_bf16(acc[mi][ni], Ah, Bl[ni]);
                    mma_bf16(acc[mi][ni], Al, Bh[ni]);
                }
            }
        }
        __syncthreads();
    }

    int rbase = my * 128 + wm * 64 + (lane >> 2);
    int cbase = wn * 32 + (lane & 3) * 2;
#pragma unroll
    for (int mi = 0; mi < 4; mi++) {
#pragma unroll
        for (int h = 0; h < 2; h++) {
            int m = rbase + mi * 16 + h * 8;
            size_t rowoff = ((size_t)b * TOK + m) * 128;
#pragma unroll
            for (int ni = 0; ni < 4; ni++) {
                int c = cbase + ni * 8;
                float v0 = acc[mi][ni][2 * h]     + bias[c];
                float v1 = acc[mi][ni][2 * h + 1] + bias[c + 1];
                float2 o;
                o.x = fmaxf(v0, 0.f);
                o.y = fmaxf(v1, 0.f);
                *reinterpret_cast<float2*>(&dwt[rowoff + c]) = o;
            }
        }
    }
}

// ---------------- smem-resident column softmax over q ----------------
// block = (32 k-cols, group); tile 512x32 fp32 = 64KB dynamic smem
#define SMX_SMEM 65536
__global__ __launch_bounds__(256)
void softmax2_k(const float* __restrict__ Sf, bf16* __restrict__ Sh, bf16* __restrict__ Sl) {
    extern __shared__ float tile[];            // [512][32]
    __shared__ float red[8][32];
    int g = blockIdx.y;
    int k0 = blockIdx.x * 32;
    int t = threadIdx.x;
    int kc = t & 31, qh = t >> 5;
    const float* Sg = Sf + (size_t)g * QL * QL + k0 + kc;
    for (int q = qh; q < QL; q += 8)
        tile[q * 32 + kc] = Sg[(size_t)q * QL];
    __syncthreads();
    // max over q
    float m = -INFINITY;
    for (int q = qh; q < QL; q += 8) m = fmaxf(m, tile[q * 32 + kc]);
    red[qh][kc] = m;
    __syncthreads();
    if (t < 32) {
        float M = red[0][kc];
#pragma unroll
        for (int r = 1; r < 8; r++) M = fmaxf(M, red[r][kc]);
        red[0][kc] = M;
    }
    __syncthreads();
    float M = red[0][kc];
    __syncthreads();
    // exp + sum (exp cached back into tile)
    float s = 0.f;
    for (int q = qh; q < QL; q += 8) {
        float e = expf(tile[q * 32 + kc] - M);
        tile[q * 32 + kc] = e;
        s += e;
    }
    red[qh][kc] = s;
    __syncthreads();
    if (t < 32) {
        float S = 0.f;
#pragma unroll
        for (int r = 0; r < 8; r++) S += red[r][kc];
        red[0][kc] = 1.f / S;
    }
    __syncthreads();
    float inv = red[0][kc];
    size_t obase = (size_t)g * QL * QL + k0 + kc;
    for (int q = qh; q < QL; q += 8) {
        float p = tile[q * 32 + kc] * inv;
        bf16 h = __float2bfloat16(p);
        Sh[obase + (size_t)q * QL] = h;
        Sl[obase + (size_t)q * QL] = __float2bfloat16(p - __bfloat162float(h));
    }
}

// ---------------- per-token layernorm (split in/out) ----------------
__global__ void ln_k(const bf16* __restrict__ Xh, const bf16* __restrict__ Xl,
                     bf16* __restrict__ Yh, bf16* __restrict__ Yl,
                     const float* __restrict__ gw, const float* __restrict__ bw) {
    int warp = threadIdx.x / 32, lane = threadIdx.x % 32;
    size_t t = (size_t)blockIdx.x * 8 + warp;
    float v[4];
    float sum = 0.f;
#pragma unroll
    for (int i = 0; i < 4; i++) {
        size_t off = t * 128 + lane + 32 * i;
        v[i] = __bfloat162float(Xh[off]) + __bfloat162float(Xl[off]);
        sum += v[i];
    }
#pragma unroll
    for (int o = 16; o; o >>= 1) sum += __shfl_xor_sync(0xffffffffu, sum, o);
    float mean = sum * (1.f / 128.f);
    float vs = 0.f;
#pragma unroll
    for (int i = 0; i < 4; i++) { float d = v[i] - mean; vs += d * d; }
#pragma unroll
    for (int o = 16; o; o >>= 1) vs += __shfl_xor_sync(0xffffffffu, vs, o);
    float inv = rsqrtf(vs * (1.f / 128.f) + 1e-5f);
#pragma unroll
    for (int i = 0; i < 4; i++) {
        int c = lane + 32 * i;
        float r = (v[i] - mean) * inv * gw[c] + bw[c];
        st_split(Yh, Yl, t * 128 + c, r);
    }
}

// ---------------- fused: ffn=gate*LN(t1+x3) + final combine ----------------
#define FIN_SMEM (64 * 129 * 4)
__global__ __launch_bounds__(256)
void final2_k(const float* __restrict__ x,
              const float* __restrict__ T1, const float* __restrict__ X3,
              const float* __restrict__ G,
              const float* __restrict__ gw, const float* __restrict__ bw,
              const float* __restrict__ ytok, const float* __restrict__ dwt,
              float* __restrict__ out) {
    extern __shared__ float sff[];             // [64][129]
    __shared__ float sy[32][65], sd[32][65];
    int i = blockIdx.x, b = blockIdx.y, tid = threadIdx.x;
    int warp = tid >> 5, lane = tid & 31;

    // phase 0: per-token LN + gate for 64 tokens of this row
#pragma unroll
    for (int tt = 0; tt < 8; tt++) {
        int tl = warp * 8 + tt;
        size_t tg = ((size_t)b * TOK + i * 64 + tl) * 128;
        float v[4];
        float sum = 0.f;
#pragma unroll
        for (int e = 0; e < 4; e++) {
            size_t c = tg + lane + 32 * e;
            v[e] = T1[c] + X3[c];
            sum += v[e];
        }
#pragma unroll
        for (int o = 16; o; o >>= 1) sum += __shfl_xor_sync(0xffffffffu, sum, o);
        float mean = sum * (1.f / 128.f);
        float vs = 0.f;
#pragma unroll
        for (int e = 0; e < 4; e++) { float d = v[e] - mean; vs += d * d; }
#pragma unroll
        for (int o = 16; o; o >>= 1) vs += __shfl_xor_sync(0xffffffffu, vs, o);
        float inv = rsqrtf(vs * (1.f / 128.f) + 1e-5f);
#pragma unroll
        for (int e = 0; e < 4; e++) {
            int c = lane + 32 * e;
            float nrm = (v[e] - mean) * inv * gw[c] + bw[c];
            sff[tl * 129 + c] = G[tg + c] * nrm;
        }
    }
    __syncthreads();

    float pos_i = (float)(i * 127) / 63.f;
    int y0 = (int)floorf(pos_i);
    int y1 = min(y0 + 1, 127);
    float wy = pos_i - (float)y0;
    for (int cc = 0; cc < 4; cc++) {
        for (int idx = tid; idx < 64 * 32; idx += 256) {
            int j = idx / 32, cl = idx % 32;
            size_t t = (size_t)b * TOK + i * 64 + j;
            sy[cl][j] = ytok[t * 128 + cc * 32 + cl];
            sd[cl][j] = dwt[t * 128 + cc * 32 + cl];
        }
        __syncthreads();
        for (int idx = tid; idx < 32 * 64; idx += 256) {
            int cl = idx / 64, j = idx % 64;
            int c = cc * 32 + cl;
            float pos_j = (float)(j * 127) / 63.f;
            int x0 = (int)floorf(pos_j);
            int x1i = min(x0 + 1, 127);
            float wx = pos_j - (float)x0;
            const float* xb = x + (long long)(b * CH + c) * HH * WW;
            float r0 = xb[y0 * WW + x0] * (1.f - wy) + xb[y1 * WW + x0] * wy;
            float r1 = xb[y0 * WW + x1i] * (1.f - wy) + xb[y1 * WW + x1i] * wy;
            float dv = r0 * (1.f - wx) + r1 * wx;
            long long oi = (((long long)b * CH + c) * HO + i) * WO + j;
            out[oi] = sff[j * 129 + c] * (dv - sd[cl][j]) + sy[cl][j];
        }
        __syncthreads();
    }
}

// ---------------- launch (stream-parallel graph branches) ----------------
extern "C" void kernel_launch(void* const* d_in, const int* in_sizes, int n_in,
                              void* d_out, int out_size) {
    (void)in_sizes; (void)n_in; (void)out_size;
    const float* x       = (const float*)d_in[0];
    const float* conv1_b = (const float*)d_in[2];
    const float* l1_w    = (const float*)d_in[3];
    const float* l1_b    = (const float*)d_in[4];
    const float* ln1_g   = (const float*)d_in[5];
    const float* ln1_b   = (const float*)d_in[6];
    const float* fc1_b   = (const float*)d_in[8];
    const float* div_b   = (const float*)d_in[10];
    const float* fc2_b   = (const float*)d_in[12];
    const float* ln3_g   = (const float*)d_in[13];
    const float* ln3_b   = (const float*)d_in[14];
    const float* fc3a_b  = (const float*)d_in[16];
    const float* fc3b_b  = (const float*)d_in[18];
    const float* lnn_g   = (const float*)d_in[19];
    const float* lnn_b   = (const float*)d_in[20];
    const float* act_b   = (const float*)d_in[22];
    float* out = (float*)d_out;

    float *y, *x1, *t1, *x3, *gate, *dwt, *Sf;
    cudaGetSymbolAddress((void**)&y,    g_y);
    cudaGetSymbolAddress((void**)&x1,   g_x1);
    cudaGetSymbolAddress((void**)&t1,   g_t1);
    cudaGetSymbolAddress((void**)&x3,   g_x3);
    cudaGetSymbolAddress((void**)&gate, g_gate);
    cudaGetSymbolAddress((void**)&dwt,  g_dwt);
    cudaGetSymbolAddress((void**)&Sf,   g_Sf);

    bf16 *yLh, *yLl, *hlhh, *hlhl, *yh, *yl, *Sh, *Sl, *yTh, *yTl;
    bf16 *attnh, *attnl, *t0h, *t0l, *t0bh, *t0bl, *x2h, *x2l, *x2bh, *x2bl;
    bf16 *Wh, *Wl, *Wch, *Wcl, *xth, *xtl;
    cudaGetSymbolAddress((void**)&yLh,   syL_h);
    cudaGetSymbolAddress((void**)&yLl,   syL_l);
    cudaGetSymbolAddress((void**)&hlhh,  shlh_h);
    cudaGetSymbolAddress((void**)&hlhl,  shlh_l);
    cudaGetSymbolAddress((void**)&yh,    sy_h);
    cudaGetSymbolAddress((void**)&yl,    sy_l);
    cudaGetSymbolAddress((void**)&Sh,    sS_h);
    cudaGetSymbolAddress((void**)&Sl,    sS_l);
    cudaGetSymbolAddress((void**)&yTh,   syT_h);
    cudaGetSymbolAddress((void**)&yTl,   syT_l);
    cudaGetSymbolAddress((void**)&attnh, sattn_h);
    cudaGetSymbolAddress((void**)&attnl, sattn_l);
    cudaGetSymbolAddress((void**)&t0h,   st0_h);
    cudaGetSymbolAddress((void**)&t0l,   st0_l);
    cudaGetSymbolAddress((void**)&t0bh,  st0b_h);
    cudaGetSymbolAddress((void**)&t0bl,  st0b_l);
    cudaGetSymbolAddress((void**)&x2h,   sx2_h);
    cudaGetSymbolAddress((void**)&x2l,   sx2_l);
    cudaGetSymbolAddress((void**)&x2bh,  sx2b_h);
    cudaGetSymbolAddress((void**)&x2bl,  sx2b_l);
    cudaGetSymbolAddress((void**)&Wh,    sW_h);
    cudaGetSymbolAddress((void**)&Wl,    sW_l);
    cudaGetSymbolAddress((void**)&Wch,   sWc_h);
    cudaGetSymbolAddress((void**)&Wcl,   sWc_l);
    cudaGetSymbolAddress((void**)&xth,   sxt_h);
    cudaGetSymbolAddress((void**)&xtl,   sxt_l);

    cudaFuncSetAttribute(bgemm_k<0,3>, cudaFuncAttributeMaxDynamicSharedMemorySize, BGE_SMEM);
    cudaFuncSetAttribute(bgemm_k<0,1>, cudaFuncAttributeMaxDynamicSharedMemorySize, BGE_SMEM);
    cudaFuncSetAttribute(bgemm_k<0,2>, cudaFuncAttributeMaxDynamicSharedMemorySize, BGE_SMEM);
    cudaFuncSetAttribute(bgemm_k<1,1>, cudaFuncAttributeMaxDynamicSharedMemorySize, BGE_SMEM);
    cudaFuncSetAttribute(bgemm_k<1,2>, cudaFuncAttributeMaxDynamicSharedMemorySize, BGE_SMEM);
    cudaFuncSetAttribute(bgemm_k<3,2>, cudaFuncAttributeMaxDynamicSharedMemorySize, BGE_SMEM);
    cudaFuncSetAttribute(bgemm_k<2,1>, cudaFuncAttributeMaxDynamicSharedMemorySize, BGE_SMEM);
    cudaFuncSetAttribute(cgemm_k, cudaFuncAttributeMaxDynamicSharedMemorySize, BGE_SMEM);
    cudaFuncSetAttribute(softmax2_k, cudaFuncAttributeMaxDynamicSharedMemorySize, SMX_SMEM);
    cudaFuncSetAttribute(final2_k, cudaFuncAttributeMaxDynamicSharedMemorySize, FIN_SMEM);

    // streams/events created once (first call = uncaptured correctness run)
    static cudaStream_t sConv = nullptr, sB = nullptr, sC = nullptr;
    static cudaEvent_t eFork = nullptr, eConvDone = nullptr, eAttn = nullptr,
                       eBDone = nullptr, eCDone = nullptr;
    if (!sConv) {
        cudaStreamCreateWithFlags(&sConv, cudaStreamNonBlocking);
        cudaStreamCreateWithFlags(&sB, cudaStreamNonBlocking);
        cudaStreamCreateWithFlags(&sC, cudaStreamNonBlocking);
        cudaEventCreateWithFlags(&eFork, cudaEventDisableTiming);
        cudaEventCreateWithFlags(&eConvDone, cudaEventDisableTiming);
        cudaEventCreateWithFlags(&eAttn, cudaEventDisableTiming);
        cudaEventCreateWithFlags(&eBDone, cudaEventDisableTiming);
        cudaEventCreateWithFlags(&eCDone, cudaEventDisableTiming);
    }

    const float* w0 = (const float*)d_in[1];
    const float* w1 = (const float*)d_in[7];
    const float* w2 = (const float*)d_in[9];
    const float* w3 = (const float*)d_in[11];
    const float* w4 = (const float*)d_in[15];
    const float* w5 = (const float*)d_in[17];
    const float* w6 = (const float*)d_in[21];

    // ---- fork conv branch ----
    cudaEventRecord(eFork, 0);
    cudaStreamWaitEvent(sConv, eFork, 0);
    nhwc_k<<<dim3(128, 16), 256, 0, sConv>>>(x, xth, xtl);
    wconv_k<<<1024, 256, 0, sConv>>>(l1_w, Wch, Wcl);
    cgemm_k<<<dim3(1, 32, 16), 256, BGE_SMEM, sConv>>>(xth, xtl, Wch, Wcl, l1_b, dwt);
    cudaEventRecord(eConvDone, sConv);

    // ---- main attention chain ----
    wsplit_k<<<512, 256>>>(w0, w1, w2, w3, w4, w5, w6, Wh, Wl);
    haar_k<<<dim3(64, 16), 256>>>(x, yLh, yLl, yTh, yTl, hlhh, hlhl);

    bgemm_k<0,3><<<dim3(1, 512, 1), 256, BGE_SMEM>>>(
        hlhh, hlhl, 0, 256, Wh, Wl, 0, 256,
        y, yh, yl, 0, 128, 256, 1.f, conv1_b, nullptr);

    // S = scale * Q @ K^T  (fp32 out)
    bgemm_k<0,1><<<dim3(4, 4, NG), 256, BGE_SMEM>>>(
        yLh, yLl, (long long)QL * 128, 128, yh, yl, (long long)QL * 128, 128,
        Sf, nullptr, nullptr, (long long)QL * QL, QL, 128, 0.35355339059327373f, nullptr, nullptr);

    softmax2_k<<<dim3(16, NG), 256, SMX_SMEM>>>(Sf, Sh, Sl);

    bgemm_k<0,2><<<dim3(1, 4, NG), 256, BGE_SMEM>>>(
        Sh, Sl, (long long)QL * QL, QL, yTh, yTl, (long long)128 * 512, 512,
        nullptr, attnh, attnl, (long long)QL * 128, 128, 512, 1.f, nullptr, nullptr);
    cudaEventRecord(eAttn, 0);

    // ---- FFN side chain B: ln3 -> fc3a -> fc3b ----
    cudaStreamWaitEvent(sB, eAttn, 0);
    ln_k<<<8192, 256, 0, sB>>>(attnh, attnl, t0bh, t0bl, ln3_g, ln3_b);
    bgemm_k<1,2><<<dim3(1, 512), 256, BGE_SMEM, sB>>>(
        t0bh, t0bl, 0, 128, Wh + 81920, Wl + 81920, 0, 128,
        nullptr, x2bh, x2bl, 0, 128, 128, 1.f, fc3a_b, nullptr);
    bgemm_k<0,1><<<dim3(1, 512), 256, BGE_SMEM, sB>>>(
        x2bh, x2bl, 0, 128, Wh + 98304, Wl + 98304, 0, 128,
        x3, nullptr, nullptr, 0, 128, 128, 1.f, fc3b_b, nullptr);
    cudaEventRecord(eBDone, sB);

    // ---- FFN side chain C: gate ----
    cudaStreamWaitEvent(sC, eAttn, 0);
    bgemm_k<2,1><<<dim3(1, 512), 256, BGE_SMEM, sC>>>(
        attnh, attnl, 0, 128, Wh + 114688, Wl + 114688, 0, 128,
        gate, nullptr, nullptr, 0, 128, 128, 1.f, act_b, nullptr);
    cudaEventRecord(eCDone, sC);

    // ---- FFN main chain: ln1 -> fc1 -> div -> fc2 ----
    ln_k<<<8192, 256>>>(attnh, attnl, t0h, t0l, ln1_g, ln1_b);
    bgemm_k<1,1><<<dim3(1, 512), 256, BGE_SMEM>>>(
        t0h, t0l, 0, 128, Wh + 32768, Wl + 32768, 0, 128,
        x1, nullptr, nullptr, 0, 128, 128, 1.f, fc1_b, nullptr);
    bgemm_k<3,2><<<dim3(1, 512), 256, BGE_SMEM>>>(
        attnh, attnl, 0, 128, Wh + 49152, Wl + 49152, 0, 128,
        nullptr, x2h, x2l, 0, 128, 128, 1.f, div_b, x1);
    bgemm_k<1,1><<<dim3(1, 512), 256, BGE_SMEM>>>(
        x2h, x2l, 0, 128, Wh + 65536, Wl + 65536, 0, 128,
        t1, nullptr, nullptr, 0, 128, 128, 1.f, fc2_b, nullptr);

    // ---- join: fused LN-gate + final combine ----
    cudaStreamWaitEvent(0, eBDone, 0);
    cudaStreamWaitEvent(0, eCDone, 0);
    cudaStreamWaitEvent(0, eConvDone, 0);
    final2_k<<<dim3(64, 16), 256, FIN_SMEM>>>(x, t1, x3, gate, lnn_g, lnn_b, y, dwt, out);
}

// round 15
// speedup vs baseline: 2.9519x; 1.0522x over previous
#include <cuda_runtime.h>
#include <cuda_bf16.h>
#include <math.h>
#include <stdint.h>

// ---------------- problem constants ----------------
#define BB   16
#define CH   128
#define HH   128
#define WW   128
#define HO   64
#define WO   64
#define TOK  4096
#define NT   65536
#define NG   128
#define QL   512
#define HB   8          // batches per half
#define HT   (HB*TOK)   // tokens per half
#define HG   (HB*8)     // groups per half

typedef unsigned long long ull;
typedef __nv_bfloat16 bf16;

// ---------------- fp32 scratch ----------------
__device__ __align__(256) float g_y  [(size_t)NT * 128];
__device__ __align__(256) float g_x1 [(size_t)NT * 128];
__device__ __align__(256) float g_t1 [(size_t)NT * 128];
__device__ __align__(256) float g_x3 [(size_t)NT * 128];
__device__ __align__(256) float g_gate[(size_t)NT * 128];
__device__ __align__(256) float g_dwt[(size_t)NT * 128];
__device__ __align__(256) float g_Sf [(size_t)NG * QL * QL];

// ---------------- split bf16 scratch ----------------
__device__ __align__(256) bf16 syL_h [(size_t)NT * 128];
__device__ __align__(256) bf16 syL_l [(size_t)NT * 128];
__device__ __align__(256) bf16 shlh_h[(size_t)NT * 256];
__device__ __align__(256) bf16 shlh_l[(size_t)NT * 256];
__device__ __align__(256) bf16 sy_h  [(size_t)NT * 128];
__device__ __align__(256) bf16 sy_l  [(size_t)NT * 128];
__device__ __align__(256) bf16 sS_h  [(size_t)NG * QL * QL];
__device__ __align__(256) bf16 sS_l  [(size_t)NG * QL * QL];
__device__ __align__(256) bf16 syT_h [(size_t)NG * 128 * 512];
__device__ __align__(256) bf16 syT_l [(size_t)NG * 128 * 512];
__device__ __align__(256) bf16 sattn_h[(size_t)NT * 128];
__device__ __align__(256) bf16 sattn_l[(size_t)NT * 128];
__device__ __align__(256) bf16 st0_h [(size_t)NT * 128];
__device__ __align__(256) bf16 st0_l [(size_t)NT * 128];
__device__ __align__(256) bf16 st0b_h[(size_t)NT * 128];
__device__ __align__(256) bf16 st0b_l[(size_t)NT * 128];
__device__ __align__(256) bf16 sx2_h [(size_t)NT * 128];
__device__ __align__(256) bf16 sx2_l [(size_t)NT * 128];
__device__ __align__(256) bf16 sx2b_h[(size_t)NT * 128];
__device__ __align__(256) bf16 sx2b_l[(size_t)NT * 128];
__device__ __align__(256) bf16 sW_h  [131072];
__device__ __align__(256) bf16 sW_l  [131072];
__device__ __align__(256) bf16 sWc_h [262144];
__device__ __align__(256) bf16 sWc_l [262144];
__device__ __align__(256) bf16 sxt_h [(size_t)BB * HH * WW * CH];
__device__ __align__(256) bf16 sxt_l [(size_t)BB * HH * WW * CH];

__device__ __forceinline__ float gelu_f(float v) {
    return 0.5f * v * (1.0f + erff(v * 0.70710678118654752f));
}
__device__ __forceinline__ uint32_t smem_u32(const void* p) {
    uint32_t a;
    asm("{ .reg .u64 t; cvta.to.shared.u64 t, %1; cvt.u32.u64 %0, t; }" : "=r"(a) : "l"(p));
    return a;
}
#define SW128(o) ((o) ^ (((o) >> 3) & 0x70))

__device__ __forceinline__ void st_split(bf16* H, bf16* L, size_t off, float v) {
    bf16 h = __float2bfloat16(v);
    H[off] = h;
    L[off] = __float2bfloat16(v - __bfloat162float(h));
}

__device__ __forceinline__ void ldm_x4(uint32_t* r, uint32_t addr) {
    asm volatile("ldmatrix.sync.aligned.m8n8.x4.shared.b16 {%0,%1,%2,%3}, [%4];"
                 : "=r"(r[0]), "=r"(r[1]), "=r"(r[2]), "=r"(r[3]) : "r"(addr));
}
__device__ __forceinline__ void ldm_x2(uint32_t* r, uint32_t addr) {
    asm volatile("ldmatrix.sync.aligned.m8n8.x2.shared.b16 {%0,%1}, [%2];"
                 : "=r"(r[0]), "=r"(r[1]) : "r"(addr));
}
__device__ __forceinline__ void mma_bf16(float* d, const uint32_t* a, const uint32_t* b) {
    asm volatile("mma.sync.aligned.m16n8k16.row.col.f32.bf16.bf16.f32 "
                 "{%0,%1,%2,%3}, {%4,%5,%6,%7}, {%8,%9}, {%0,%1,%2,%3};"
                 : "+f"(d[0]), "+f"(d[1]), "+f"(d[2]), "+f"(d[3])
                 : "r"(a[0]), "r"(a[1]), "r"(a[2]), "r"(a[3]), "r"(b[0]), "r"(b[1]));
}
__device__ __forceinline__ void cp16(uint32_t dst, const void* src) {
    asm volatile("cp.async.cg.shared.global [%0], [%1], 16;" :: "r"(dst), "l"(src));
}
__device__ __forceinline__ void cp16z(uint32_t dst, const void* src, int sz) {
    asm volatile("cp.async.cg.shared.global [%0], [%1], 16, %2;" :: "r"(dst), "l"(src), "r"(sz));
}

// ---------------- weight splits ----------------
__global__ void wsplit_k(const float* __restrict__ conv1_w, const float* __restrict__ fc1_w,
                         const float* __restrict__ div_w, const float* __restrict__ fc2_w,
                         const float* __restrict__ fc3a_w, const float* __restrict__ fc3b_w,
                         const float* __restrict__ act_w,
                         bf16* __restrict__ WH, bf16* __restrict__ WL) {
    int i = blockIdx.x * 256 + threadIdx.x;
    float v;
    if      (i <  32768) v = conv1_w[i];
    else if (i <  49152) v = fc1_w [i - 32768];
    else if (i <  65536) v = div_w [i - 49152];
    else if (i <  81920) v = fc2_w [i - 65536];
    else if (i <  98304) v = fc3a_w[i - 81920];
    else if (i < 114688) v = fc3b_w[i - 98304];
    else                 v = act_w [i - 114688];
    bf16 h = __float2bfloat16(v);
    WH[i] = h;
    WL[i] = __float2bfloat16(v - __bfloat162float(h));
}

__global__ void wconv_k(const float* __restrict__ l1_w,
                        bf16* __restrict__ WH, bf16* __restrict__ WL) {
    int i = blockIdx.x * 256 + threadIdx.x;
    int oc = i >> 11;
    int k = i & 2047;
    int tap = k >> 7, ic = k & 127;
    float v = l1_w[oc * 2048 + ic * 16 + tap];
    bf16 h = __float2bfloat16(v);
    WH[i] = h;
    WL[i] = __float2bfloat16(v - __bfloat162float(h));
}

// ---------------- x NCHW -> NHWC split (per half) ----------------
__global__ void nhwc_k(const float* __restrict__ x,
                       bf16* __restrict__ xh, bf16* __restrict__ xl, int b_off) {
    __shared__ float tile[32][129];
    int h = blockIdx.x, b = blockIdx.y + b_off, tid = threadIdx.x;
    for (int cc = 0; cc < 4; cc++) {
        for (int idx = tid; idx < 32 * 128; idx += 256) {
            int cl = idx >> 7, w = idx & 127;
            tile[cl][w] = x[(((size_t)b * CH + cc * 32 + cl) * HH + h) * WW + w];
        }
        __syncthreads();
        for (int idx = tid; idx < 128 * 32; idx += 256) {
            int w = idx >> 5, cl = idx & 31;
            size_t o = (((size_t)b * HH + h) * WW + w) * CH + cc * 32 + cl;
            st_split(xh, xl, o, tile[cl][w]);
        }
        __syncthreads();
    }
}

// ---------------- Haar DWT -> split token layouts (per half) ----------------
__global__ void haar_k(const float* __restrict__ x,
                       bf16* __restrict__ yLh, bf16* __restrict__ yLl,
                       bf16* __restrict__ yTh, bf16* __restrict__ yTl,
                       bf16* __restrict__ hlhh, bf16* __restrict__ hlhl, int b_off) {
    __shared__ float sLL[32][65], sHL[32][65], sLH[32][65], sHH[32][65];
    int i = blockIdx.x, b = blockIdx.y + b_off, tid = threadIdx.x;
    for (int cc = 0; cc < 4; cc++) {
        for (int idx = tid; idx < 32 * 64; idx += 256) {
            int cl = idx / 64, j = idx % 64;
            int c = cc * 32 + cl;
            const float* base = x + (((long long)(b * CH + c) * HH + 2 * i) * WW) + 2 * j;
            float a = base[0], bb2 = base[1], cv = base[WW], d = base[WW + 1];
            sLL[cl][j] = (a + bb2 + cv + d) * 0.5f;
            sHL[cl][j] = (a - bb2 + cv - d) * 0.5f;
            sLH[cl][j] = (a + bb2 - cv - d) * 0.5f;
            sHH[cl][j] = (a - bb2 - cv + d) * 0.5f;
        }
        __syncthreads();
        for (int idx = tid; idx < 64 * 32; idx += 256) {
            int j = idx / 32, cl = idx % 32;
            size_t t = (size_t)b * TOK + i * 64 + j;
            int c = cc * 32 + cl;
            st_split(yLh, yLl, t * 128 + c, sLL[cl][j]);
            st_split(hlhh, hlhl, t * 256 + c, sHL[cl][j]);
            st_split(hlhh, hlhl, t * 256 + 128 + c, sLH[cl][j]);
        }
        {
            int g = b * 8 + (i >> 3);
            int qoff = (i & 7) * 64;
            for (int idx = tid; idx < 32 * 64; idx += 256) {
                int cl = idx / 64, j = idx % 64;
                int c = cc * 32 + cl;
                st_split(yTh, yTl, ((size_t)g * 128 + c) * 512 + qoff + j, sHH[cl][j]);
            }
        }
        __syncthreads();
    }
}

// ---------------- split-bf16 cp.async pipelined GEMM ----------------
#define BGE_SMEM 131072

__device__ __forceinline__ void issue_chunk(
    const bf16* __restrict__ Ahi, const bf16* __restrict__ Alo, int lda,
    const bf16* __restrict__ Bhi, const bf16* __restrict__ Blo, int ldb,
    int k0, uint32_t base, int t) {
#pragma unroll
    for (int q = 0; q < 4; q++) {
        int idx = q * 256 + t;
        int row = idx >> 3, gg = idx & 7;
        uint32_t sw = SW128((uint32_t)(row * 128 + gg * 16));
        cp16(base + sw,         Ahi + (long long)row * lda + k0 + gg * 8);
        cp16(base + 16384 + sw, Alo + (long long)row * lda + k0 + gg * 8);
        cp16(base + 32768 + sw, Bhi + (long long)row * ldb + k0 + gg * 8);
        cp16(base + 49152 + sw, Blo + (long long)row * ldb + k0 + gg * 8);
    }
}

template <int EPI, int OMODE>
__global__ __launch_bounds__(256)
void bgemm_k(const bf16* __restrict__ Ahi, const bf16* __restrict__ Alo, long long sAg, int lda,
             const bf16* __restrict__ Bhi, const bf16* __restrict__ Blo, long long sBg, int ldb,
             float* __restrict__ Cf, bf16* __restrict__ Chi, bf16* __restrict__ Clo,
             long long sCg, int ldc, int K, float alpha,
             const float* __restrict__ bias, const float* __restrict__ extra) {
    extern __shared__ char smem[];
    uint32_t sb = smem_u32(smem);
    int t = threadIdx.x;
    int wid = t >> 5, lane = t & 31;
    int n0 = blockIdx.x * 128;
    int m0 = blockIdx.y * 128;
    int g = blockIdx.z;
    Ahi += (long long)g * sAg + (long long)m0 * lda;
    Alo += (long long)g * sAg + (long long)m0 * lda;
    Bhi += (long long)g * sBg + (long long)n0 * ldb;
    Blo += (long long)g * sBg + (long long)n0 * ldb;
    long long co = (long long)g * sCg;

    int wm = wid >> 2;
    int wn = wid & 3;

    float acc[4][4][4];
#pragma unroll
    for (int mi = 0; mi < 4; mi++)
#pragma unroll
        for (int ni = 0; ni < 4; ni++)
#pragma unroll
            for (int e = 0; e < 4; e++) acc[mi][ni][e] = 0.f;

    int a_row_l = lane & 15;
    int a_k8    = (lane >> 4) << 3;
    int b_row_l = lane & 7;
    int b_k8    = ((lane >> 3) & 1) << 3;

    int nchunks = K >> 6;
    issue_chunk(Ahi, Alo, lda, Bhi, Blo, ldb, 0, sb, t);
    asm volatile("cp.async.commit_group;" ::: "memory");

    for (int ch = 0; ch < nchunks; ch++) {
        if (ch + 1 < nchunks) {
            issue_chunk(Ahi, Alo, lda, Bhi, Blo, ldb, (ch + 1) * 64,
                        sb + ((ch + 1) & 1) * 65536, t);
            asm volatile("cp.async.commit_group;" ::: "memory");
            asm volatile("cp.async.wait_group 1;" ::: "memory");
        } else {
            asm volatile("cp.async.wait_group 0;" ::: "memory");
        }
        __syncthreads();
        uint32_t base = sb + (ch & 1) * 65536;
        uint32_t aHiA = base, aLoA = base + 16384, bHiA = base + 32768, bLoA = base + 49152;
#pragma unroll
        for (int ks = 0; ks < 4; ks++) {
            uint32_t Bh[4][2], Bl[4][2];
#pragma unroll
            for (int ni = 0; ni < 4; ni++) {
                uint32_t byte = (uint32_t)((wn * 32 + ni * 8 + b_row_l) * 128 +
                                           (ks * 16 + b_k8) * 2);
                uint32_t sw = SW128(byte);
                ldm_x2(Bh[ni], bHiA + sw);
                ldm_x2(Bl[ni], bLoA + sw);
            }
#pragma unroll
            for (int mi = 0; mi < 4; mi++) {
                uint32_t Ah[4], Al[4];
                uint32_t byte = (uint32_t)((wm * 64 + mi * 16 + a_row_l) * 128 +
                                           (ks * 16 + a_k8) * 2);
                uint32_t sw = SW128(byte);
                ldm_x4(Ah, aHiA + sw);
                ldm_x4(Al, aLoA + sw);
#pragma unroll
                for (int ni = 0; ni < 4; ni++) {
                    mma_bf16(acc[mi][ni], Ah, Bh[ni]);
                    mma_bf16(acc[mi][ni], Ah, Bl[ni]);
                    mma_bf16(acc[mi][ni], Al, Bh[ni]);
                }
            }
        }
        __syncthreads();
    }

    int rbase = m0 + wm * 64 + (lane >> 2);
    int cbase = n0 + wn * 32 + (lane & 3) * 2;
#pragma unroll
    for (int mi = 0; mi < 4; mi++) {
#pragma unroll
        for (int h = 0; h < 2; h++) {
            int m = rbase + mi * 16 + h * 8;
            long long rowoff = co + (long long)m * ldc;
#pragma unroll
            for (int ni = 0; ni < 4; ni++) {
                int c = cbase + ni * 8;
                float v0 = acc[mi][ni][2 * h]     * alpha;
                float v1 = acc[mi][ni][2 * h + 1] * alpha;
                if (bias) { v0 += bias[c]; v1 += bias[c + 1]; }
                if (EPI == 1 || EPI == 3) { v0 = gelu_f(v0); v1 = gelu_f(v1); }
                if (EPI == 2) {
                    v0 = 1.f / (1.f + expf(-v0));
                    v1 = 1.f / (1.f + expf(-v1));
                }
                if (EPI == 3) {
                    float2 ev = *reinterpret_cast<const float2*>(&extra[rowoff + c]);
                    v0 -= ev.x; v1 -= ev.y;
                }
                if (OMODE & 1) {
                    float2 o; o.x = v0; o.y = v1;
                    *reinterpret_cast<float2*>(&Cf[rowoff + c]) = o;
                }
                if (OMODE & 2) {
                    bf16 h0 = __float2bfloat16(v0), h1 = __float2bfloat16(v1);
                    __nv_bfloat162 hp, lp;
                    hp.x = h0; hp.y = h1;
                    lp.x = __float2bfloat16(v0 - __bfloat162float(h0));
                    lp.y = __float2bfloat16(v1 - __bfloat162float(h1));
                    *reinterpret_cast<__nv_bfloat162*>(&Chi[rowoff + c]) = hp;
                    *reinterpret_cast<__nv_bfloat162*>(&Clo[rowoff + c]) = lp;
                }
            }
        }
    }
}

// ---------------- conv 4x4 s2 p1 as implicit GEMM (per half) ----------------
__device__ __forceinline__ void issue_conv_chunk(
    const bf16* __restrict__ xh, const bf16* __restrict__ xl,
    const bf16* __restrict__ wh, const bf16* __restrict__ wl,
    int b, const int* iq, const int* jq, int ch, uint32_t base, int t) {
    int tap = ch >> 1;
    int icH = (ch & 1) * 64;
    int r = tap >> 2, s = tap & 3;
#pragma unroll
    for (int q = 0; q < 4; q++) {
        int idx = q * 256 + t;
        int row = idx >> 3, gg = idx & 7;
        uint32_t sw = SW128((uint32_t)(row * 128 + gg * 16));
        int yy = 2 * iq[q] - 1 + r;
        int xx = 2 * jq[q] - 1 + s;
        bool ok = ((unsigned)yy < 128u) && ((unsigned)xx < 128u);
        int yyc = ok ? yy : 0, xxc = ok ? xx : 0;
        size_t off = ((((size_t)b * HH + yyc) * WW + xxc) * CH) + icH + gg * 8;
        int sz = ok ? 16 : 0;
        cp16z(base + sw,         xh + off, sz);
        cp16z(base + 16384 + sw, xl + off, sz);
        size_t woff = (size_t)row * 2048 + ch * 64 + gg * 8;
        cp16(base + 32768 + sw, wh + woff);
        cp16(base + 49152 + sw, wl + woff);
    }
}

__global__ __launch_bounds__(256)
void cgemm_k(const bf16* __restrict__ xh, const bf16* __restrict__ xl,
             const bf16* __restrict__ wh, const bf16* __restrict__ wl,
             const float* __restrict__ bias, float* __restrict__ dwt, int b_off) {
    extern __shared__ char smem[];
    uint32_t sb = smem_u32(smem);
    int t = threadIdx.x;
    int wid = t >> 5, lane = t & 31;
    int my = blockIdx.y;
    int b = blockIdx.z + b_off;
    int wm = wid >> 2;
    int wn = wid & 3;

    int iq[4], jq[4];
#pragma unroll
    for (int q = 0; q < 4; q++) {
        int idx = q * 256 + t;
        int m = my * 128 + (idx >> 3);
        iq[q] = m >> 6;
        jq[q] = m & 63;
    }

    float acc[4][4][4];
#pragma unroll
    for (int mi = 0; mi < 4; mi++)
#pragma unroll
        for (int ni = 0; ni < 4; ni++)
#pragma unroll
            for (int e = 0; e < 4; e++) acc[mi][ni][e] = 0.f;

    int a_row_l = lane & 15;
    int a_k8    = (lane >> 4) << 3;
    int b_row_l = lane & 7;
    int b_k8    = ((lane >> 3) & 1) << 3;

    issue_conv_chunk(xh, xl, wh, wl, b, iq, jq, 0, sb, t);
    asm volatile("cp.async.commit_group;" ::: "memory");

    for (int ch = 0; ch < 32; ch++) {
        if (ch + 1 < 32) {
            issue_conv_chunk(xh, xl, wh, wl, b, iq, jq, ch + 1,
                             sb + ((ch + 1) & 1) * 65536, t);
            asm volatile("cp.async.commit_group;" ::: "memory");
            asm volatile("cp.async.wait_group 1;" ::: "memory");
        } else {
            asm volatile("cp.async.wait_group 0;" ::: "memory");
        }
        __syncthreads();
        uint32_t base = sb + (ch & 1) * 65536;
        uint32_t aHiA = base, aLoA = base + 16384, bHiA = base + 32768, bLoA = base + 49152;
#pragma unroll
        for (int ks = 0; ks < 4; ks++) {
            uint32_t Bh[4][2], Bl[4][2];
#pragma unroll
            for (int ni = 0; ni < 4; ni++) {
                uint32_t byte = (uint32_t)((wn * 32 + ni * 8 + b_row_l) * 128 +
                                           (ks * 16 + b_k8) * 2);
                uint32_t sw = SW128(byte);
                ldm_x2(Bh[ni], bHiA + sw);
                ldm_x2(Bl[ni], bLoA + sw);
            }
#pragma unroll
            for (int mi = 0; mi < 4; mi++) {
                uint32_t Ah[4], Al[4];
                uint32_t byte = (uint32_t)((wm * 64 + mi * 16 + a_row_l) * 128 +
                                           (ks * 16 + a_k8) * 2);
                uint32_t sw = SW128(byte);
                ldm_x4(Ah, aHiA + sw);
                ldm_x4(Al, aLoA + sw);
#pragma unroll
                for (int ni = 0; ni < 4; ni++) {
                    mma_bf16(acc[mi][ni], Ah, Bh[ni]);
                    mma_bf16(acc[mi][ni], Ah, Bl[ni]);
                    mma_bf16(acc[mi][ni], Al, Bh[ni]);
                }
            }
        }
        __syncthreads();
    }

    int rbase = my * 128 + wm * 64 + (lane >> 2);
    int cbase = wn * 32 + (lane & 3) * 2;
#pragma unroll
    for (int mi = 0; mi < 4; mi++) {
#pragma unroll
        for (int h = 0; h < 2; h++) {
            int m = rbase + mi * 16 + h * 8;
            size_t rowoff = ((size_t)b * TOK + m) * 128;
#pragma unroll
            for (int ni = 0; ni < 4; ni++) {
                int c = cbase + ni * 8;
                float v0 = acc[mi][ni][2 * h]     + bias[c];
                float v1 = acc[mi][ni][2 * h + 1] + bias[c + 1];
                float2 o;
                o.x = fmaxf(v0, 0.f);
                o.y = fmaxf(v1, 0.f);
                *reinterpret_cast<float2*>(&dwt[rowoff + c]) = o;
            }
        }
    }
}

// ---------------- smem-resident column softmax over q ----------------
#define SMX_SMEM 65536
__global__ __launch_bounds__(256)
void softmax2_k(const float* __restrict__ Sf, bf16* __restrict__ Sh, bf16* __restrict__ Sl) {
    extern __shared__ float tile[];
    __shared__ float red[8][32];
    int g = blockIdx.y;
    int k0 = blockIdx.x * 32;
    int t = threadIdx.x;
    int kc = t & 31, qh = t >> 5;
    const float* Sg = Sf + (size_t)g * QL * QL + k0 + kc;
    for (int q = qh; q < QL; q += 8)
        tile[q * 32 + kc] = Sg[(size_t)q * QL];
    __syncthreads();
    float m = -INFINITY;
    for (int q = qh; q < QL; q += 8) m = fmaxf(m, tile[q * 32 + kc]);
    red[qh][kc] = m;
    __syncthreads();
    if (t < 32) {
        float M = red[0][kc];
#pragma unroll
        for (int r = 1; r < 8; r++) M = fmaxf(M, red[r][kc]);
        red[0][kc] = M;
    }
    __syncthreads();
    float M = red[0][kc];
    __syncthreads();
    float s = 0.f;
    for (int q = qh; q < QL; q += 8) {
        float e = expf(tile[q * 32 + kc] - M);
        tile[q * 32 + kc] = e;
        s += e;
    }
    red[qh][kc] = s;
    __syncthreads();
    if (t < 32) {
        float S = 0.f;
#pragma unroll
        for (int r = 0; r < 8; r++) S += red[r][kc];
        red[0][kc] = 1.f / S;
    }
    __syncthreads();
    float inv = red[0][kc];
    size_t obase = (size_t)g * QL * QL + k0 + kc;
    for (int q = qh; q < QL; q += 8) {
        float p = tile[q * 32 + kc] * inv;
        bf16 h = __float2bfloat16(p);
        Sh[obase + (size_t)q * QL] = h;
        Sl[obase + (size_t)q * QL] = __float2bfloat16(p - __bfloat162float(h));
    }
}

// ---------------- per-token layernorm (split in/out) ----------------
__global__ void ln_k(const bf16* __restrict__ Xh, const bf16* __restrict__ Xl,
                     bf16* __restrict__ Yh, bf16* __restrict__ Yl,
                     const float* __restrict__ gw, const float* __restrict__ bw) {
    int warp = threadIdx.x / 32, lane = threadIdx.x % 32;
    size_t t = (size_t)blockIdx.x * 8 + warp;
    float v[4];
    float sum = 0.f;
#pragma unroll
    for (int i = 0; i < 4; i++) {
        size_t off = t * 128 + lane + 32 * i;
        v[i] = __bfloat162float(Xh[off]) + __bfloat162float(Xl[off]);
        sum += v[i];
    }
#pragma unroll
    for (int o = 16; o; o >>= 1) sum += __shfl_xor_sync(0xffffffffu, sum, o);
    float mean = sum * (1.f / 128.f);
    float vs = 0.f;
#pragma unroll
    for (int i = 0; i < 4; i++) { float d = v[i] - mean; vs += d * d; }
#pragma unroll
    for (int o = 16; o; o >>= 1) vs += __shfl_xor_sync(0xffffffffu, vs, o);
    float inv = rsqrtf(vs * (1.f / 128.f) + 1e-5f);
#pragma unroll
    for (int i = 0; i < 4; i++) {
        int c = lane + 32 * i;
        float r = (v[i] - mean) * inv * gw[c] + bw[c];
        st_split(Yh, Yl, t * 128 + c, r);
    }
}

// ---------------- fused: ffn=gate*LN(t1+x3) + final combine (per half) ----------------
#define FIN_SMEM (64 * 129 * 4)
__global__ __launch_bounds__(256)
void final2_k(const float* __restrict__ x,
              const float* __restrict__ T1, const float* __restrict__ X3,
              const float* __restrict__ G,
              const float* __restrict__ gw, const float* __restrict__ bw,
              const float* __restrict__ ytok, const float* __restrict__ dwt,
              float* __restrict__ out, int b_off) {
    extern __shared__ float sff[];
    __shared__ float sy[32][65], sd[32][65];
    int i = blockIdx.x, b = blockIdx.y + b_off, tid = threadIdx.x;
    int warp = tid >> 5, lane = tid & 31;

#pragma unroll
    for (int tt = 0; tt < 8; tt++) {
        int tl = warp * 8 + tt;
        size_t tg = ((size_t)b * TOK + i * 64 + tl) * 128;
        float v[4];
        float sum = 0.f;
#pragma unroll
        for (int e = 0; e < 4; e++) {
            size_t c = tg + lane + 32 * e;
            v[e] = T1[c] + X3[c];
            sum += v[e];
        }
#pragma unroll
        for (int o = 16; o; o >>= 1) sum += __shfl_xor_sync(0xffffffffu, sum, o);
        float mean = sum * (1.f / 128.f);
        float vs = 0.f;
#pragma unroll
        for (int e = 0; e < 4; e++) { float d = v[e] - mean; vs += d * d; }
#pragma unroll
        for (int o = 16; o; o >>= 1) vs += __shfl_xor_sync(0xffffffffu, vs, o);
        float inv = rsqrtf(vs * (1.f / 128.f) + 1e-5f);
#pragma unroll
        for (int e = 0; e < 4; e++) {
            int c = lane + 32 * e;
            float nrm = (v[e] - mean) * inv * gw[c] + bw[c];
            sff[tl * 129 + c] = G[tg + c] * nrm;
        }
    }
    __syncthreads();

    float pos_i = (float)(i * 127) / 63.f;
    int y0 = (int)floorf(pos_i);
    int y1 = min(y0 + 1, 127);
    float wy = pos_i - (float)y0;
    for (int cc = 0; cc < 4; cc++) {
        for (int idx = tid; idx < 64 * 32; idx += 256) {
            int j = idx / 32, cl = idx % 32;
            size_t t = (size_t)b * TOK + i * 64 + j;
            sy[cl][j] = ytok[t * 128 + cc * 32 + cl];
            sd[cl][j] = dwt[t * 128 + cc * 32 + cl];
        }
        __syncthreads();
        for (int idx = tid; idx < 32 * 64; idx += 256) {
            int cl = idx / 64, j = idx % 64;
            int c = cc * 32 + cl;
            float pos_j = (float)(j * 127) / 63.f;
            int x0 = (int)floorf(pos_j);
            int x1i = min(x0 + 1, 127);
            float wx = pos_j - (float)x0;
            const float* xb = x + (long long)(b * CH + c) * HH * WW;
            float r0 = xb[y0 * WW + x0] * (1.f - wy) + xb[y1 * WW + x0] * wy;
            float r1 = xb[y0 * WW + x1i] * (1.f - wy) + xb[y1 * WW + x1i] * wy;
            float dv = r0 * (1.f - wx) + r1 * wx;
            long long oi = (((long long)b * CH + c) * HO + i) * WO + j;
            out[oi] = sff[j * 129 + c] * (dv - sd[cl][j]) + sy[cl][j];
        }
        __syncthreads();
    }
}

// ---------------- launch: two batch halves, 3-stream budget ----------------
extern "C" void kernel_launch(void* const* d_in, const int* in_sizes, int n_in,
                              void* d_out, int out_size) {
    (void)in_sizes; (void)n_in; (void)out_size;
    const float* x       = (const float*)d_in[0];
    const float* conv1_b = (const float*)d_in[2];
    const float* l1_w    = (const float*)d_in[3];
    const float* l1_b    = (const float*)d_in[4];
    const float* ln1_g   = (const float*)d_in[5];
    const float* ln1_b   = (const float*)d_in[6];
    const float* fc1_b   = (const float*)d_in[8];
    const float* div_b   = (const float*)d_in[10];
    const float* fc2_b   = (const float*)d_in[12];
    const float* ln3_g   = (const float*)d_in[13];
    const float* ln3_b   = (const float*)d_in[14];
    const float* fc3a_b  = (const float*)d_in[16];
    const float* fc3b_b  = (const float*)d_in[18];
    const float* lnn_g   = (const float*)d_in[19];
    const float* lnn_b   = (const float*)d_in[20];
    const float* act_b   = (const float*)d_in[22];
    float* out = (float*)d_out;

    float *y, *x1, *t1, *x3, *gate, *dwt, *Sf;
    cudaGetSymbolAddress((void**)&y,    g_y);
    cudaGetSymbolAddress((void**)&x1,   g_x1);
    cudaGetSymbolAddress((void**)&t1,   g_t1);
    cudaGetSymbolAddress((void**)&x3,   g_x3);
    cudaGetSymbolAddress((void**)&gate, g_gate);
    cudaGetSymbolAddress((void**)&dwt,  g_dwt);
    cudaGetSymbolAddress((void**)&Sf,   g_Sf);

    bf16 *yLh, *yLl, *hlhh, *hlhl, *yh, *yl, *Sh, *Sl, *yTh, *yTl;
    bf16 *attnh, *attnl, *t0h, *t0l, *t0bh, *t0bl, *x2h, *x2l, *x2bh, *x2bl;
    bf16 *Wh, *Wl, *Wch, *Wcl, *xth, *xtl;
    cudaGetSymbolAddress((void**)&yLh,   syL_h);
    cudaGetSymbolAddress((void**)&yLl,   syL_l);
    cudaGetSymbolAddress((void**)&hlhh,  shlh_h);
    cudaGetSymbolAddress((void**)&hlhl,  shlh_l);
    cudaGetSymbolAddress((void**)&yh,    sy_h);
    cudaGetSymbolAddress((void**)&yl,    sy_l);
    cudaGetSymbolAddress((void**)&Sh,    sS_h);
    cudaGetSymbolAddress((void**)&Sl,    sS_l);
    cudaGetSymbolAddress((void**)&yTh,   syT_h);
    cudaGetSymbolAddress((void**)&yTl,   syT_l);
    cudaGetSymbolAddress((void**)&attnh, sattn_h);
    cudaGetSymbolAddress((void**)&attnl, sattn_l);
    cudaGetSymbolAddress((void**)&t0h,   st0_h);
    cudaGetSymbolAddress((void**)&t0l,   st0_l);
    cudaGetSymbolAddress((void**)&t0bh,  st0b_h);
    cudaGetSymbolAddress((void**)&t0bl,  st0b_l);
    cudaGetSymbolAddress((void**)&x2h,   sx2_h);
    cudaGetSymbolAddress((void**)&x2l,   sx2_l);
    cudaGetSymbolAddress((void**)&x2bh,  sx2b_h);
    cudaGetSymbolAddress((void**)&x2bl,  sx2b_l);
    cudaGetSymbolAddress((void**)&Wh,    sW_h);
    cudaGetSymbolAddress((void**)&Wl,    sW_l);
    cudaGetSymbolAddress((void**)&Wch,   sWc_h);
    cudaGetSymbolAddress((void**)&Wcl,   sWc_l);
    cudaGetSymbolAddress((void**)&xth,   sxt_h);
    cudaGetSymbolAddress((void**)&xtl,   sxt_l);

    cudaFuncSetAttribute(bgemm_k<0,3>, cudaFuncAttributeMaxDynamicSharedMemorySize, BGE_SMEM);
    cudaFuncSetAttribute(bgemm_k<0,1>, cudaFuncAttributeMaxDynamicSharedMemorySize, BGE_SMEM);
    cudaFuncSetAttribute(bgemm_k<0,2>, cudaFuncAttributeMaxDynamicSharedMemorySize, BGE_SMEM);
    cudaFuncSetAttribute(bgemm_k<1,1>, cudaFuncAttributeMaxDynamicSharedMemorySize, BGE_SMEM);
    cudaFuncSetAttribute(bgemm_k<1,2>, cudaFuncAttributeMaxDynamicSharedMemorySize, BGE_SMEM);
    cudaFuncSetAttribute(bgemm_k<3,2>, cudaFuncAttributeMaxDynamicSharedMemorySize, BGE_SMEM);
    cudaFuncSetAttribute(bgemm_k<2,1>, cudaFuncAttributeMaxDynamicSharedMemorySize, BGE_SMEM);
    cudaFuncSetAttribute(cgemm_k, cudaFuncAttributeMaxDynamicSharedMemorySize, BGE_SMEM);
    cudaFuncSetAttribute(softmax2_k, cudaFuncAttributeMaxDynamicSharedMemorySize, SMX_SMEM);
    cudaFuncSetAttribute(final2_k, cudaFuncAttributeMaxDynamicSharedMemorySize, FIN_SMEM);

    // exactly 3 created streams (same budget as the passing R11 build)
    static cudaStream_t sH1 = nullptr, sA = nullptr, sB2 = nullptr;
    static cudaEvent_t e0, eW, eAttn[2], eB[2], eC[2], eConv[2], eF1;
    if (!sH1) {
        cudaStreamCreateWithFlags(&sH1, cudaStreamNonBlocking);
        cudaStreamCreateWithFlags(&sA, cudaStreamNonBlocking);
        cudaStreamCreateWithFlags(&sB2, cudaStreamNonBlocking);
        cudaEventCreateWithFlags(&e0, cudaEventDisableTiming);
        cudaEventCreateWithFlags(&eW, cudaEventDisableTiming);
        cudaEventCreateWithFlags(&eF1, cudaEventDisableTiming);
        for (int h = 0; h < 2; h++) {
            cudaEventCreateWithFlags(&eAttn[h], cudaEventDisableTiming);
            cudaEventCreateWithFlags(&eB[h], cudaEventDisableTiming);
            cudaEventCreateWithFlags(&eC[h], cudaEventDisableTiming);
            cudaEventCreateWithFlags(&eConv[h], cudaEventDisableTiming);
        }
    }

    const float* w0 = (const float*)d_in[1];
    const float* w1 = (const float*)d_in[7];
    const float* w2 = (const float*)d_in[9];
    const float* w3 = (const float*)d_in[11];
    const float* w4 = (const float*)d_in[15];
    const float* w5 = (const float*)d_in[17];
    const float* w6 = (const float*)d_in[21];

    cudaEventRecord(e0, 0);
    cudaStreamWaitEvent(sH1, e0, 0);
    cudaStreamWaitEvent(sA, e0, 0);
    cudaStreamWaitEvent(sB2, e0, 0);

    // weights on default; half-1 chain waits on them
    wsplit_k<<<512, 256>>>(w0, w1, w2, w3, w4, w5, w6, Wh, Wl);
    cudaEventRecord(eW, 0);
    cudaStreamWaitEvent(sH1, eW, 0);

    // conv branch (both halves, sequential on sA)
    wconv_k<<<1024, 256, 0, sA>>>(l1_w, Wch, Wcl);
    nhwc_k<<<dim3(128, HB), 256, 0, sA>>>(x, xth, xtl, 0);
    cgemm_k<<<dim3(1, 32, HB), 256, BGE_SMEM, sA>>>(xth, xtl, Wch, Wcl, l1_b, dwt, 0);
    cudaEventRecord(eConv[0], sA);
    nhwc_k<<<dim3(128, HB), 256, 0, sA>>>(x, xth, xtl, HB);
    cgemm_k<<<dim3(1, 32, HB), 256, BGE_SMEM, sA>>>(xth, xtl, Wch, Wcl, l1_b, dwt, HB);
    cudaEventRecord(eConv[1], sA);

    for (int h = 0; h < 2; h++) {
        cudaStream_t m = (h == 0) ? (cudaStream_t)0 : sH1;
        size_t TO = (size_t)h * HT * 128;
        size_t TO2 = (size_t)h * HT * 256;
        size_t GO = (size_t)h * HG * QL * QL;
        size_t VO = (size_t)h * HG * 128 * 512;
        int b0 = h * HB;

        // attention chain
        haar_k<<<dim3(64, HB), 256, 0, m>>>(x, yLh, yLl, yTh, yTl, hlhh, hlhl, b0);

        bgemm_k<0,3><<<dim3(1, HT / 128, 1), 256, BGE_SMEM, m>>>(
            hlhh + TO2, hlhl + TO2, 0, 256, Wh, Wl, 0, 256,
            y + TO, yh + TO, yl + TO, 0, 128, 256, 1.f, conv1_b, nullptr);

        bgemm_k<0,1><<<dim3(4, 4, HG), 256, BGE_SMEM, m>>>(
            yLh + TO, yLl + TO, (long long)QL * 128, 128,
            yh + TO, yl + TO, (long long)QL * 128, 128,
            Sf + GO, nullptr, nullptr, (long long)QL * QL, QL,
            128, 0.35355339059327373f, nullptr, nullptr);

        softmax2_k<<<dim3(16, HG), 256, SMX_SMEM, m>>>(Sf + GO, Sh + GO, Sl + GO);

        bgemm_k<0,2><<<dim3(1, 4, HG), 256, BGE_SMEM, m>>>(
            Sh + GO, Sl + GO, (long long)QL * QL, QL,
            yTh + VO, yTl + VO, (long long)128 * 512, 512,
            nullptr, attnh + TO, attnl + TO, (long long)QL * 128, 128, 512, 1.f, nullptr, nullptr);
        cudaEventRecord(eAttn[h], m);

        // side chain B on sB2: ln3 -> fc3a -> fc3b
        cudaStreamWaitEvent(sB2, eAttn[h], 0);
        ln_k<<<HT / 8, 256, 0, sB2>>>(attnh + TO, attnl + TO, t0bh + TO, t0bl + TO, ln3_g, ln3_b);
        bgemm_k<1,2><<<dim3(1, HT / 128), 256, BGE_SMEM, sB2>>>(
            t0bh + TO, t0bl + TO, 0, 128, Wh + 81920, Wl + 81920, 0, 128,
            nullptr, x2bh + TO, x2bl + TO, 0, 128, 128, 1.f, fc3a_b, nullptr);
        bgemm_k<0,1><<<dim3(1, HT / 128), 256, BGE_SMEM, sB2>>>(
            x2bh + TO, x2bl + TO, 0, 128, Wh + 98304, Wl + 98304, 0, 128,
            x3 + TO, nullptr, nullptr, 0, 128, 128, 1.f, fc3b_b, nullptr);
        cudaEventRecord(eB[h], sB2);

        // side chain C (gate) on sA, after its conv work
        cudaStreamWaitEvent(sA, eAttn[h], 0);
        bgemm_k<2,1><<<dim3(1, HT / 128), 256, BGE_SMEM, sA>>>(
            attnh + TO, attnl + TO, 0, 128, Wh + 114688, Wl + 114688, 0, 128,
            gate + TO, nullptr, nullptr, 0, 128, 128, 1.f, act_b, nullptr);
        cudaEventRecord(eC[h], sA);

        // main FFN chain
        ln_k<<<HT / 8, 256, 0, m>>>(attnh + TO, attnl + TO, t0h + TO, t0l + TO, ln1_g, ln1_b);
        bgemm_k<1,1><<<dim3(1, HT / 128), 256, BGE_SMEM, m>>>(
            t0h + TO, t0l + TO, 0, 128, Wh + 32768, Wl + 32768, 0, 128,
            x1 + TO, nullptr, nullptr, 0, 128, 128, 1.f, fc1_b, nullptr);
        bgemm_k<3,2><<<dim3(1, HT / 128), 256, BGE_SMEM, m>>>(
            attnh + TO, attnl + TO, 0, 128, Wh + 49152, Wl + 49152, 0, 128,
            nullptr, x2h + TO, x2l + TO, 0, 128, 128, 1.f, div_b, x1 + TO);
        bgemm_k<1,1><<<dim3(1, HT / 128), 256, BGE_SMEM, m>>>(
            x2h + TO, x2l + TO, 0, 128, Wh + 65536, Wl + 65536, 0, 128,
            t1 + TO, nullptr, nullptr, 0, 128, 128, 1.f, fc2_b, nullptr);

        // join this half
        cudaStreamWaitEvent(m, eB[h], 0);
        cudaStreamWaitEvent(m, eC[h], 0);
        cudaStreamWaitEvent(m, eConv[h], 0);
        final2_k<<<dim3(64, HB), 256, FIN_SMEM, m>>>(
            x, t1, x3, gate, lnn_g, lnn_b, y, dwt, out, b0);
    }

    // rejoin half-1 into origin stream
    cudaEventRecord(eF1, sH1);
    cudaStreamWaitEvent(0, eF1, 0);
}